// round 9
// baseline (speedup 1.0000x reference)
#include <cuda_runtime.h>
#include <cuda_bf16.h>
#include <cstdint>

using bf = __nv_bfloat16;
static constexpr int  BATCH = 32;
static constexpr int  NH    = 8;
static constexpr long MB    = 512L * 512L;
static constexpr long HB    = 512L * 64L;

// ---------------------------------------------------------------------------
// Scratch (static __device__ arrays: allocation-free per harness rules)
// ---------------------------------------------------------------------------
__device__ float g_oi [(long)BATCH * 512 * 512];

__device__ bf g_xT_hi[(long)BATCH * MB], g_xT_lo[(long)BATCH * MB];
__device__ bf g_xp_hi[(long)BATCH * MB], g_xp_lo[(long)BATCH * MB];
__device__ bf g_cc_hi[(long)BATCH * MB], g_cc_lo[(long)BATCH * MB];
__device__ bf g_oi_hi[(long)BATCH * MB], g_oi_lo[(long)BATCH * MB];
__device__ bf g_q_hi[(long)BATCH * NH * HB], g_q_lo[(long)BATCH * NH * HB];
__device__ bf g_k_hi[(long)BATCH * NH * HB], g_k_lo[(long)BATCH * NH * HB];
__device__ bf g_v_hi[(long)BATCH * NH * HB], g_v_lo[(long)BATCH * NH * HB];

__device__ bf g_wcin_hi [MB], g_wcin_lo [MB];
__device__ bf g_wcout_hi[MB], g_wcout_lo[MB];
__device__ bf g_wsi_hi  [MB], g_wsi_lo  [MB];
__device__ bf g_woi_hi  [MB], g_woi_lo  [MB];
__device__ bf g_wqA_hi[NH*4096], g_wqA_lo[NH*4096];
__device__ bf g_wkA_hi[NH*4096], g_wkA_lo[NH*4096];
__device__ bf g_wvA_hi[NH*4096], g_wvA_lo[NH*4096];
__device__ bf g_wqB_hi[NH*4096], g_wqB_lo[NH*4096];
__device__ bf g_wkB_hi[NH*4096], g_wkB_lo[NH*4096];
__device__ bf g_wvB_hi[NH*4096], g_wvB_lo[NH*4096];

// ---------------------------------------------------------------------------
// Low-level helpers (sm_80+ baseline)
// ---------------------------------------------------------------------------
__device__ __forceinline__ void mma16816(float* c, const uint32_t* a,
                                         uint32_t b0, uint32_t b1) {
    asm volatile(
        "mma.sync.aligned.m16n8k16.row.col.f32.bf16.bf16.f32 "
        "{%0,%1,%2,%3}, {%4,%5,%6,%7}, {%8,%9}, {%0,%1,%2,%3};"
        : "+f"(c[0]), "+f"(c[1]), "+f"(c[2]), "+f"(c[3])
        : "r"(a[0]), "r"(a[1]), "r"(a[2]), "r"(a[3]), "r"(b0), "r"(b1));
}
__device__ __forceinline__ void ldsm4(uint32_t* r, uint32_t a) {
    asm volatile("ldmatrix.sync.aligned.m8n8.x4.shared.b16 {%0,%1,%2,%3}, [%4];"
                 : "=r"(r[0]), "=r"(r[1]), "=r"(r[2]), "=r"(r[3]) : "r"(a));
}
__device__ __forceinline__ void ldsm4t(uint32_t* r, uint32_t a) {
    asm volatile("ldmatrix.sync.aligned.m8n8.x4.trans.shared.b16 {%0,%1,%2,%3}, [%4];"
                 : "=r"(r[0]), "=r"(r[1]), "=r"(r[2]), "=r"(r[3]) : "r"(a));
}
__device__ __forceinline__ void cpa16(uint32_t s, const void* g) {
    asm volatile("cp.async.cg.shared.global [%0], [%1], 16;" :: "r"(s), "l"(g));
}
#define CP_COMMIT() asm volatile("cp.async.commit_group;" ::: "memory")
#define CP_WAIT(N)  asm volatile("cp.async.wait_group %0;" :: "n"(N) : "memory")
__device__ __forceinline__ uint32_t smem_u32(const void* p) {
    uint32_t a;
    asm("{ .reg .u64 t; cvta.to.shared.u64 t, %1; cvt.u32.u64 %0, t; }"
        : "=r"(a) : "l"(p));
    return a;
}
__device__ __forceinline__ void split_pack(float a, float b,
                                           uint32_t& hi, uint32_t& lo) {
    __nv_bfloat162 h, l;
    h.x = __float2bfloat16_rn(a); h.y = __float2bfloat16_rn(b);
    l.x = __float2bfloat16_rn(a - __bfloat162float(h.x));
    l.y = __float2bfloat16_rn(b - __bfloat162float(h.y));
    hi = *reinterpret_cast<uint32_t*>(&h);
    lo = *reinterpret_cast<uint32_t*>(&l);
}
__device__ __forceinline__ void split_store(bf* H, bf* L, long off,
                                            float a, float b) {
    uint32_t h, l; split_pack(a, b, h, l);
    *reinterpret_cast<uint32_t*>(H + off) = h;
    *reinterpret_cast<uint32_t*>(L + off) = l;
}

// ---------------------------------------------------------------------------
// Batched fp32 -> bf16 hi/lo weight splits: 8 jobs, one launch
// ---------------------------------------------------------------------------
struct SplitJob  { const float4* src; bf* hi; bf* lo; long n4; };
struct SplitJobs { SplitJob j[8]; };

__global__ __launch_bounds__(256) void split8(SplitJobs jobs)
{
    const SplitJob jb = jobs.j[blockIdx.y];
    long i = (long)blockIdx.x * 256 + threadIdx.x;
    if (i >= jb.n4) return;
    float4 v = jb.src[i];
    uint32_t h0, l0, h1, l1;
    split_pack(v.x, v.y, h0, l0);
    split_pack(v.z, v.w, h1, l1);
    uint2 ph = {h0, h1}, pl = {l0, l1};
    *(uint2*)(jb.hi + i * 4) = ph;
    *(uint2*)(jb.lo + i * 4) = pl;
}

__global__ __launch_bounds__(256) void transpose_split_kernel(
    const float* __restrict__ in, bf* __restrict__ hi, bf* __restrict__ lo)
{
    __shared__ float t[32][33];
    const int b = blockIdx.z;
    const int s0 = blockIdx.x * 32, d0 = blockIdx.y * 32;
    const long base = (long)b * MB;
    const int tx = threadIdx.x, ty = threadIdx.y;
    #pragma unroll
    for (int i = ty; i < 32; i += 8)
        t[i][tx] = in[base + (long)(s0 + i) * 512 + d0 + tx];
    __syncthreads();
    #pragma unroll
    for (int i = ty; i < 32; i += 8) {
        float v = t[tx][i];
        bf h = __float2bfloat16_rn(v);
        bf l = __float2bfloat16_rn(v - __bfloat162float(h));
        long o = base + (long)(d0 + i) * 512 + s0 + tx;
        hi[o] = h; lo[o] = l;
    }
}

// ---------------------------------------------------------------------------
// Weight-combine GEMM (fp32 in, bf16 hi/lo out): C[m][n] = sum_k A[m,k]*B[k,n]
// Two jobs via blockIdx.z. 64x64 tiles.
// ---------------------------------------------------------------------------
__global__ __launch_bounds__(256) void gemm64w(
    const float* __restrict__ A0, const float* __restrict__ B0,
    bf* __restrict__ C0h, bf* __restrict__ C0l,
    const float* __restrict__ A1, const float* __restrict__ B1,
    bf* __restrict__ C1h, bf* __restrict__ C1l)
{
    const float* A = blockIdx.z ? A1 : A0;
    const float* B = blockIdx.z ? B1 : B0;
    bf* Ch = blockIdx.z ? C1h : C0h;
    bf* Cl = blockIdx.z ? C1l : C0l;
    __shared__ float As[16][64], Bs[16][64];
    const int bM = blockIdx.y * 64, bN = blockIdx.x * 64;
    const int tid = threadIdx.x, tx = tid & 15, ty = tid >> 4;
    float acc[4][4];
    #pragma unroll
    for (int i = 0; i < 4; i++)
        #pragma unroll
        for (int j = 0; j < 4; j++) acc[i][j] = 0.f;
    for (int kt = 0; kt < 32; kt++) {
        const int k0 = kt * 16;
        __syncthreads();
        #pragma unroll
        for (int it = 0; it < 4; it++) {
            int id = tid + it * 256;
            As[id & 15][id >> 4] = A[(long)(bM + (id >> 4)) * 512 + k0 + (id & 15)];
            Bs[id >> 6][id & 63] = B[(long)(k0 + (id >> 6)) * 512 + bN + (id & 63)];
        }
        __syncthreads();
        #pragma unroll
        for (int k = 0; k < 16; k++) {
            float av[4], bv[4];
            #pragma unroll
            for (int i = 0; i < 4; i++) av[i] = As[k][ty * 4 + i];
            #pragma unroll
            for (int j = 0; j < 4; j++) bv[j] = Bs[k][tx * 4 + j];
            #pragma unroll
            for (int i = 0; i < 4; i++)
                #pragma unroll
                for (int j = 0; j < 4; j++)
                    acc[i][j] = fmaf(av[i], bv[j], acc[i][j]);
        }
    }
    #pragma unroll
    for (int i = 0; i < 4; i++) {
        const long o = (long)(bM + ty * 4 + i) * 512 + bN + tx * 4;
        split_store(Ch, Cl, o,     acc[i][0], acc[i][1]);
        split_store(Ch, Cl, o + 2, acc[i][2], acc[i][3]);
    }
}

// ---------------------------------------------------------------------------
// Pipelined tensor-core batched GEMM: C[b][m][n] = sum_k A[b][m][k]*B[b][n][k]
// BK=32, 2-stage cp.async, ldmatrix fragments, 3-term hi/lo accumulation.
// ---------------------------------------------------------------------------
static constexpr int SK2 = 40;
static constexpr int ARR = 128 * SK2 * 2;
static constexpr int STG = 4 * ARR;
static constexpr int TCG_SMEM = 2 * STG;       // 81920

__device__ __forceinline__ void tcg_load(
    uint32_t sb, const bf* Ah, const bf* Al, const bf* Bh, const bf* Bl,
    int bM, int bN, int k0, int tid)
{
    #pragma unroll
    for (int a = 0; a < 4; a++) {
        const bf* src = (a == 0) ? Ah : (a == 1) ? Al : (a == 2) ? Bh : Bl;
        const int row0 = (a < 2) ? bM : bN;
        const uint32_t dst = sb + a * ARR;
        #pragma unroll
        for (int it = 0; it < 2; it++) {
            int id = tid + it * 256;
            int r = id >> 2, c4 = id & 3;
            cpa16(dst + (uint32_t)(r * SK2 + c4 * 8) * 2,
                  src + (long)(row0 + r) * 512 + k0 + c4 * 8);
        }
    }
}

template<int EPI, int OF32, int OBF16>
__global__ __launch_bounds__(256) void tc_gemm(
    const bf* __restrict__ Ahi, const bf* __restrict__ Alo, long sA,
    const bf* __restrict__ Bhi, const bf* __restrict__ Blo, long sB,
    float* __restrict__ C, bf* __restrict__ Chi, bf* __restrict__ Clo, long sC,
    const float* __restrict__ R, long sR, const float* __restrict__ alpha_ptr)
{
    extern __shared__ __align__(16) char smc[];
    const uint32_t sb0 = smem_u32(smc);
    const int tid = threadIdx.x, lane = tid & 31, wid = tid >> 5;
    const int g = lane >> 2, tg = lane & 3;
    const int wm = (wid >> 1) * 32, wn = (wid & 1) * 64;
    const int bN = blockIdx.x * 128, bM = blockIdx.y * 128, bz = blockIdx.z;
    Ahi += (long)bz * sA; Alo += (long)bz * sA;
    Bhi += (long)bz * sB; Blo += (long)bz * sB;
    if (EPI != 0) R += (long)bz * sR;

    float acc[2][8][4];
    #pragma unroll
    for (int i = 0; i < 2; i++)
        #pragma unroll
        for (int j = 0; j < 8; j++)
            #pragma unroll
            for (int q = 0; q < 4; q++) acc[i][j][q] = 0.f;

    tcg_load(sb0, Ahi, Alo, Bhi, Blo, bM, bN, 0, tid);
    CP_COMMIT();

    for (int t = 0; t < 16; t++) {
        if (t < 15) {
            tcg_load(sb0 + ((t + 1) & 1) * STG, Ahi, Alo, Bhi, Blo,
                     bM, bN, (t + 1) * 32, tid);
            CP_COMMIT();
            CP_WAIT(1);
        } else {
            CP_WAIT(0);
        }
        __syncthreads();
        const uint32_t sb = sb0 + (t & 1) * STG;
        #pragma unroll
        for (int ks = 0; ks < 2; ks++) {
            const int kb = ks * 16;
            const uint32_t lrow = (lane & 7) + ((lane >> 3) & 1) * 8;
            const uint32_t lcol = kb + (lane >> 4) * 8;
            uint32_t ah[2][4], al[2][4];
            #pragma unroll
            for (int mi = 0; mi < 2; mi++) {
                uint32_t ad = sb + ((wm + mi * 16 + lrow) * SK2 + lcol) * 2;
                ldsm4(ah[mi], ad);
                ldsm4(al[mi], ad + ARR);
            }
            uint32_t bh[4][4], bl[4][4];
            #pragma unroll
            for (int nb = 0; nb < 4; nb++) {
                uint32_t ad = sb + 2 * ARR + ((wn + nb * 16 + lrow) * SK2 + lcol) * 2;
                ldsm4(bh[nb], ad);
                ldsm4(bl[nb], ad + ARR);
            }
            #pragma unroll
            for (int nb = 0; nb < 4; nb++)
                #pragma unroll
                for (int h2 = 0; h2 < 2; h2++) {
                    const uint32_t b0h = bh[nb][h2], b1h = bh[nb][h2 + 2];
                    const uint32_t b0l = bl[nb][h2], b1l = bl[nb][h2 + 2];
                    #pragma unroll
                    for (int mi = 0; mi < 2; mi++) {
                        float* a = acc[mi][nb * 2 + h2];
                        mma16816(a, ah[mi], b0h, b1h);
                        mma16816(a, ah[mi], b0l, b1l);
                        mma16816(a, al[mi], b0h, b1h);
                    }
                }
        }
        __syncthreads();
    }

    float ab = 0.f;
    if (EPI == 2) ab = 1.f / (1.f + expf(-alpha_ptr[0]));
    #pragma unroll
    for (int mi = 0; mi < 2; mi++)
        #pragma unroll
        for (int nj = 0; nj < 8; nj++) {
            const int row = bM + wm + mi * 16 + g;
            const int col = bN + wn + nj * 8 + tg * 2;
            float v0 = acc[mi][nj][0], v1 = acc[mi][nj][1];
            float v2 = acc[mi][nj][2], v3 = acc[mi][nj][3];
            const long o0 = (long)bz * sC + (long)row * 512 + col;
            const long o1 = o0 + 8 * 512;
            if (EPI == 1) {
                float2 r0 = *(const float2*)(R + (long)row * 512 + col);
                float2 r1 = *(const float2*)(R + (long)(row + 8) * 512 + col);
                v0 += r0.x; v1 += r0.y; v2 += r1.x; v3 += r1.y;
            } else if (EPI == 2) {
                float2 r0 = *(const float2*)(R + (long)row * 512 + col);
                float2 r1 = *(const float2*)(R + (long)(row + 8) * 512 + col);
                v0 = (1.f - ab) * v0 + ab * r0.x;
                v1 = (1.f - ab) * v1 + ab * r0.y;
                v2 = (1.f - ab) * v2 + ab * r1.x;
                v3 = (1.f - ab) * v3 + ab * r1.y;
            }
            if (OF32) {
                float2 w0 = {v0, v1}, w1 = {v2, v3};
                *(float2*)(C + o0) = w0;
                *(float2*)(C + o1) = w1;
            }
            if (OBF16) {
                split_store(Chi, Clo, o0, v0, v1);
                split_store(Chi, Clo, o1, v2, v3);
            }
        }
}

// ---------------------------------------------------------------------------
// QKV projection (mma): per (64-token tile, head, batch).
// ---------------------------------------------------------------------------
static constexpr int SK = 72;
static constexpr int QKV_SMEM = 8 * 64 * SK * 2;   // 73728

__device__ __forceinline__ void head_gemm(
    uint32_t wbase, const uint32_t xh[4][4], const uint32_t xl[4][4],
    float scale, bf* Oh, bf* Ol, long obase, int row0, int lane)
{
    const int g = lane >> 2, tg = lane & 3;
    const uint32_t lrow = (lane & 7) + ((lane >> 3) & 1) * 8;
    const uint32_t lc8 = (lane >> 4) * 8;
    float acc[8][4];
    #pragma unroll
    for (int j = 0; j < 8; j++)
        #pragma unroll
        for (int q = 0; q < 4; q++) acc[j][q] = 0.f;
    #pragma unroll
    for (int ks = 0; ks < 4; ks++) {
        uint32_t bh[4][4], bl[4][4];
        #pragma unroll
        for (int nb = 0; nb < 4; nb++) {
            uint32_t ad = wbase + ((nb * 16 + lrow) * SK + ks * 16 + lc8) * 2;
            ldsm4(bh[nb], ad);
            ldsm4(bl[nb], ad + (uint32_t)(64 * SK * 2));
        }
        #pragma unroll
        for (int nb = 0; nb < 4; nb++)
            #pragma unroll
            for (int h2 = 0; h2 < 2; h2++) {
                float* a = acc[nb * 2 + h2];
                mma16816(a, xh[ks], bh[nb][h2], bh[nb][h2 + 2]);
                mma16816(a, xh[ks], bl[nb][h2], bl[nb][h2 + 2]);
                mma16816(a, xl[ks], bh[nb][h2], bh[nb][h2 + 2]);
            }
    }
    #pragma unroll
    for (int nj = 0; nj < 8; nj++) {
        const long o0 = obase + (long)(row0 + g) * 64 + nj * 8 + tg * 2;
        split_store(Oh, Ol, o0, acc[nj][0] * scale, acc[nj][1] * scale);
        split_store(Oh, Ol, o0 + 8 * 64, acc[nj][2] * scale, acc[nj][3] * scale);
    }
}

__global__ __launch_bounds__(128) void qkv_mma(
    const bf* __restrict__ Xh, const bf* __restrict__ Xl,
    const bf* __restrict__ Wqh, const bf* __restrict__ Wql,
    const bf* __restrict__ Wkh, const bf* __restrict__ Wkl,
    const bf* __restrict__ Wvh, const bf* __restrict__ Wvl,
    bf* __restrict__ Qh, bf* __restrict__ Ql,
    bf* __restrict__ Kh, bf* __restrict__ Kl,
    bf* __restrict__ Vh, bf* __restrict__ Vl)
{
    extern __shared__ __align__(16) bf smq[];
    const int tile0 = blockIdx.x * 64, h = blockIdx.y, b = blockIdx.z;
    const int tid = threadIdx.x, lane = tid & 31, wid = tid >> 5;
    const long xbase = (long)b * MB;
    const long obase = (long)(b * NH + h) * HB;
    bf* Xs = smq;
    bf* Ws = smq + 2 * 64 * SK;

    #pragma unroll
    for (int it = 0; it < 4; it++) {
        int id = tid + it * 128;
        int r = id >> 3, c8 = (id & 7) * 8;
        *(uint4*)(Xs + r * SK + c8) =
            *(const uint4*)(Xh + xbase + (long)(tile0 + r) * 512 + h * 64 + c8);
        *(uint4*)(Xs + 64 * SK + r * SK + c8) =
            *(const uint4*)(Xl + xbase + (long)(tile0 + r) * 512 + h * 64 + c8);
    }
    const bf* wsrc[6] = {Wqh, Wql, Wkh, Wkl, Wvh, Wvl};
    #pragma unroll
    for (int a = 0; a < 6; a++)
        #pragma unroll
        for (int it = 0; it < 4; it++) {
            int id = tid + it * 128;
            int r = id >> 3, c8 = (id & 7) * 8;
            *(uint4*)(Ws + a * 64 * SK + r * SK + c8) =
                *(const uint4*)(wsrc[a] + h * 4096 + r * 64 + c8);
        }
    __syncthreads();

    const uint32_t xb = smem_u32(Xs);
    const uint32_t lrow = (lane & 7) + ((lane >> 3) & 1) * 8;
    const uint32_t lc8 = (lane >> 4) * 8;
    uint32_t xhf[4][4], xlf[4][4];
    #pragma unroll
    for (int ks = 0; ks < 4; ks++) {
        uint32_t ad = xb + ((wid * 16 + lrow) * SK + ks * 16 + lc8) * 2;
        ldsm4(xhf[ks], ad);
        ldsm4(xlf[ks], ad + (uint32_t)(64 * SK * 2));
    }
    const uint32_t wb = smem_u32(Ws);
    const int row0 = tile0 + wid * 16;
    head_gemm(wb,             xhf, xlf, 0.125f, Qh, Ql, obase, row0, lane);
    head_gemm(wb + 2*64*SK*2, xhf, xlf, 1.f,    Kh, Kl, obase, row0, lane);
    head_gemm(wb + 4*64*SK*2, xhf, xlf, 1.f,    Vh, Vl, obase, row0, lane);
}

// ---------------------------------------------------------------------------
// Flash attention (mma): 256 threads, 128-row q-strip per CTA,
// cp.async double-buffered K/V stages. Q pre-scaled. Output bf16 hi/lo,
// head-concatenated: O[b][row][h*64+e].
// ---------------------------------------------------------------------------
static constexpr int ASTB = 64 * SK * 2;             // bytes per KV array (9216)
static constexpr int STA  = 4 * ASTB;                // bytes per KV stage (36864)
static constexpr int ATTN_SMEM = 2 * STA;            // 73728

__device__ __forceinline__ void attn_load_kv(
    uint32_t dst, const bf* Kh, const bf* Kl, const bf* Vh, const bf* Vl,
    long base, int kt, int tid)
{
    #pragma unroll
    for (int it = 0; it < 2; it++) {
        int id = tid + it * 256;       // 0..511
        int r = id >> 3, c8 = (id & 7) * 8;
        const long gsrc = base + (long)(kt * 64 + r) * 64 + c8;
        const uint32_t so = (uint32_t)(r * SK + c8) * 2;
        cpa16(dst            + so, Kh + gsrc);
        cpa16(dst +     ASTB + so, Kl + gsrc);
        cpa16(dst + 2 * ASTB + so, Vh + gsrc);
        cpa16(dst + 3 * ASTB + so, Vl + gsrc);
    }
}

__global__ __launch_bounds__(256) void attn_mma(
    const bf* __restrict__ Qh, const bf* __restrict__ Ql,
    const bf* __restrict__ Kh, const bf* __restrict__ Kl,
    const bf* __restrict__ Vh, const bf* __restrict__ Vl,
    const float* __restrict__ mask,
    bf* __restrict__ Oh, bf* __restrict__ Ol)
{
    extern __shared__ __align__(16) bf sma[];
    const int q0 = blockIdx.x * 128, h = blockIdx.y, b = blockIdx.z;
    const int tid = threadIdx.x, lane = tid & 31, wid = tid >> 5;
    const int g = lane >> 2, tg = lane & 3;
    const long base = (long)(b * NH + h) * HB;
    const uint32_t sb = smem_u32(sma);
    const uint32_t lrow = (lane & 7) + ((lane >> 3) & 1) * 8;
    const uint32_t lc8 = (lane >> 4) * 8;

    // Stage the 128-row Q strip (hi then lo) through stage 0 via cp.async
    #pragma unroll
    for (int it = 0; it < 4; it++) {
        int id = tid + it * 256;       // 0..1023
        int r = id >> 3, c8 = (id & 7) * 8;
        const long gq = base + (long)(q0 + r) * 64 + c8;
        cpa16(sb + (uint32_t)(r * SK + c8) * 2, Qh + gq);
        cpa16(sb + (uint32_t)((128 + r) * SK + c8) * 2, Ql + gq);
    }
    CP_COMMIT(); CP_WAIT(0);
    __syncthreads();
    uint32_t qh[4][4], ql[4][4];
    #pragma unroll
    for (int ks = 0; ks < 4; ks++) {
        uint32_t ad = sb + ((wid * 16 + lrow) * SK + ks * 16 + lc8) * 2;
        ldsm4(qh[ks], ad);
        ldsm4(ql[ks], ad + (uint32_t)(128 * SK * 2));
    }
    __syncthreads();   // all warps done reading Q before stage0 is reused

    float m0 = -1e30f, m1 = -1e30f, l0 = 0.f, l1 = 0.f;
    float o[8][4];
    #pragma unroll
    for (int j = 0; j < 8; j++)
        #pragma unroll
        for (int q = 0; q < 4; q++) o[j][q] = 0.f;

    attn_load_kv(sb, Kh, Kl, Vh, Vl, base, 0, tid);
    CP_COMMIT();

    for (int kt = 0; kt < 8; kt++) {
        if (kt < 7) {
            attn_load_kv(sb + ((kt + 1) & 1) * STA, Kh, Kl, Vh, Vl,
                         base, kt + 1, tid);
            CP_COMMIT();
            CP_WAIT(1);
        } else {
            CP_WAIT(0);
        }
        __syncthreads();
        const uint32_t KHs = sb + (kt & 1) * STA;
        const uint32_t KLs = KHs + ASTB;
        const uint32_t VHs = KHs + 2 * ASTB;
        const uint32_t VLs = KHs + 3 * ASTB;

        // S = Q K^T (3-term)
        float s[8][4];
        #pragma unroll
        for (int j = 0; j < 8; j++)
            #pragma unroll
            for (int q = 0; q < 4; q++) s[j][q] = 0.f;
        #pragma unroll
        for (int ks = 0; ks < 4; ks++) {
            uint32_t bh[4][4], bl[4][4];
            #pragma unroll
            for (int nb = 0; nb < 4; nb++) {
                uint32_t ad = KHs + ((nb * 16 + lrow) * SK + ks * 16 + lc8) * 2;
                ldsm4(bh[nb], ad);
                ldsm4(bl[nb], ad + ASTB);
            }
            #pragma unroll
            for (int nb = 0; nb < 4; nb++)
                #pragma unroll
                for (int h2 = 0; h2 < 2; h2++) {
                    float* a = s[nb * 2 + h2];
                    mma16816(a, qh[ks], bh[nb][h2], bh[nb][h2 + 2]);
                    mma16816(a, qh[ks], bl[nb][h2], bl[nb][h2 + 2]);
                    mma16816(a, ql[ks], bh[nb][h2], bh[nb][h2 + 2]);
                }
        }
        if (mask) {
            const int mr = q0 + wid * 16 + g;
            #pragma unroll
            for (int nj = 0; nj < 8; nj++) {
                const int mc = kt * 64 + nj * 8 + tg * 2;
                float2 a0 = *(const float2*)(mask + (long)mr * 512 + mc);
                float2 a1 = *(const float2*)(mask + (long)(mr + 8) * 512 + mc);
                s[nj][0] += a0.x; s[nj][1] += a0.y;
                s[nj][2] += a1.x; s[nj][3] += a1.y;
            }
        }

        // online softmax (rows g and g+8; reduce across tg lanes)
        float tm0 = -1e30f, tm1 = -1e30f;
        #pragma unroll
        for (int nj = 0; nj < 8; nj++) {
            tm0 = fmaxf(tm0, fmaxf(s[nj][0], s[nj][1]));
            tm1 = fmaxf(tm1, fmaxf(s[nj][2], s[nj][3]));
        }
        tm0 = fmaxf(tm0, __shfl_xor_sync(~0u, tm0, 1));
        tm0 = fmaxf(tm0, __shfl_xor_sync(~0u, tm0, 2));
        tm1 = fmaxf(tm1, __shfl_xor_sync(~0u, tm1, 1));
        tm1 = fmaxf(tm1, __shfl_xor_sync(~0u, tm1, 2));
        const float nm0 = fmaxf(m0, tm0), nm1 = fmaxf(m1, tm1);
        float sum0 = 0.f, sum1 = 0.f;
        #pragma unroll
        for (int nj = 0; nj < 8; nj++) {
            s[nj][0] = __expf(s[nj][0] - nm0); sum0 += s[nj][0];
            s[nj][1] = __expf(s[nj][1] - nm0); sum0 += s[nj][1];
            s[nj][2] = __expf(s[nj][2] - nm1); sum1 += s[nj][2];
            s[nj][3] = __expf(s[nj][3] - nm1); sum1 += s[nj][3];
        }
        sum0 += __shfl_xor_sync(~0u, sum0, 1);
        sum0 += __shfl_xor_sync(~0u, sum0, 2);
        sum1 += __shfl_xor_sync(~0u, sum1, 1);
        sum1 += __shfl_xor_sync(~0u, sum1, 2);
        const float c0 = __expf(m0 - nm0), c1 = __expf(m1 - nm1);
        l0 = l0 * c0 + sum0; l1 = l1 * c1 + sum1;
        m0 = nm0; m1 = nm1;
        #pragma unroll
        for (int j = 0; j < 8; j++) {
            o[j][0] *= c0; o[j][1] *= c0; o[j][2] *= c1; o[j][3] *= c1;
        }

        // P fragments (FA2 accum->A identity), hi/lo
        uint32_t ph[4][4], pl[4][4];
        #pragma unroll
        for (int ks = 0; ks < 4; ks++) {
            split_pack(s[2*ks][0],   s[2*ks][1],   ph[ks][0], pl[ks][0]);
            split_pack(s[2*ks][2],   s[2*ks][3],   ph[ks][1], pl[ks][1]);
            split_pack(s[2*ks+1][0], s[2*ks+1][1], ph[ks][2], pl[ks][2]);
            split_pack(s[2*ks+1][2], s[2*ks+1][3], ph[ks][3], pl[ks][3]);
        }

        // O += P V  (V^T fragments via ldmatrix.trans)
        #pragma unroll
        for (int ks = 0; ks < 4; ks++) {
            uint32_t vh[4][4], vl[4][4];
            #pragma unroll
            for (int nb = 0; nb < 4; nb++) {
                uint32_t ad = VHs + ((ks * 16 + (lane & 15)) * SK + nb * 16 + lc8) * 2;
                ldsm4t(vh[nb], ad);
                ldsm4t(vl[nb], ad + ASTB);
            }
            #pragma unroll
            for (int nb = 0; nb < 4; nb++)
                #pragma unroll
                for (int h2 = 0; h2 < 2; h2++) {
                    float* a = o[nb * 2 + h2];
                    const uint32_t b0h = vh[nb][h2 * 2], b1h = vh[nb][h2 * 2 + 1];
                    const uint32_t b0l = vl[nb][h2 * 2], b1l = vl[nb][h2 * 2 + 1];
                    mma16816(a, ph[ks], b0h, b1h);
                    mma16816(a, ph[ks], b0l, b1l);
                    mma16816(a, pl[ks], b0h, b1h);
                }
        }
        __syncthreads();   // all warps done with this stage before overwrite
    }

    const float i0 = 1.f / l0, i1 = 1.f / l1;
    const int row = q0 + wid * 16 + g;
    #pragma unroll
    for (int nj = 0; nj < 8; nj++) {
        const long o0 = (long)b * MB + (long)row * 512 + h * 64 + nj * 8 + tg * 2;
        split_store(Oh, Ol, o0,           o[nj][0] * i0, o[nj][1] * i0);
        split_store(Oh, Ol, o0 + 8 * 512, o[nj][2] * i1, o[nj][3] * i1);
    }
}

// ---------------------------------------------------------------------------
// Launch sequence (single stream, graph-capturable, allocation-free)
// ---------------------------------------------------------------------------
extern "C" void kernel_launch(void* const* d_in, const int* in_sizes, int n_in,
                              void* d_out, int out_size)
{
    const float* x             = (const float*)d_in[0];
    const float* mask          = (const float*)d_in[1];
    const float* Wq_inter      = (const float*)d_in[2];
    const float* Wk_inter      = (const float*)d_in[3];
    const float* Wv_inter      = (const float*)d_in[4];
    const float* Wq_intra      = (const float*)d_in[5];
    const float* Wk_intra      = (const float*)d_in[6];
    const float* Wv_intra      = (const float*)d_in[7];
    const float* W_proj_in     = (const float*)d_in[8];
    const float* W_proj_out    = (const float*)d_in[9];
    const float* W_split_inter = (const float*)d_in[10];
    const float* W_out_inter   = (const float*)d_in[11];
    const float* W_split_intra = (const float*)d_in[12];
    const float* W_out_intra   = (const float*)d_in[13];
    const float* alpha         = (const float*)d_in[14];
    float* out = (float*)d_out;

    float* oi;
    cudaGetSymbolAddress((void**)&oi, g_oi);

    bf *xTh,*xTl,*xph,*xpl,*cch,*ccl,*oih,*oil,*qhh,*qll,*khh,*kll,*vhh,*vll;
    bf *wcinh,*wcinl,*wcouth,*wcoutl,*wsih,*wsil,*woih,*woil;
    bf *wqAh,*wqAl,*wkAh,*wkAl,*wvAh,*wvAl,*wqBh,*wqBl,*wkBh,*wkBl,*wvBh,*wvBl;
    cudaGetSymbolAddress((void**)&xTh, g_xT_hi); cudaGetSymbolAddress((void**)&xTl, g_xT_lo);
    cudaGetSymbolAddress((void**)&xph, g_xp_hi); cudaGetSymbolAddress((void**)&xpl, g_xp_lo);
    cudaGetSymbolAddress((void**)&cch, g_cc_hi); cudaGetSymbolAddress((void**)&ccl, g_cc_lo);
    cudaGetSymbolAddress((void**)&oih, g_oi_hi); cudaGetSymbolAddress((void**)&oil, g_oi_lo);
    cudaGetSymbolAddress((void**)&qhh, g_q_hi);  cudaGetSymbolAddress((void**)&qll, g_q_lo);
    cudaGetSymbolAddress((void**)&khh, g_k_hi);  cudaGetSymbolAddress((void**)&kll, g_k_lo);
    cudaGetSymbolAddress((void**)&vhh, g_v_hi);  cudaGetSymbolAddress((void**)&vll, g_v_lo);
    cudaGetSymbolAddress((void**)&wcinh, g_wcin_hi);  cudaGetSymbolAddress((void**)&wcinl, g_wcin_lo);
    cudaGetSymbolAddress((void**)&wcouth, g_wcout_hi);cudaGetSymbolAddress((void**)&wcoutl, g_wcout_lo);
    cudaGetSymbolAddress((void**)&wsih, g_wsi_hi);    cudaGetSymbolAddress((void**)&wsil, g_wsi_lo);
    cudaGetSymbolAddress((void**)&woih, g_woi_hi);    cudaGetSymbolAddress((void**)&woil, g_woi_lo);
    cudaGetSymbolAddress((void**)&wqAh, g_wqA_hi); cudaGetSymbolAddress((void**)&wqAl, g_wqA_lo);
    cudaGetSymbolAddress((void**)&wkAh, g_wkA_hi); cudaGetSymbolAddress((void**)&wkAl, g_wkA_lo);
    cudaGetSymbolAddress((void**)&wvAh, g_wvA_hi); cudaGetSymbolAddress((void**)&wvAl, g_wvA_lo);
    cudaGetSymbolAddress((void**)&wqBh, g_wqB_hi); cudaGetSymbolAddress((void**)&wqBl, g_wqB_lo);
    cudaGetSymbolAddress((void**)&wkBh, g_wkB_hi); cudaGetSymbolAddress((void**)&wkBl, g_wkB_lo);
    cudaGetSymbolAddress((void**)&wvBh, g_wvB_hi); cudaGetSymbolAddress((void**)&wvBl, g_wvB_lo);

    cudaFuncSetAttribute(tc_gemm<0,0,1>, cudaFuncAttributeMaxDynamicSharedMemorySize, TCG_SMEM);
    cudaFuncSetAttribute(tc_gemm<1,1,1>, cudaFuncAttributeMaxDynamicSharedMemorySize, TCG_SMEM);
    cudaFuncSetAttribute(tc_gemm<2,1,0>, cudaFuncAttributeMaxDynamicSharedMemorySize, TCG_SMEM);
    cudaFuncSetAttribute(qkv_mma,  cudaFuncAttributeMaxDynamicSharedMemorySize, QKV_SMEM);
    cudaFuncSetAttribute(attn_mma, cudaFuncAttributeMaxDynamicSharedMemorySize, ATTN_SMEM);

    dim3 gb(4, 4, BATCH);
    dim3 gq(8, NH, BATCH);
    dim3 gattn(4, NH, BATCH);
    dim3 gts(16, 16, BATCH), tts(32, 8);
    const long W4 = MB / 4, H4 = (long)NH * 4096 / 4;

    // Combined weights: fp32 GEMM with direct bf16 hi/lo epilogue (2 jobs)
    gemm64w<<<dim3(8, 8, 2), 256>>>(W_split_inter, W_proj_in, wcinh, wcinl,
                                    W_proj_out, W_out_inter, wcouth, wcoutl);

    // All independent weight splits in ONE launch
    SplitJobs jobs;
    jobs.j[0] = {(const float4*)W_split_intra, wsih, wsil, W4};
    jobs.j[1] = {(const float4*)W_out_intra,   woih, woil, W4};
    jobs.j[2] = {(const float4*)Wq_inter, wqAh, wqAl, H4};
    jobs.j[3] = {(const float4*)Wk_inter, wkAh, wkAl, H4};
    jobs.j[4] = {(const float4*)Wv_inter, wvAh, wvAl, H4};
    jobs.j[5] = {(const float4*)Wq_intra, wqBh, wqBl, H4};
    jobs.j[6] = {(const float4*)Wk_intra, wkBh, wkBl, H4};
    jobs.j[7] = {(const float4*)Wv_intra, wvBh, wvBl, H4};
    split8<<<dim3(256, 8, 1), 256>>>(jobs);

    transpose_split_kernel<<<gts, tts>>>(x, xTh, xTl);

    // GEMM1: xp = xT @ wcin^T  (bf16 out)
    tc_gemm<0,0,1><<<gb, 256, TCG_SMEM>>>(xTh, xTl, MB, wcinh, wcinl, 0,
                                          nullptr, xph, xpl, MB, nullptr, 0, nullptr);
    // inter path
    qkv_mma<<<gq, 128, QKV_SMEM>>>(xph, xpl, wqAh, wqAl, wkAh, wkAl, wvAh, wvAl,
                                   qhh, qll, khh, kll, vhh, vll);
    attn_mma<<<gattn, 256, ATTN_SMEM>>>(qhh, qll, khh, kll, vhh, vll,
                                        nullptr, cch, ccl);
    // GEMM2: oi = wcout @ cc^T + x  (fp32 + bf16 out)
    tc_gemm<1,1,1><<<gb, 256, TCG_SMEM>>>(wcouth, wcoutl, 0, cch, ccl, MB,
                                          oi, oih, oil, MB, x, MB, nullptr);
    // GEMM3: xi = oi @ wsi^T  (bf16 out, reuse xp)
    tc_gemm<0,0,1><<<gb, 256, TCG_SMEM>>>(oih, oil, MB, wsih, wsil, 0,
                                          nullptr, xph, xpl, MB, nullptr, 0, nullptr);
    // intra path
    qkv_mma<<<gq, 128, QKV_SMEM>>>(xph, xpl, wqBh, wqBl, wkBh, wkBl, wvBh, wvBl,
                                   qhh, qll, khh, kll, vhh, vll);
    attn_mma<<<gattn, 256, ATTN_SMEM>>>(qhh, qll, khh, kll, vhh, vll,
                                        mask, cch, ccl);
    // GEMM4: out = (1-a)*(cc @ woi^T) + a*oi
    tc_gemm<2,1,0><<<gb, 256, TCG_SMEM>>>(cch, ccl, MB, woih, woil, 0,
                                          out, nullptr, nullptr, MB, oi, MB, alpha);
}

// round 10
// speedup vs baseline: 1.0701x; 1.0701x over previous
#include <cuda_runtime.h>
#include <cuda_bf16.h>
#include <cstdint>

using bf = __nv_bfloat16;
static constexpr int  BATCH = 32;
static constexpr int  NH    = 8;
static constexpr long MB    = 512L * 512L;
static constexpr long HB    = 512L * 64L;

// ---------------------------------------------------------------------------
// Scratch (static __device__ arrays: allocation-free per harness rules)
// ---------------------------------------------------------------------------
__device__ float g_oi [(long)BATCH * 512 * 512];

__device__ bf g_xT_hi[(long)BATCH * MB], g_xT_lo[(long)BATCH * MB];
__device__ bf g_xp_hi[(long)BATCH * MB], g_xp_lo[(long)BATCH * MB];
__device__ bf g_cc_hi[(long)BATCH * MB], g_cc_lo[(long)BATCH * MB];
__device__ bf g_oi_hi[(long)BATCH * MB], g_oi_lo[(long)BATCH * MB];
__device__ bf g_q_hi[(long)BATCH * NH * HB], g_q_lo[(long)BATCH * NH * HB];
__device__ bf g_k_hi[(long)BATCH * NH * HB], g_k_lo[(long)BATCH * NH * HB];
__device__ bf g_v_hi[(long)BATCH * NH * HB], g_v_lo[(long)BATCH * NH * HB];

__device__ bf g_wcin_hi [MB], g_wcin_lo [MB];
__device__ bf g_wcout_hi[MB], g_wcout_lo[MB];
__device__ bf g_wsi_hi  [MB], g_wsi_lo  [MB];
__device__ bf g_woi_hi  [MB], g_woi_lo  [MB];
__device__ bf g_wqA_hi[NH*4096], g_wqA_lo[NH*4096];
__device__ bf g_wkA_hi[NH*4096], g_wkA_lo[NH*4096];
__device__ bf g_wvA_hi[NH*4096], g_wvA_lo[NH*4096];
__device__ bf g_wqB_hi[NH*4096], g_wqB_lo[NH*4096];
__device__ bf g_wkB_hi[NH*4096], g_wkB_lo[NH*4096];
__device__ bf g_wvB_hi[NH*4096], g_wvB_lo[NH*4096];

// ---------------------------------------------------------------------------
// Low-level helpers (sm_80+ baseline)
// ---------------------------------------------------------------------------
__device__ __forceinline__ void mma16816(float* c, const uint32_t* a,
                                         uint32_t b0, uint32_t b1) {
    asm volatile(
        "mma.sync.aligned.m16n8k16.row.col.f32.bf16.bf16.f32 "
        "{%0,%1,%2,%3}, {%4,%5,%6,%7}, {%8,%9}, {%0,%1,%2,%3};"
        : "+f"(c[0]), "+f"(c[1]), "+f"(c[2]), "+f"(c[3])
        : "r"(a[0]), "r"(a[1]), "r"(a[2]), "r"(a[3]), "r"(b0), "r"(b1));
}
__device__ __forceinline__ void ldsm4(uint32_t* r, uint32_t a) {
    asm volatile("ldmatrix.sync.aligned.m8n8.x4.shared.b16 {%0,%1,%2,%3}, [%4];"
                 : "=r"(r[0]), "=r"(r[1]), "=r"(r[2]), "=r"(r[3]) : "r"(a));
}
__device__ __forceinline__ void ldsm4t(uint32_t* r, uint32_t a) {
    asm volatile("ldmatrix.sync.aligned.m8n8.x4.trans.shared.b16 {%0,%1,%2,%3}, [%4];"
                 : "=r"(r[0]), "=r"(r[1]), "=r"(r[2]), "=r"(r[3]) : "r"(a));
}
__device__ __forceinline__ void cpa16(uint32_t s, const void* g) {
    asm volatile("cp.async.cg.shared.global [%0], [%1], 16;" :: "r"(s), "l"(g));
}
#define CP_COMMIT() asm volatile("cp.async.commit_group;" ::: "memory")
#define CP_WAIT(N)  asm volatile("cp.async.wait_group %0;" :: "n"(N) : "memory")
__device__ __forceinline__ uint32_t smem_u32(const void* p) {
    uint32_t a;
    asm("{ .reg .u64 t; cvta.to.shared.u64 t, %1; cvt.u32.u64 %0, t; }"
        : "=r"(a) : "l"(p));
    return a;
}
// XOR swizzles (conflict-free for ldsm 8-row phases)
__device__ __forceinline__ uint32_t sw64(int r, int c) {   // 64B rows
    return (uint32_t)(r * 64 + ((c ^ ((r >> 1) & 3)) << 4));
}
__device__ __forceinline__ uint32_t sw128(int r, int c) {  // 128B rows
    return (uint32_t)(r * 128 + ((c ^ (r & 7)) << 4));
}
__device__ __forceinline__ void split_pack(float a, float b,
                                           uint32_t& hi, uint32_t& lo) {
    __nv_bfloat162 h, l;
    h.x = __float2bfloat16_rn(a); h.y = __float2bfloat16_rn(b);
    l.x = __float2bfloat16_rn(a - __bfloat162float(h.x));
    l.y = __float2bfloat16_rn(b - __bfloat162float(h.y));
    hi = *reinterpret_cast<uint32_t*>(&h);
    lo = *reinterpret_cast<uint32_t*>(&l);
}
__device__ __forceinline__ void split_store(bf* H, bf* L, long off,
                                            float a, float b) {
    uint32_t h, l; split_pack(a, b, h, l);
    *reinterpret_cast<uint32_t*>(H + off) = h;
    *reinterpret_cast<uint32_t*>(L + off) = l;
}

// ---------------------------------------------------------------------------
// Batched fp32 -> bf16 hi/lo weight splits: 8 jobs, one launch
// ---------------------------------------------------------------------------
struct SplitJob  { const float4* src; bf* hi; bf* lo; long n4; };
struct SplitJobs { SplitJob j[8]; };

__global__ __launch_bounds__(256) void split8(SplitJobs jobs)
{
    const SplitJob jb = jobs.j[blockIdx.y];
    long i = (long)blockIdx.x * 256 + threadIdx.x;
    if (i >= jb.n4) return;
    float4 v = jb.src[i];
    uint32_t h0, l0, h1, l1;
    split_pack(v.x, v.y, h0, l0);
    split_pack(v.z, v.w, h1, l1);
    uint2 ph = {h0, h1}, pl = {l0, l1};
    *(uint2*)(jb.hi + i * 4) = ph;
    *(uint2*)(jb.lo + i * 4) = pl;
}

__global__ __launch_bounds__(256) void transpose_split_kernel(
    const float* __restrict__ in, bf* __restrict__ hi, bf* __restrict__ lo)
{
    __shared__ float t[32][33];
    const int b = blockIdx.z;
    const int s0 = blockIdx.x * 32, d0 = blockIdx.y * 32;
    const long base = (long)b * MB;
    const int tx = threadIdx.x, ty = threadIdx.y;
    #pragma unroll
    for (int i = ty; i < 32; i += 8)
        t[i][tx] = in[base + (long)(s0 + i) * 512 + d0 + tx];
    __syncthreads();
    #pragma unroll
    for (int i = ty; i < 32; i += 8) {
        float v = t[tx][i];
        bf h = __float2bfloat16_rn(v);
        bf l = __float2bfloat16_rn(v - __bfloat162float(h));
        long o = base + (long)(d0 + i) * 512 + s0 + tx;
        hi[o] = h; lo[o] = l;
    }
}

// ---------------------------------------------------------------------------
// Weight-combine GEMM (fp32 in, bf16 hi/lo out): C[m][n] = sum_k A[m,k]*B[k,n]
// ---------------------------------------------------------------------------
__global__ __launch_bounds__(256) void gemm64w(
    const float* __restrict__ A0, const float* __restrict__ B0,
    bf* __restrict__ C0h, bf* __restrict__ C0l,
    const float* __restrict__ A1, const float* __restrict__ B1,
    bf* __restrict__ C1h, bf* __restrict__ C1l)
{
    const float* A = blockIdx.z ? A1 : A0;
    const float* B = blockIdx.z ? B1 : B0;
    bf* Ch = blockIdx.z ? C1h : C0h;
    bf* Cl = blockIdx.z ? C1l : C0l;
    __shared__ float As[16][64], Bs[16][64];
    const int bM = blockIdx.y * 64, bN = blockIdx.x * 64;
    const int tid = threadIdx.x, tx = tid & 15, ty = tid >> 4;
    float acc[4][4];
    #pragma unroll
    for (int i = 0; i < 4; i++)
        #pragma unroll
        for (int j = 0; j < 4; j++) acc[i][j] = 0.f;
    for (int kt = 0; kt < 32; kt++) {
        const int k0 = kt * 16;
        __syncthreads();
        #pragma unroll
        for (int it = 0; it < 4; it++) {
            int id = tid + it * 256;
            As[id & 15][id >> 4] = A[(long)(bM + (id >> 4)) * 512 + k0 + (id & 15)];
            Bs[id >> 6][id & 63] = B[(long)(k0 + (id >> 6)) * 512 + bN + (id & 63)];
        }
        __syncthreads();
        #pragma unroll
        for (int k = 0; k < 16; k++) {
            float av[4], bv[4];
            #pragma unroll
            for (int i = 0; i < 4; i++) av[i] = As[k][ty * 4 + i];
            #pragma unroll
            for (int j = 0; j < 4; j++) bv[j] = Bs[k][tx * 4 + j];
            #pragma unroll
            for (int i = 0; i < 4; i++)
                #pragma unroll
                for (int j = 0; j < 4; j++)
                    acc[i][j] = fmaf(av[i], bv[j], acc[i][j]);
        }
    }
    #pragma unroll
    for (int i = 0; i < 4; i++) {
        const long o = (long)(bM + ty * 4 + i) * 512 + bN + tx * 4;
        split_store(Ch, Cl, o,     acc[i][0], acc[i][1]);
        split_store(Ch, Cl, o + 2, acc[i][2], acc[i][3]);
    }
}

// ---------------------------------------------------------------------------
// Pipelined tensor-core batched GEMM: C[b][m][n] = sum_k A[b][m][k]*B[b][n][k]
// BK=32, 3-stage cp.async, swizzled smem, ONE sync/iter, 3-term hi/lo.
// ---------------------------------------------------------------------------
static constexpr int ARR = 128 * 64;           // bytes per array (8192)
static constexpr int STG = 4 * ARR;            // bytes per stage  (32768)
static constexpr int TCG_SMEM = 3 * STG;       // 98304

__device__ __forceinline__ void tcg_load(
    uint32_t sb, const bf* Ah, const bf* Al, const bf* Bh, const bf* Bl,
    int bM, int bN, int k0, int tid)
{
    #pragma unroll
    for (int a = 0; a < 4; a++) {
        const bf* src = (a == 0) ? Ah : (a == 1) ? Al : (a == 2) ? Bh : Bl;
        const int row0 = (a < 2) ? bM : bN;
        const uint32_t dst = sb + a * ARR;
        #pragma unroll
        for (int it = 0; it < 2; it++) {
            int id = tid + it * 256;           // 0..511
            int r = id >> 2, c4 = id & 3;
            cpa16(dst + sw64(r, c4),
                  src + (long)(row0 + r) * 512 + k0 + c4 * 8);
        }
    }
}

template<int EPI, int OF32, int OBF16>
__global__ __launch_bounds__(256) void tc_gemm(
    const bf* __restrict__ Ahi, const bf* __restrict__ Alo, long sA,
    const bf* __restrict__ Bhi, const bf* __restrict__ Blo, long sB,
    float* __restrict__ C, bf* __restrict__ Chi, bf* __restrict__ Clo, long sC,
    const float* __restrict__ R, long sR, const float* __restrict__ alpha_ptr)
{
    extern __shared__ __align__(16) char smc[];
    const uint32_t sb0 = smem_u32(smc);
    const int tid = threadIdx.x, lane = tid & 31, wid = tid >> 5;
    const int g = lane >> 2, tg = lane & 3;
    const int wm = (wid >> 1) * 32, wn = (wid & 1) * 64;
    const int bN = blockIdx.x * 128, bM = blockIdx.y * 128, bz = blockIdx.z;
    Ahi += (long)bz * sA; Alo += (long)bz * sA;
    Bhi += (long)bz * sB; Blo += (long)bz * sB;
    if (EPI != 0) R += (long)bz * sR;

    const int lrow = (lane & 7) + ((lane >> 3) & 1) * 8;
    const int lch  = lane >> 4;                 // chunk half-select 0/1

    float acc[2][8][4];
    #pragma unroll
    for (int i = 0; i < 2; i++)
        #pragma unroll
        for (int j = 0; j < 8; j++)
            #pragma unroll
            for (int q = 0; q < 4; q++) acc[i][j][q] = 0.f;

    tcg_load(sb0,       Ahi, Alo, Bhi, Blo, bM, bN, 0,  tid); CP_COMMIT();
    tcg_load(sb0 + STG, Ahi, Alo, Bhi, Blo, bM, bN, 32, tid); CP_COMMIT();

    int st = 0, ld = 2;
    for (int t = 0; t < 16; t++) {
        if (t < 15) { CP_WAIT(1); } else { CP_WAIT(0); }
        __syncthreads();
        if (t < 14) {
            tcg_load(sb0 + ld * STG, Ahi, Alo, Bhi, Blo,
                     bM, bN, (t + 2) * 32, tid);
            CP_COMMIT();
            if (++ld == 3) ld = 0;
        }
        const uint32_t sb = sb0 + st * STG;
        if (++st == 3) st = 0;
        #pragma unroll
        for (int ks = 0; ks < 2; ks++) {
            const int ch = 2 * ks + lch;
            uint32_t ah[2][4], al[2][4];
            #pragma unroll
            for (int mi = 0; mi < 2; mi++) {
                uint32_t ad = sb + sw64(wm + mi * 16 + lrow, ch);
                ldsm4(ah[mi], ad);
                ldsm4(al[mi], ad + ARR);
            }
            uint32_t bh[4][4], bl[4][4];
            #pragma unroll
            for (int nb = 0; nb < 4; nb++) {
                uint32_t ad = sb + 2 * ARR + sw64(wn + nb * 16 + lrow, ch);
                ldsm4(bh[nb], ad);
                ldsm4(bl[nb], ad + ARR);
            }
            #pragma unroll
            for (int nb = 0; nb < 4; nb++)
                #pragma unroll
                for (int h2 = 0; h2 < 2; h2++) {
                    const uint32_t b0h = bh[nb][h2], b1h = bh[nb][h2 + 2];
                    const uint32_t b0l = bl[nb][h2], b1l = bl[nb][h2 + 2];
                    #pragma unroll
                    for (int mi = 0; mi < 2; mi++) {
                        float* a = acc[mi][nb * 2 + h2];
                        mma16816(a, ah[mi], b0h, b1h);
                        mma16816(a, ah[mi], b0l, b1l);
                        mma16816(a, al[mi], b0h, b1h);
                    }
                }
        }
    }

    float ab = 0.f;
    if (EPI == 2) ab = 1.f / (1.f + expf(-alpha_ptr[0]));
    #pragma unroll
    for (int mi = 0; mi < 2; mi++)
        #pragma unroll
        for (int nj = 0; nj < 8; nj++) {
            const int row = bM + wm + mi * 16 + g;
            const int col = bN + wn + nj * 8 + tg * 2;
            float v0 = acc[mi][nj][0], v1 = acc[mi][nj][1];
            float v2 = acc[mi][nj][2], v3 = acc[mi][nj][3];
            const long o0 = (long)bz * sC + (long)row * 512 + col;
            const long o1 = o0 + 8 * 512;
            if (EPI == 1) {
                float2 r0 = *(const float2*)(R + (long)row * 512 + col);
                float2 r1 = *(const float2*)(R + (long)(row + 8) * 512 + col);
                v0 += r0.x; v1 += r0.y; v2 += r1.x; v3 += r1.y;
            } else if (EPI == 2) {
                float2 r0 = *(const float2*)(R + (long)row * 512 + col);
                float2 r1 = *(const float2*)(R + (long)(row + 8) * 512 + col);
                v0 = (1.f - ab) * v0 + ab * r0.x;
                v1 = (1.f - ab) * v1 + ab * r0.y;
                v2 = (1.f - ab) * v2 + ab * r1.x;
                v3 = (1.f - ab) * v3 + ab * r1.y;
            }
            if (OF32) {
                float2 w0 = {v0, v1}, w1 = {v2, v3};
                *(float2*)(C + o0) = w0;
                *(float2*)(C + o1) = w1;
            }
            if (OBF16) {
                split_store(Chi, Clo, o0, v0, v1);
                split_store(Chi, Clo, o1, v2, v3);
            }
        }
}

// ---------------------------------------------------------------------------
// QKV projection (mma): per (64-token tile, head, batch).
// ---------------------------------------------------------------------------
static constexpr int SK = 72;
static constexpr int QKV_SMEM = 8 * 64 * SK * 2;   // 73728

__device__ __forceinline__ void head_gemm(
    uint32_t wbase, const uint32_t xh[4][4], const uint32_t xl[4][4],
    float scale, bf* Oh, bf* Ol, long obase, int row0, int lane)
{
    const int g = lane >> 2, tg = lane & 3;
    const uint32_t lrow = (lane & 7) + ((lane >> 3) & 1) * 8;
    const uint32_t lc8 = (lane >> 4) * 8;
    float acc[8][4];
    #pragma unroll
    for (int j = 0; j < 8; j++)
        #pragma unroll
        for (int q = 0; q < 4; q++) acc[j][q] = 0.f;
    #pragma unroll
    for (int ks = 0; ks < 4; ks++) {
        uint32_t bh[4][4], bl[4][4];
        #pragma unroll
        for (int nb = 0; nb < 4; nb++) {
            uint32_t ad = wbase + ((nb * 16 + lrow) * SK + ks * 16 + lc8) * 2;
            ldsm4(bh[nb], ad);
            ldsm4(bl[nb], ad + (uint32_t)(64 * SK * 2));
        }
        #pragma unroll
        for (int nb = 0; nb < 4; nb++)
            #pragma unroll
            for (int h2 = 0; h2 < 2; h2++) {
                float* a = acc[nb * 2 + h2];
                mma16816(a, xh[ks], bh[nb][h2], bh[nb][h2 + 2]);
                mma16816(a, xh[ks], bl[nb][h2], bl[nb][h2 + 2]);
                mma16816(a, xl[ks], bh[nb][h2], bh[nb][h2 + 2]);
            }
    }
    #pragma unroll
    for (int nj = 0; nj < 8; nj++) {
        const long o0 = obase + (long)(row0 + g) * 64 + nj * 8 + tg * 2;
        split_store(Oh, Ol, o0, acc[nj][0] * scale, acc[nj][1] * scale);
        split_store(Oh, Ol, o0 + 8 * 64, acc[nj][2] * scale, acc[nj][3] * scale);
    }
}

__global__ __launch_bounds__(128) void qkv_mma(
    const bf* __restrict__ Xh, const bf* __restrict__ Xl,
    const bf* __restrict__ Wqh, const bf* __restrict__ Wql,
    const bf* __restrict__ Wkh, const bf* __restrict__ Wkl,
    const bf* __restrict__ Wvh, const bf* __restrict__ Wvl,
    bf* __restrict__ Qh, bf* __restrict__ Ql,
    bf* __restrict__ Kh, bf* __restrict__ Kl,
    bf* __restrict__ Vh, bf* __restrict__ Vl)
{
    extern __shared__ __align__(16) bf smq[];
    const int tile0 = blockIdx.x * 64, h = blockIdx.y, b = blockIdx.z;
    const int tid = threadIdx.x, lane = tid & 31, wid = tid >> 5;
    const long xbase = (long)b * MB;
    const long obase = (long)(b * NH + h) * HB;
    bf* Xs = smq;
    bf* Ws = smq + 2 * 64 * SK;

    #pragma unroll
    for (int it = 0; it < 4; it++) {
        int id = tid + it * 128;
        int r = id >> 3, c8 = (id & 7) * 8;
        *(uint4*)(Xs + r * SK + c8) =
            *(const uint4*)(Xh + xbase + (long)(tile0 + r) * 512 + h * 64 + c8);
        *(uint4*)(Xs + 64 * SK + r * SK + c8) =
            *(const uint4*)(Xl + xbase + (long)(tile0 + r) * 512 + h * 64 + c8);
    }
    const bf* wsrc[6] = {Wqh, Wql, Wkh, Wkl, Wvh, Wvl};
    #pragma unroll
    for (int a = 0; a < 6; a++)
        #pragma unroll
        for (int it = 0; it < 4; it++) {
            int id = tid + it * 128;
            int r = id >> 3, c8 = (id & 7) * 8;
            *(uint4*)(Ws + a * 64 * SK + r * SK + c8) =
                *(const uint4*)(wsrc[a] + h * 4096 + r * 64 + c8);
        }
    __syncthreads();

    const uint32_t xb = smem_u32(Xs);
    const uint32_t lrow = (lane & 7) + ((lane >> 3) & 1) * 8;
    const uint32_t lc8 = (lane >> 4) * 8;
    uint32_t xhf[4][4], xlf[4][4];
    #pragma unroll
    for (int ks = 0; ks < 4; ks++) {
        uint32_t ad = xb + ((wid * 16 + lrow) * SK + ks * 16 + lc8) * 2;
        ldsm4(xhf[ks], ad);
        ldsm4(xlf[ks], ad + (uint32_t)(64 * SK * 2));
    }
    const uint32_t wb = smem_u32(Ws);
    const int row0 = tile0 + wid * 16;
    head_gemm(wb,             xhf, xlf, 0.125f, Qh, Ql, obase, row0, lane);
    head_gemm(wb + 2*64*SK*2, xhf, xlf, 1.f,    Kh, Kl, obase, row0, lane);
    head_gemm(wb + 4*64*SK*2, xhf, xlf, 1.f,    Vh, Vl, obase, row0, lane);
}

// ---------------------------------------------------------------------------
// Flash attention (mma): 256 threads, 128-row q-strip, 3-stage swizzled
// cp.async KV pipeline, ONE sync per kv-iter. Output bf16 hi/lo,
// head-concatenated: O[b][row][h*64+e].
// ---------------------------------------------------------------------------
static constexpr int AAR = 64 * 128;                 // bytes per KV array (8192)
static constexpr int STA = 4 * AAR;                  // bytes per stage (32768)
static constexpr int ATTN_SMEM = 3 * STA;            // 98304

__device__ __forceinline__ void attn_load_kv(
    uint32_t dst, const bf* Kh, const bf* Kl, const bf* Vh, const bf* Vl,
    long base, int kt, int tid)
{
    #pragma unroll
    for (int it = 0; it < 2; it++) {
        int id = tid + it * 256;       // 0..511
        int r = id >> 3, c8 = id & 7;
        const long gsrc = base + (long)(kt * 64 + r) * 64 + c8 * 8;
        const uint32_t so = sw128(r, c8);
        cpa16(dst           + so, Kh + gsrc);
        cpa16(dst +     AAR + so, Kl + gsrc);
        cpa16(dst + 2 * AAR + so, Vh + gsrc);
        cpa16(dst + 3 * AAR + so, Vl + gsrc);
    }
}

__global__ __launch_bounds__(256, 2) void attn_mma(
    const bf* __restrict__ Qh, const bf* __restrict__ Ql,
    const bf* __restrict__ Kh, const bf* __restrict__ Kl,
    const bf* __restrict__ Vh, const bf* __restrict__ Vl,
    const float* __restrict__ mask,
    bf* __restrict__ Oh, bf* __restrict__ Ol)
{
    extern __shared__ __align__(16) bf sma[];
    const int q0 = blockIdx.x * 128, h = blockIdx.y, b = blockIdx.z;
    const int tid = threadIdx.x, lane = tid & 31, wid = tid >> 5;
    const int g = lane >> 2, tg = lane & 3;
    const long base = (long)(b * NH + h) * HB;
    const uint32_t sb = smem_u32(sma);
    const int lrow = (lane & 7) + ((lane >> 3) & 1) * 8;
    const int lch  = lane >> 4;

    // Stage the 128-row Q strip: hi at sb, lo at sb+16384 (within stage 0)
    #pragma unroll
    for (int it = 0; it < 4; it++) {
        int id = tid + it * 256;       // 0..1023
        int r = id >> 3, c8 = id & 7;
        const long gq = base + (long)(q0 + r) * 64 + c8 * 8;
        cpa16(sb +         sw128(r, c8), Qh + gq);
        cpa16(sb + 16384 + sw128(r, c8), Ql + gq);
    }
    CP_COMMIT(); CP_WAIT(0);
    __syncthreads();
    uint32_t qh[4][4], ql[4][4];
    #pragma unroll
    for (int ks = 0; ks < 4; ks++) {
        uint32_t ad = sb + sw128(wid * 16 + lrow, 2 * ks + lch);
        ldsm4(qh[ks], ad);
        ldsm4(ql[ks], ad + 16384);
    }
    __syncthreads();   // all warps done reading Q before stages are reused

    float m0 = -1e30f, m1 = -1e30f, l0 = 0.f, l1 = 0.f;
    float o[8][4];
    #pragma unroll
    for (int j = 0; j < 8; j++)
        #pragma unroll
        for (int q = 0; q < 4; q++) o[j][q] = 0.f;

    attn_load_kv(sb,       Kh, Kl, Vh, Vl, base, 0, tid); CP_COMMIT();
    attn_load_kv(sb + STA, Kh, Kl, Vh, Vl, base, 1, tid); CP_COMMIT();

    int st = 0, ld = 2;
    for (int kt = 0; kt < 8; kt++) {
        if (kt < 7) { CP_WAIT(1); } else { CP_WAIT(0); }
        __syncthreads();
        if (kt < 6) {
            attn_load_kv(sb + ld * STA, Kh, Kl, Vh, Vl, base, kt + 2, tid);
            CP_COMMIT();
            if (++ld == 3) ld = 0;
        }
        const uint32_t KHs = sb + st * STA;
        if (++st == 3) st = 0;
        const uint32_t VHs = KHs + 2 * AAR;

        // S = Q K^T (3-term)
        float s[8][4];
        #pragma unroll
        for (int j = 0; j < 8; j++)
            #pragma unroll
            for (int q = 0; q < 4; q++) s[j][q] = 0.f;
        #pragma unroll
        for (int ks = 0; ks < 4; ks++) {
            uint32_t bh[4][4], bl[4][4];
            #pragma unroll
            for (int nb = 0; nb < 4; nb++) {
                uint32_t ad = KHs + sw128(nb * 16 + lrow, 2 * ks + lch);
                ldsm4(bh[nb], ad);
                ldsm4(bl[nb], ad + AAR);
            }
            #pragma unroll
            for (int nb = 0; nb < 4; nb++)
                #pragma unroll
                for (int h2 = 0; h2 < 2; h2++) {
                    float* a = s[nb * 2 + h2];
                    mma16816(a, qh[ks], bh[nb][h2], bh[nb][h2 + 2]);
                    mma16816(a, qh[ks], bl[nb][h2], bl[nb][h2 + 2]);
                    mma16816(a, ql[ks], bh[nb][h2], bh[nb][h2 + 2]);
                }
        }
        if (mask) {
            const int mr = q0 + wid * 16 + g;
            #pragma unroll
            for (int nj = 0; nj < 8; nj++) {
                const int mc = kt * 64 + nj * 8 + tg * 2;
                float2 a0 = *(const float2*)(mask + (long)mr * 512 + mc);
                float2 a1 = *(const float2*)(mask + (long)(mr + 8) * 512 + mc);
                s[nj][0] += a0.x; s[nj][1] += a0.y;
                s[nj][2] += a1.x; s[nj][3] += a1.y;
            }
        }

        // online softmax (rows g and g+8; reduce across tg lanes)
        float tm0 = -1e30f, tm1 = -1e30f;
        #pragma unroll
        for (int nj = 0; nj < 8; nj++) {
            tm0 = fmaxf(tm0, fmaxf(s[nj][0], s[nj][1]));
            tm1 = fmaxf(tm1, fmaxf(s[nj][2], s[nj][3]));
        }
        tm0 = fmaxf(tm0, __shfl_xor_sync(~0u, tm0, 1));
        tm0 = fmaxf(tm0, __shfl_xor_sync(~0u, tm0, 2));
        tm1 = fmaxf(tm1, __shfl_xor_sync(~0u, tm1, 1));
        tm1 = fmaxf(tm1, __shfl_xor_sync(~0u, tm1, 2));
        const float nm0 = fmaxf(m0, tm0), nm1 = fmaxf(m1, tm1);
        float sum0 = 0.f, sum1 = 0.f;
        #pragma unroll
        for (int nj = 0; nj < 8; nj++) {
            s[nj][0] = __expf(s[nj][0] - nm0); sum0 += s[nj][0];
            s[nj][1] = __expf(s[nj][1] - nm0); sum0 += s[nj][1];
            s[nj][2] = __expf(s[nj][2] - nm1); sum1 += s[nj][2];
            s[nj][3] = __expf(s[nj][3] - nm1); sum1 += s[nj][3];
        }
        sum0 += __shfl_xor_sync(~0u, sum0, 1);
        sum0 += __shfl_xor_sync(~0u, sum0, 2);
        sum1 += __shfl_xor_sync(~0u, sum1, 1);
        sum1 += __shfl_xor_sync(~0u, sum1, 2);
        const float c0 = __expf(m0 - nm0), c1 = __expf(m1 - nm1);
        l0 = l0 * c0 + sum0; l1 = l1 * c1 + sum1;
        m0 = nm0; m1 = nm1;
        #pragma unroll
        for (int j = 0; j < 8; j++) {
            o[j][0] *= c0; o[j][1] *= c0; o[j][2] *= c1; o[j][3] *= c1;
        }

        // P fragments (FA2 accum->A identity), hi/lo
        uint32_t ph[4][4], pl[4][4];
        #pragma unroll
        for (int ks = 0; ks < 4; ks++) {
            split_pack(s[2*ks][0],   s[2*ks][1],   ph[ks][0], pl[ks][0]);
            split_pack(s[2*ks][2],   s[2*ks][3],   ph[ks][1], pl[ks][1]);
            split_pack(s[2*ks+1][0], s[2*ks+1][1], ph[ks][2], pl[ks][2]);
            split_pack(s[2*ks+1][2], s[2*ks+1][3], ph[ks][3], pl[ks][3]);
        }

        // O += P V  (V^T fragments via ldmatrix.trans)
        #pragma unroll
        for (int ks = 0; ks < 4; ks++) {
            uint32_t vh[4][4], vl[4][4];
            #pragma unroll
            for (int nb = 0; nb < 4; nb++) {
                uint32_t ad = VHs + sw128(ks * 16 + (lane & 15), 2 * nb + lch);
                ldsm4t(vh[nb], ad);
                ldsm4t(vl[nb], ad + AAR);
            }
            #pragma unroll
            for (int nb = 0; nb < 4; nb++)
                #pragma unroll
                for (int h2 = 0; h2 < 2; h2++) {
                    float* a = o[nb * 2 + h2];
                    const uint32_t b0h = vh[nb][h2 * 2], b1h = vh[nb][h2 * 2 + 1];
                    const uint32_t b0l = vl[nb][h2 * 2], b1l = vl[nb][h2 * 2 + 1];
                    mma16816(a, ph[ks], b0h, b1h);
                    mma16816(a, ph[ks], b0l, b1l);
                    mma16816(a, pl[ks], b0h, b1h);
                }
        }
    }

    const float i0 = 1.f / l0, i1 = 1.f / l1;
    const int row = q0 + wid * 16 + g;
    #pragma unroll
    for (int nj = 0; nj < 8; nj++) {
        const long o0 = (long)b * MB + (long)row * 512 + h * 64 + nj * 8 + tg * 2;
        split_store(Oh, Ol, o0,           o[nj][0] * i0, o[nj][1] * i0);
        split_store(Oh, Ol, o0 + 8 * 512, o[nj][2] * i1, o[nj][3] * i1);
    }
}

// ---------------------------------------------------------------------------
// Launch sequence (single stream, graph-capturable, allocation-free)
// ---------------------------------------------------------------------------
extern "C" void kernel_launch(void* const* d_in, const int* in_sizes, int n_in,
                              void* d_out, int out_size)
{
    const float* x             = (const float*)d_in[0];
    const float* mask          = (const float*)d_in[1];
    const float* Wq_inter      = (const float*)d_in[2];
    const float* Wk_inter      = (const float*)d_in[3];
    const float* Wv_inter      = (const float*)d_in[4];
    const float* Wq_intra      = (const float*)d_in[5];
    const float* Wk_intra      = (const float*)d_in[6];
    const float* Wv_intra      = (const float*)d_in[7];
    const float* W_proj_in     = (const float*)d_in[8];
    const float* W_proj_out    = (const float*)d_in[9];
    const float* W_split_inter = (const float*)d_in[10];
    const float* W_out_inter   = (const float*)d_in[11];
    const float* W_split_intra = (const float*)d_in[12];
    const float* W_out_intra   = (const float*)d_in[13];
    const float* alpha         = (const float*)d_in[14];
    float* out = (float*)d_out;

    float* oi;
    cudaGetSymbolAddress((void**)&oi, g_oi);

    bf *xTh,*xTl,*xph,*xpl,*cch,*ccl,*oih,*oil,*qhh,*qll,*khh,*kll,*vhh,*vll;
    bf *wcinh,*wcinl,*wcouth,*wcoutl,*wsih,*wsil,*woih,*woil;
    bf *wqAh,*wqAl,*wkAh,*wkAl,*wvAh,*wvAl,*wqBh,*wqBl,*wkBh,*wkBl,*wvBh,*wvBl;
    cudaGetSymbolAddress((void**)&xTh, g_xT_hi); cudaGetSymbolAddress((void**)&xTl, g_xT_lo);
    cudaGetSymbolAddress((void**)&xph, g_xp_hi); cudaGetSymbolAddress((void**)&xpl, g_xp_lo);
    cudaGetSymbolAddress((void**)&cch, g_cc_hi); cudaGetSymbolAddress((void**)&ccl, g_cc_lo);
    cudaGetSymbolAddress((void**)&oih, g_oi_hi); cudaGetSymbolAddress((void**)&oil, g_oi_lo);
    cudaGetSymbolAddress((void**)&qhh, g_q_hi);  cudaGetSymbolAddress((void**)&qll, g_q_lo);
    cudaGetSymbolAddress((void**)&khh, g_k_hi);  cudaGetSymbolAddress((void**)&kll, g_k_lo);
    cudaGetSymbolAddress((void**)&vhh, g_v_hi);  cudaGetSymbolAddress((void**)&vll, g_v_lo);
    cudaGetSymbolAddress((void**)&wcinh, g_wcin_hi);  cudaGetSymbolAddress((void**)&wcinl, g_wcin_lo);
    cudaGetSymbolAddress((void**)&wcouth, g_wcout_hi);cudaGetSymbolAddress((void**)&wcoutl, g_wcout_lo);
    cudaGetSymbolAddress((void**)&wsih, g_wsi_hi);    cudaGetSymbolAddress((void**)&wsil, g_wsi_lo);
    cudaGetSymbolAddress((void**)&woih, g_woi_hi);    cudaGetSymbolAddress((void**)&woil, g_woi_lo);
    cudaGetSymbolAddress((void**)&wqAh, g_wqA_hi); cudaGetSymbolAddress((void**)&wqAl, g_wqA_lo);
    cudaGetSymbolAddress((void**)&wkAh, g_wkA_hi); cudaGetSymbolAddress((void**)&wkAl, g_wkA_lo);
    cudaGetSymbolAddress((void**)&wvAh, g_wvA_hi); cudaGetSymbolAddress((void**)&wvAl, g_wvA_lo);
    cudaGetSymbolAddress((void**)&wqBh, g_wqB_hi); cudaGetSymbolAddress((void**)&wqBl, g_wqB_lo);
    cudaGetSymbolAddress((void**)&wkBh, g_wkB_hi); cudaGetSymbolAddress((void**)&wkBl, g_wkB_lo);
    cudaGetSymbolAddress((void**)&wvBh, g_wvB_hi); cudaGetSymbolAddress((void**)&wvBl, g_wvB_lo);

    cudaFuncSetAttribute(tc_gemm<0,0,1>, cudaFuncAttributeMaxDynamicSharedMemorySize, TCG_SMEM);
    cudaFuncSetAttribute(tc_gemm<1,1,1>, cudaFuncAttributeMaxDynamicSharedMemorySize, TCG_SMEM);
    cudaFuncSetAttribute(tc_gemm<2,1,0>, cudaFuncAttributeMaxDynamicSharedMemorySize, TCG_SMEM);
    cudaFuncSetAttribute(qkv_mma,  cudaFuncAttributeMaxDynamicSharedMemorySize, QKV_SMEM);
    cudaFuncSetAttribute(attn_mma, cudaFuncAttributeMaxDynamicSharedMemorySize, ATTN_SMEM);

    dim3 gb(4, 4, BATCH);
    dim3 gq(8, NH, BATCH);
    dim3 gattn(4, NH, BATCH);
    dim3 gts(16, 16, BATCH), tts(32, 8);
    const long W4 = MB / 4, H4 = (long)NH * 4096 / 4;

    // Combined weights: fp32 GEMM with direct bf16 hi/lo epilogue (2 jobs)
    gemm64w<<<dim3(8, 8, 2), 256>>>(W_split_inter, W_proj_in, wcinh, wcinl,
                                    W_proj_out, W_out_inter, wcouth, wcoutl);

    // All independent weight splits in ONE launch
    SplitJobs jobs;
    jobs.j[0] = {(const float4*)W_split_intra, wsih, wsil, W4};
    jobs.j[1] = {(const float4*)W_out_intra,   woih, woil, W4};
    jobs.j[2] = {(const float4*)Wq_inter, wqAh, wqAl, H4};
    jobs.j[3] = {(const float4*)Wk_inter, wkAh, wkAl, H4};
    jobs.j[4] = {(const float4*)Wv_inter, wvAh, wvAl, H4};
    jobs.j[5] = {(const float4*)Wq_intra, wqBh, wqBl, H4};
    jobs.j[6] = {(const float4*)Wk_intra, wkBh, wkBl, H4};
    jobs.j[7] = {(const float4*)Wv_intra, wvBh, wvBl, H4};
    split8<<<dim3(256, 8, 1), 256>>>(jobs);

    transpose_split_kernel<<<gts, tts>>>(x, xTh, xTl);

    // GEMM1: xp = xT @ wcin^T  (bf16 out)
    tc_gemm<0,0,1><<<gb, 256, TCG_SMEM>>>(xTh, xTl, MB, wcinh, wcinl, 0,
                                          nullptr, xph, xpl, MB, nullptr, 0, nullptr);
    // inter path
    qkv_mma<<<gq, 128, QKV_SMEM>>>(xph, xpl, wqAh, wqAl, wkAh, wkAl, wvAh, wvAl,
                                   qhh, qll, khh, kll, vhh, vll);
    attn_mma<<<gattn, 256, ATTN_SMEM>>>(qhh, qll, khh, kll, vhh, vll,
                                        nullptr, cch, ccl);
    // GEMM2: oi = wcout @ cc^T + x  (fp32 + bf16 out)
    tc_gemm<1,1,1><<<gb, 256, TCG_SMEM>>>(wcouth, wcoutl, 0, cch, ccl, MB,
                                          oi, oih, oil, MB, x, MB, nullptr);
    // GEMM3: xi = oi @ wsi^T  (bf16 out, reuse xp)
    tc_gemm<0,0,1><<<gb, 256, TCG_SMEM>>>(oih, oil, MB, wsih, wsil, 0,
                                          nullptr, xph, xpl, MB, nullptr, 0, nullptr);
    // intra path
    qkv_mma<<<gq, 128, QKV_SMEM>>>(xph, xpl, wqBh, wqBl, wkBh, wkBl, wvBh, wvBl,
                                   qhh, qll, khh, kll, vhh, vll);
    attn_mma<<<gattn, 256, ATTN_SMEM>>>(qhh, qll, khh, kll, vhh, vll,
                                        mask, cch, ccl);
    // GEMM4: out = (1-a)*(cc @ woi^T) + a*oi
    tc_gemm<2,1,0><<<gb, 256, TCG_SMEM>>>(cch, ccl, MB, woih, woil, 0,
                                          out, nullptr, nullptr, MB, oi, MB, alpha);
}

// round 11
// speedup vs baseline: 1.1177x; 1.0444x over previous
#include <cuda_runtime.h>
#include <cuda_bf16.h>
#include <cstdint>

using bf = __nv_bfloat16;
static constexpr int  BATCH = 32;
static constexpr int  NH    = 8;
static constexpr long MB    = 512L * 512L;
static constexpr long HB    = 512L * 64L;

// ---------------------------------------------------------------------------
// Scratch (static __device__ arrays: allocation-free per harness rules)
// ---------------------------------------------------------------------------
__device__ float g_oi [(long)BATCH * 512 * 512];

__device__ bf g_xT_hi[(long)BATCH * MB], g_xT_lo[(long)BATCH * MB];
__device__ bf g_xp_hi[(long)BATCH * MB], g_xp_lo[(long)BATCH * MB];
__device__ bf g_cc_hi[(long)BATCH * MB], g_cc_lo[(long)BATCH * MB];
__device__ bf g_oi_hi[(long)BATCH * MB], g_oi_lo[(long)BATCH * MB];
__device__ bf g_q_hi[(long)BATCH * NH * HB], g_q_lo[(long)BATCH * NH * HB];
__device__ bf g_k_hi[(long)BATCH * NH * HB], g_k_lo[(long)BATCH * NH * HB];
__device__ bf g_v_hi[(long)BATCH * NH * HB], g_v_lo[(long)BATCH * NH * HB];

__device__ bf g_wcin_hi [MB], g_wcin_lo [MB];
__device__ bf g_wcout_hi[MB], g_wcout_lo[MB];
__device__ bf g_wsi_hi  [MB], g_wsi_lo  [MB];
__device__ bf g_woi_hi  [MB], g_woi_lo  [MB];
__device__ bf g_wqA_hi[NH*4096], g_wqA_lo[NH*4096];
__device__ bf g_wkA_hi[NH*4096], g_wkA_lo[NH*4096];
__device__ bf g_wvA_hi[NH*4096], g_wvA_lo[NH*4096];
__device__ bf g_wqB_hi[NH*4096], g_wqB_lo[NH*4096];
__device__ bf g_wkB_hi[NH*4096], g_wkB_lo[NH*4096];
__device__ bf g_wvB_hi[NH*4096], g_wvB_lo[NH*4096];

// ---------------------------------------------------------------------------
// Low-level helpers (sm_80+ baseline)
// ---------------------------------------------------------------------------
__device__ __forceinline__ void mma16816(float* c, const uint32_t* a,
                                         uint32_t b0, uint32_t b1) {
    asm volatile(
        "mma.sync.aligned.m16n8k16.row.col.f32.bf16.bf16.f32 "
        "{%0,%1,%2,%3}, {%4,%5,%6,%7}, {%8,%9}, {%0,%1,%2,%3};"
        : "+f"(c[0]), "+f"(c[1]), "+f"(c[2]), "+f"(c[3])
        : "r"(a[0]), "r"(a[1]), "r"(a[2]), "r"(a[3]), "r"(b0), "r"(b1));
}
__device__ __forceinline__ void ldsm4(uint32_t* r, uint32_t a) {
    asm volatile("ldmatrix.sync.aligned.m8n8.x4.shared.b16 {%0,%1,%2,%3}, [%4];"
                 : "=r"(r[0]), "=r"(r[1]), "=r"(r[2]), "=r"(r[3]) : "r"(a));
}
__device__ __forceinline__ void ldsm4t(uint32_t* r, uint32_t a) {
    asm volatile("ldmatrix.sync.aligned.m8n8.x4.trans.shared.b16 {%0,%1,%2,%3}, [%4];"
                 : "=r"(r[0]), "=r"(r[1]), "=r"(r[2]), "=r"(r[3]) : "r"(a));
}
__device__ __forceinline__ void cpa16(uint32_t s, const void* g) {
    asm volatile("cp.async.cg.shared.global [%0], [%1], 16;" :: "r"(s), "l"(g));
}
#define CP_COMMIT() asm volatile("cp.async.commit_group;" ::: "memory")
#define CP_WAIT(N)  asm volatile("cp.async.wait_group %0;" :: "n"(N) : "memory")
__device__ __forceinline__ uint32_t smem_u32(const void* p) {
    uint32_t a;
    asm("{ .reg .u64 t; cvta.to.shared.u64 t, %1; cvt.u32.u64 %0, t; }"
        : "=r"(a) : "l"(p));
    return a;
}
// XOR swizzles (conflict-free for ldsm 8-row phases)
__device__ __forceinline__ uint32_t sw64(int r, int c) {   // 64B rows
    return (uint32_t)(r * 64 + ((c ^ ((r >> 1) & 3)) << 4));
}
__device__ __forceinline__ uint32_t sw128(int r, int c) {  // 128B rows
    return (uint32_t)(r * 128 + ((c ^ (r & 7)) << 4));
}
__device__ __forceinline__ void split_pack(float a, float b,
                                           uint32_t& hi, uint32_t& lo) {
    __nv_bfloat162 h, l;
    h.x = __float2bfloat16_rn(a); h.y = __float2bfloat16_rn(b);
    l.x = __float2bfloat16_rn(a - __bfloat162float(h.x));
    l.y = __float2bfloat16_rn(b - __bfloat162float(h.y));
    hi = *reinterpret_cast<uint32_t*>(&h);
    lo = *reinterpret_cast<uint32_t*>(&l);
}
__device__ __forceinline__ void split_store(bf* H, bf* L, long off,
                                            float a, float b) {
    uint32_t h, l; split_pack(a, b, h, l);
    *reinterpret_cast<uint32_t*>(H + off) = h;
    *reinterpret_cast<uint32_t*>(L + off) = l;
}

// ---------------------------------------------------------------------------
// Batched fp32 -> bf16 hi/lo weight splits: 8 jobs, one launch
// ---------------------------------------------------------------------------
struct SplitJob  { const float4* src; bf* hi; bf* lo; long n4; };
struct SplitJobs { SplitJob j[8]; };

__global__ __launch_bounds__(256) void split8(SplitJobs jobs)
{
    const SplitJob jb = jobs.j[blockIdx.y];
    long i = (long)blockIdx.x * 256 + threadIdx.x;
    if (i >= jb.n4) return;
    float4 v = jb.src[i];
    uint32_t h0, l0, h1, l1;
    split_pack(v.x, v.y, h0, l0);
    split_pack(v.z, v.w, h1, l1);
    uint2 ph = {h0, h1}, pl = {l0, l1};
    *(uint2*)(jb.hi + i * 4) = ph;
    *(uint2*)(jb.lo + i * 4) = pl;
}

__global__ __launch_bounds__(256) void transpose_split_kernel(
    const float* __restrict__ in, bf* __restrict__ hi, bf* __restrict__ lo)
{
    __shared__ float t[32][33];
    const int b = blockIdx.z;
    const int s0 = blockIdx.x * 32, d0 = blockIdx.y * 32;
    const long base = (long)b * MB;
    const int tx = threadIdx.x, ty = threadIdx.y;
    #pragma unroll
    for (int i = ty; i < 32; i += 8)
        t[i][tx] = in[base + (long)(s0 + i) * 512 + d0 + tx];
    __syncthreads();
    #pragma unroll
    for (int i = ty; i < 32; i += 8) {
        float v = t[tx][i];
        bf h = __float2bfloat16_rn(v);
        bf l = __float2bfloat16_rn(v - __bfloat162float(h));
        long o = base + (long)(d0 + i) * 512 + s0 + tx;
        hi[o] = h; lo[o] = l;
    }
}

// ---------------------------------------------------------------------------
// Weight-combine GEMM (fp32 in, bf16 hi/lo out): C[m][n] = sum_k A[m,k]*B[k,n]
// ---------------------------------------------------------------------------
__global__ __launch_bounds__(256) void gemm64w(
    const float* __restrict__ A0, const float* __restrict__ B0,
    bf* __restrict__ C0h, bf* __restrict__ C0l,
    const float* __restrict__ A1, const float* __restrict__ B1,
    bf* __restrict__ C1h, bf* __restrict__ C1l)
{
    const float* A = blockIdx.z ? A1 : A0;
    const float* B = blockIdx.z ? B1 : B0;
    bf* Ch = blockIdx.z ? C1h : C0h;
    bf* Cl = blockIdx.z ? C1l : C0l;
    __shared__ float As[16][64], Bs[16][64];
    const int bM = blockIdx.y * 64, bN = blockIdx.x * 64;
    const int tid = threadIdx.x, tx = tid & 15, ty = tid >> 4;
    float acc[4][4];
    #pragma unroll
    for (int i = 0; i < 4; i++)
        #pragma unroll
        for (int j = 0; j < 4; j++) acc[i][j] = 0.f;
    for (int kt = 0; kt < 32; kt++) {
        const int k0 = kt * 16;
        __syncthreads();
        #pragma unroll
        for (int it = 0; it < 4; it++) {
            int id = tid + it * 256;
            As[id & 15][id >> 4] = A[(long)(bM + (id >> 4)) * 512 + k0 + (id & 15)];
            Bs[id >> 6][id & 63] = B[(long)(k0 + (id >> 6)) * 512 + bN + (id & 63)];
        }
        __syncthreads();
        #pragma unroll
        for (int k = 0; k < 16; k++) {
            float av[4], bv[4];
            #pragma unroll
            for (int i = 0; i < 4; i++) av[i] = As[k][ty * 4 + i];
            #pragma unroll
            for (int j = 0; j < 4; j++) bv[j] = Bs[k][tx * 4 + j];
            #pragma unroll
            for (int i = 0; i < 4; i++)
                #pragma unroll
                for (int j = 0; j < 4; j++)
                    acc[i][j] = fmaf(av[i], bv[j], acc[i][j]);
        }
    }
    #pragma unroll
    for (int i = 0; i < 4; i++) {
        const long o = (long)(bM + ty * 4 + i) * 512 + bN + tx * 4;
        split_store(Ch, Cl, o,     acc[i][0], acc[i][1]);
        split_store(Ch, Cl, o + 2, acc[i][2], acc[i][3]);
    }
}

// ---------------------------------------------------------------------------
// Pipelined tensor-core batched GEMM: C[b][m][n] = sum_k A[b][m][k]*B[b][n][k]
// BK=32, 3-stage cp.async, swizzled smem, ONE sync/iter, 3-term hi/lo.
// __launch_bounds__(256, 2): 128-reg cap so 2 CTAs/SM stay resident.
// ---------------------------------------------------------------------------
static constexpr int ARR = 128 * 64;           // bytes per array (8192)
static constexpr int STG = 4 * ARR;            // bytes per stage  (32768)
static constexpr int TCG_SMEM = 3 * STG;       // 98304

__device__ __forceinline__ void tcg_load(
    uint32_t sb, const bf* Ah, const bf* Al, const bf* Bh, const bf* Bl,
    int bM, int bN, int k0, int tid)
{
    #pragma unroll
    for (int a = 0; a < 4; a++) {
        const bf* src = (a == 0) ? Ah : (a == 1) ? Al : (a == 2) ? Bh : Bl;
        const int row0 = (a < 2) ? bM : bN;
        const uint32_t dst = sb + a * ARR;
        #pragma unroll
        for (int it = 0; it < 2; it++) {
            int id = tid + it * 256;           // 0..511
            int r = id >> 2, c4 = id & 3;
            cpa16(dst + sw64(r, c4),
                  src + (long)(row0 + r) * 512 + k0 + c4 * 8);
        }
    }
}

template<int EPI, int OF32, int OBF16>
__global__ __launch_bounds__(256, 2) void tc_gemm(
    const bf* __restrict__ Ahi, const bf* __restrict__ Alo, long sA,
    const bf* __restrict__ Bhi, const bf* __restrict__ Blo, long sB,
    float* __restrict__ C, bf* __restrict__ Chi, bf* __restrict__ Clo, long sC,
    const float* __restrict__ R, long sR, const float* __restrict__ alpha_ptr)
{
    extern __shared__ __align__(16) char smc[];
    const uint32_t sb0 = smem_u32(smc);
    const int tid = threadIdx.x, lane = tid & 31, wid = tid >> 5;
    const int g = lane >> 2, tg = lane & 3;
    const int wm = (wid >> 1) * 32, wn = (wid & 1) * 64;
    const int bN = blockIdx.x * 128, bM = blockIdx.y * 128, bz = blockIdx.z;
    Ahi += (long)bz * sA; Alo += (long)bz * sA;
    Bhi += (long)bz * sB; Blo += (long)bz * sB;
    if (EPI != 0) R += (long)bz * sR;

    const int lrow = (lane & 7) + ((lane >> 3) & 1) * 8;
    const int lch  = lane >> 4;                 // chunk half-select 0/1

    float acc[2][8][4];
    #pragma unroll
    for (int i = 0; i < 2; i++)
        #pragma unroll
        for (int j = 0; j < 8; j++)
            #pragma unroll
            for (int q = 0; q < 4; q++) acc[i][j][q] = 0.f;

    tcg_load(sb0,       Ahi, Alo, Bhi, Blo, bM, bN, 0,  tid); CP_COMMIT();
    tcg_load(sb0 + STG, Ahi, Alo, Bhi, Blo, bM, bN, 32, tid); CP_COMMIT();

    int st = 0, ld = 2;
    for (int t = 0; t < 16; t++) {
        if (t < 15) { CP_WAIT(1); } else { CP_WAIT(0); }
        __syncthreads();
        if (t < 14) {
            tcg_load(sb0 + ld * STG, Ahi, Alo, Bhi, Blo,
                     bM, bN, (t + 2) * 32, tid);
            CP_COMMIT();
            if (++ld == 3) ld = 0;
        }
        const uint32_t sb = sb0 + st * STG;
        if (++st == 3) st = 0;
        #pragma unroll
        for (int ks = 0; ks < 2; ks++) {
            const int ch = 2 * ks + lch;
            uint32_t ah[2][4], al[2][4];
            #pragma unroll
            for (int mi = 0; mi < 2; mi++) {
                uint32_t ad = sb + sw64(wm + mi * 16 + lrow, ch);
                ldsm4(ah[mi], ad);
                ldsm4(al[mi], ad + ARR);
            }
            // B fragments loaded per-nb (short live range -> fits 128 regs)
            #pragma unroll
            for (int nb = 0; nb < 4; nb++) {
                uint32_t bh[4], bl[4];
                uint32_t ad = sb + 2 * ARR + sw64(wn + nb * 16 + lrow, ch);
                ldsm4(bh, ad);
                ldsm4(bl, ad + ARR);
                #pragma unroll
                for (int h2 = 0; h2 < 2; h2++) {
                    const uint32_t b0h = bh[h2], b1h = bh[h2 + 2];
                    const uint32_t b0l = bl[h2], b1l = bl[h2 + 2];
                    #pragma unroll
                    for (int mi = 0; mi < 2; mi++) {
                        float* a = acc[mi][nb * 2 + h2];
                        mma16816(a, ah[mi], b0h, b1h);
                        mma16816(a, ah[mi], b0l, b1l);
                        mma16816(a, al[mi], b0h, b1h);
                    }
                }
            }
        }
    }

    float ab = 0.f;
    if (EPI == 2) ab = 1.f / (1.f + expf(-alpha_ptr[0]));
    #pragma unroll
    for (int mi = 0; mi < 2; mi++)
        #pragma unroll
        for (int nj = 0; nj < 8; nj++) {
            const int row = bM + wm + mi * 16 + g;
            const int col = bN + wn + nj * 8 + tg * 2;
            float v0 = acc[mi][nj][0], v1 = acc[mi][nj][1];
            float v2 = acc[mi][nj][2], v3 = acc[mi][nj][3];
            const long o0 = (long)bz * sC + (long)row * 512 + col;
            const long o1 = o0 + 8 * 512;
            if (EPI == 1) {
                float2 r0 = *(const float2*)(R + (long)row * 512 + col);
                float2 r1 = *(const float2*)(R + (long)(row + 8) * 512 + col);
                v0 += r0.x; v1 += r0.y; v2 += r1.x; v3 += r1.y;
            } else if (EPI == 2) {
                float2 r0 = *(const float2*)(R + (long)row * 512 + col);
                float2 r1 = *(const float2*)(R + (long)(row + 8) * 512 + col);
                v0 = (1.f - ab) * v0 + ab * r0.x;
                v1 = (1.f - ab) * v1 + ab * r0.y;
                v2 = (1.f - ab) * v2 + ab * r1.x;
                v3 = (1.f - ab) * v3 + ab * r1.y;
            }
            if (OF32) {
                float2 w0 = {v0, v1}, w1 = {v2, v3};
                *(float2*)(C + o0) = w0;
                *(float2*)(C + o1) = w1;
            }
            if (OBF16) {
                split_store(Chi, Clo, o0, v0, v1);
                split_store(Chi, Clo, o1, v2, v3);
            }
        }
}

// ---------------------------------------------------------------------------
// QKV projection (mma): per (64-token tile, head, batch).
// ---------------------------------------------------------------------------
static constexpr int SK = 72;
static constexpr int QKV_SMEM = 8 * 64 * SK * 2;   // 73728

__device__ __forceinline__ void head_gemm(
    uint32_t wbase, const uint32_t xh[4][4], const uint32_t xl[4][4],
    float scale, bf* Oh, bf* Ol, long obase, int row0, int lane)
{
    const int g = lane >> 2, tg = lane & 3;
    const uint32_t lrow = (lane & 7) + ((lane >> 3) & 1) * 8;
    const uint32_t lc8 = (lane >> 4) * 8;
    float acc[8][4];
    #pragma unroll
    for (int j = 0; j < 8; j++)
        #pragma unroll
        for (int q = 0; q < 4; q++) acc[j][q] = 0.f;
    #pragma unroll
    for (int ks = 0; ks < 4; ks++) {
        #pragma unroll
        for (int nb = 0; nb < 4; nb++) {
            uint32_t bh[4], bl[4];
            uint32_t ad = wbase + ((nb * 16 + lrow) * SK + ks * 16 + lc8) * 2;
            ldsm4(bh, ad);
            ldsm4(bl, ad + (uint32_t)(64 * SK * 2));
            #pragma unroll
            for (int h2 = 0; h2 < 2; h2++) {
                float* a = acc[nb * 2 + h2];
                mma16816(a, xh[ks], bh[h2], bh[h2 + 2]);
                mma16816(a, xh[ks], bl[h2], bl[h2 + 2]);
                mma16816(a, xl[ks], bh[h2], bh[h2 + 2]);
            }
        }
    }
    #pragma unroll
    for (int nj = 0; nj < 8; nj++) {
        const long o0 = obase + (long)(row0 + g) * 64 + nj * 8 + tg * 2;
        split_store(Oh, Ol, o0, acc[nj][0] * scale, acc[nj][1] * scale);
        split_store(Oh, Ol, o0 + 8 * 64, acc[nj][2] * scale, acc[nj][3] * scale);
    }
}

__global__ __launch_bounds__(128) void qkv_mma(
    const bf* __restrict__ Xh, const bf* __restrict__ Xl,
    const bf* __restrict__ Wqh, const bf* __restrict__ Wql,
    const bf* __restrict__ Wkh, const bf* __restrict__ Wkl,
    const bf* __restrict__ Wvh, const bf* __restrict__ Wvl,
    bf* __restrict__ Qh, bf* __restrict__ Ql,
    bf* __restrict__ Kh, bf* __restrict__ Kl,
    bf* __restrict__ Vh, bf* __restrict__ Vl)
{
    extern __shared__ __align__(16) bf smq[];
    const int tile0 = blockIdx.x * 64, h = blockIdx.y, b = blockIdx.z;
    const int tid = threadIdx.x, lane = tid & 31, wid = tid >> 5;
    const long xbase = (long)b * MB;
    const long obase = (long)(b * NH + h) * HB;
    bf* Xs = smq;
    bf* Ws = smq + 2 * 64 * SK;

    #pragma unroll
    for (int it = 0; it < 4; it++) {
        int id = tid + it * 128;
        int r = id >> 3, c8 = (id & 7) * 8;
        *(uint4*)(Xs + r * SK + c8) =
            *(const uint4*)(Xh + xbase + (long)(tile0 + r) * 512 + h * 64 + c8);
        *(uint4*)(Xs + 64 * SK + r * SK + c8) =
            *(const uint4*)(Xl + xbase + (long)(tile0 + r) * 512 + h * 64 + c8);
    }
    const bf* wsrc[6] = {Wqh, Wql, Wkh, Wkl, Wvh, Wvl};
    #pragma unroll
    for (int a = 0; a < 6; a++)
        #pragma unroll
        for (int it = 0; it < 4; it++) {
            int id = tid + it * 128;
            int r = id >> 3, c8 = (id & 7) * 8;
            *(uint4*)(Ws + a * 64 * SK + r * SK + c8) =
                *(const uint4*)(wsrc[a] + h * 4096 + r * 64 + c8);
        }
    __syncthreads();

    const uint32_t xb = smem_u32(Xs);
    const uint32_t lrow = (lane & 7) + ((lane >> 3) & 1) * 8;
    const uint32_t lc8 = (lane >> 4) * 8;
    uint32_t xhf[4][4], xlf[4][4];
    #pragma unroll
    for (int ks = 0; ks < 4; ks++) {
        uint32_t ad = xb + ((wid * 16 + lrow) * SK + ks * 16 + lc8) * 2;
        ldsm4(xhf[ks], ad);
        ldsm4(xlf[ks], ad + (uint32_t)(64 * SK * 2));
    }
    const uint32_t wb = smem_u32(Ws);
    const int row0 = tile0 + wid * 16;
    head_gemm(wb,             xhf, xlf, 0.125f, Qh, Ql, obase, row0, lane);
    head_gemm(wb + 2*64*SK*2, xhf, xlf, 1.f,    Kh, Kl, obase, row0, lane);
    head_gemm(wb + 4*64*SK*2, xhf, xlf, 1.f,    Vh, Vl, obase, row0, lane);
}

// ---------------------------------------------------------------------------
// Flash attention (mma): 256 threads, 128-row q-strip, 3-stage swizzled
// cp.async KV pipeline, ONE sync per kv-iter. Output bf16 hi/lo,
// head-concatenated: O[b][row][h*64+e].
// ---------------------------------------------------------------------------
static constexpr int AAR = 64 * 128;                 // bytes per KV array (8192)
static constexpr int STA = 4 * AAR;                  // bytes per stage (32768)
static constexpr int ATTN_SMEM = 3 * STA;            // 98304

__device__ __forceinline__ void attn_load_kv(
    uint32_t dst, const bf* Kh, const bf* Kl, const bf* Vh, const bf* Vl,
    long base, int kt, int tid)
{
    #pragma unroll
    for (int it = 0; it < 2; it++) {
        int id = tid + it * 256;       // 0..511
        int r = id >> 3, c8 = id & 7;
        const long gsrc = base + (long)(kt * 64 + r) * 64 + c8 * 8;
        const uint32_t so = sw128(r, c8);
        cpa16(dst           + so, Kh + gsrc);
        cpa16(dst +     AAR + so, Kl + gsrc);
        cpa16(dst + 2 * AAR + so, Vh + gsrc);
        cpa16(dst + 3 * AAR + so, Vl + gsrc);
    }
}

__global__ __launch_bounds__(256, 2) void attn_mma(
    const bf* __restrict__ Qh, const bf* __restrict__ Ql,
    const bf* __restrict__ Kh, const bf* __restrict__ Kl,
    const bf* __restrict__ Vh, const bf* __restrict__ Vl,
    const float* __restrict__ mask,
    bf* __restrict__ Oh, bf* __restrict__ Ol)
{
    extern __shared__ __align__(16) bf sma[];
    const int q0 = blockIdx.x * 128, h = blockIdx.y, b = blockIdx.z;
    const int tid = threadIdx.x, lane = tid & 31, wid = tid >> 5;
    const int g = lane >> 2, tg = lane & 3;
    const long base = (long)(b * NH + h) * HB;
    const uint32_t sb = smem_u32(sma);
    const int lrow = (lane & 7) + ((lane >> 3) & 1) * 8;
    const int lch  = lane >> 4;

    // Stage the 128-row Q strip: hi at sb, lo at sb+16384 (within stage 0)
    #pragma unroll
    for (int it = 0; it < 4; it++) {
        int id = tid + it * 256;       // 0..1023
        int r = id >> 3, c8 = id & 7;
        const long gq = base + (long)(q0 + r) * 64 + c8 * 8;
        cpa16(sb +         sw128(r, c8), Qh + gq);
        cpa16(sb + 16384 + sw128(r, c8), Ql + gq);
    }
    CP_COMMIT(); CP_WAIT(0);
    __syncthreads();
    uint32_t qh[4][4], ql[4][4];
    #pragma unroll
    for (int ks = 0; ks < 4; ks++) {
        uint32_t ad = sb + sw128(wid * 16 + lrow, 2 * ks + lch);
        ldsm4(qh[ks], ad);
        ldsm4(ql[ks], ad + 16384);
    }
    __syncthreads();   // all warps done reading Q before stages are reused

    float m0 = -1e30f, m1 = -1e30f, l0 = 0.f, l1 = 0.f;
    float o[8][4];
    #pragma unroll
    for (int j = 0; j < 8; j++)
        #pragma unroll
        for (int q = 0; q < 4; q++) o[j][q] = 0.f;

    attn_load_kv(sb,       Kh, Kl, Vh, Vl, base, 0, tid); CP_COMMIT();
    attn_load_kv(sb + STA, Kh, Kl, Vh, Vl, base, 1, tid); CP_COMMIT();

    int st = 0, ld = 2;
    for (int kt = 0; kt < 8; kt++) {
        if (kt < 7) { CP_WAIT(1); } else { CP_WAIT(0); }
        __syncthreads();
        if (kt < 6) {
            attn_load_kv(sb + ld * STA, Kh, Kl, Vh, Vl, base, kt + 2, tid);
            CP_COMMIT();
            if (++ld == 3) ld = 0;
        }
        const uint32_t KHs = sb + st * STA;
        if (++st == 3) st = 0;
        const uint32_t VHs = KHs + 2 * AAR;

        // S = Q K^T (3-term)
        float s[8][4];
        #pragma unroll
        for (int j = 0; j < 8; j++)
            #pragma unroll
            for (int q = 0; q < 4; q++) s[j][q] = 0.f;
        #pragma unroll
        for (int ks = 0; ks < 4; ks++) {
            #pragma unroll
            for (int nb = 0; nb < 4; nb++) {
                uint32_t bh[4], bl[4];
                uint32_t ad = KHs + sw128(nb * 16 + lrow, 2 * ks + lch);
                ldsm4(bh, ad);
                ldsm4(bl, ad + AAR);
                #pragma unroll
                for (int h2 = 0; h2 < 2; h2++) {
                    float* a = s[nb * 2 + h2];
                    mma16816(a, qh[ks], bh[h2], bh[h2 + 2]);
                    mma16816(a, qh[ks], bl[h2], bl[h2 + 2]);
                    mma16816(a, ql[ks], bh[h2], bh[h2 + 2]);
                }
            }
        }
        if (mask) {
            const int mr = q0 + wid * 16 + g;
            #pragma unroll
            for (int nj = 0; nj < 8; nj++) {
                const int mc = kt * 64 + nj * 8 + tg * 2;
                float2 a0 = *(const float2*)(mask + (long)mr * 512 + mc);
                float2 a1 = *(const float2*)(mask + (long)(mr + 8) * 512 + mc);
                s[nj][0] += a0.x; s[nj][1] += a0.y;
                s[nj][2] += a1.x; s[nj][3] += a1.y;
            }
        }

        // online softmax (rows g and g+8; reduce across tg lanes)
        float tm0 = -1e30f, tm1 = -1e30f;
        #pragma unroll
        for (int nj = 0; nj < 8; nj++) {
            tm0 = fmaxf(tm0, fmaxf(s[nj][0], s[nj][1]));
            tm1 = fmaxf(tm1, fmaxf(s[nj][2], s[nj][3]));
        }
        tm0 = fmaxf(tm0, __shfl_xor_sync(~0u, tm0, 1));
        tm0 = fmaxf(tm0, __shfl_xor_sync(~0u, tm0, 2));
        tm1 = fmaxf(tm1, __shfl_xor_sync(~0u, tm1, 1));
        tm1 = fmaxf(tm1, __shfl_xor_sync(~0u, tm1, 2));
        const float nm0 = fmaxf(m0, tm0), nm1 = fmaxf(m1, tm1);
        float sum0 = 0.f, sum1 = 0.f;
        #pragma unroll
        for (int nj = 0; nj < 8; nj++) {
            s[nj][0] = __expf(s[nj][0] - nm0); sum0 += s[nj][0];
            s[nj][1] = __expf(s[nj][1] - nm0); sum0 += s[nj][1];
            s[nj][2] = __expf(s[nj][2] - nm1); sum1 += s[nj][2];
            s[nj][3] = __expf(s[nj][3] - nm1); sum1 += s[nj][3];
        }
        sum0 += __shfl_xor_sync(~0u, sum0, 1);
        sum0 += __shfl_xor_sync(~0u, sum0, 2);
        sum1 += __shfl_xor_sync(~0u, sum1, 1);
        sum1 += __shfl_xor_sync(~0u, sum1, 2);
        const float c0 = __expf(m0 - nm0), c1 = __expf(m1 - nm1);
        l0 = l0 * c0 + sum0; l1 = l1 * c1 + sum1;
        m0 = nm0; m1 = nm1;
        #pragma unroll
        for (int j = 0; j < 8; j++) {
            o[j][0] *= c0; o[j][1] *= c0; o[j][2] *= c1; o[j][3] *= c1;
        }

        // P fragments (FA2 accum->A identity), hi/lo
        uint32_t ph[4][4], pl[4][4];
        #pragma unroll
        for (int ks = 0; ks < 4; ks++) {
            split_pack(s[2*ks][0],   s[2*ks][1],   ph[ks][0], pl[ks][0]);
            split_pack(s[2*ks][2],   s[2*ks][3],   ph[ks][1], pl[ks][1]);
            split_pack(s[2*ks+1][0], s[2*ks+1][1], ph[ks][2], pl[ks][2]);
            split_pack(s[2*ks+1][2], s[2*ks+1][3], ph[ks][3], pl[ks][3]);
        }

        // O += P V  (V^T fragments via ldmatrix.trans)
        #pragma unroll
        for (int ks = 0; ks < 4; ks++) {
            #pragma unroll
            for (int nb = 0; nb < 4; nb++) {
                uint32_t vh[4], vl[4];
                uint32_t ad = VHs + sw128(ks * 16 + (lane & 15), 2 * nb + lch);
                ldsm4t(vh, ad);
                ldsm4t(vl, ad + AAR);
                #pragma unroll
                for (int h2 = 0; h2 < 2; h2++) {
                    float* a = o[nb * 2 + h2];
                    const uint32_t b0h = vh[h2 * 2], b1h = vh[h2 * 2 + 1];
                    const uint32_t b0l = vl[h2 * 2], b1l = vl[h2 * 2 + 1];
                    mma16816(a, ph[ks], b0h, b1h);
                    mma16816(a, ph[ks], b0l, b1l);
                    mma16816(a, pl[ks], b0h, b1h);
                }
            }
        }
    }

    const float i0 = 1.f / l0, i1 = 1.f / l1;
    const int row = q0 + wid * 16 + g;
    #pragma unroll
    for (int nj = 0; nj < 8; nj++) {
        const long o0 = (long)b * MB + (long)row * 512 + h * 64 + nj * 8 + tg * 2;
        split_store(Oh, Ol, o0,           o[nj][0] * i0, o[nj][1] * i0);
        split_store(Oh, Ol, o0 + 8 * 512, o[nj][2] * i1, o[nj][3] * i1);
    }
}

// ---------------------------------------------------------------------------
// Launch sequence (single stream, graph-capturable, allocation-free)
// ---------------------------------------------------------------------------
extern "C" void kernel_launch(void* const* d_in, const int* in_sizes, int n_in,
                              void* d_out, int out_size)
{
    const float* x             = (const float*)d_in[0];
    const float* mask          = (const float*)d_in[1];
    const float* Wq_inter      = (const float*)d_in[2];
    const float* Wk_inter      = (const float*)d_in[3];
    const float* Wv_inter      = (const float*)d_in[4];
    const float* Wq_intra      = (const float*)d_in[5];
    const float* Wk_intra      = (const float*)d_in[6];
    const float* Wv_intra      = (const float*)d_in[7];
    const float* W_proj_in     = (const float*)d_in[8];
    const float* W_proj_out    = (const float*)d_in[9];
    const float* W_split_inter = (const float*)d_in[10];
    const float* W_out_inter   = (const float*)d_in[11];
    const float* W_split_intra = (const float*)d_in[12];
    const float* W_out_intra   = (const float*)d_in[13];
    const float* alpha         = (const float*)d_in[14];
    float* out = (float*)d_out;

    float* oi;
    cudaGetSymbolAddress((void**)&oi, g_oi);

    bf *xTh,*xTl,*xph,*xpl,*cch,*ccl,*oih,*oil,*qhh,*qll,*khh,*kll,*vhh,*vll;
    bf *wcinh,*wcinl,*wcouth,*wcoutl,*wsih,*wsil,*woih,*woil;
    bf *wqAh,*wqAl,*wkAh,*wkAl,*wvAh,*wvAl,*wqBh,*wqBl,*wkBh,*wkBl,*wvBh,*wvBl;
    cudaGetSymbolAddress((void**)&xTh, g_xT_hi); cudaGetSymbolAddress((void**)&xTl, g_xT_lo);
    cudaGetSymbolAddress((void**)&xph, g_xp_hi); cudaGetSymbolAddress((void**)&xpl, g_xp_lo);
    cudaGetSymbolAddress((void**)&cch, g_cc_hi); cudaGetSymbolAddress((void**)&ccl, g_cc_lo);
    cudaGetSymbolAddress((void**)&oih, g_oi_hi); cudaGetSymbolAddress((void**)&oil, g_oi_lo);
    cudaGetSymbolAddress((void**)&qhh, g_q_hi);  cudaGetSymbolAddress((void**)&qll, g_q_lo);
    cudaGetSymbolAddress((void**)&khh, g_k_hi);  cudaGetSymbolAddress((void**)&kll, g_k_lo);
    cudaGetSymbolAddress((void**)&vhh, g_v_hi);  cudaGetSymbolAddress((void**)&vll, g_v_lo);
    cudaGetSymbolAddress((void**)&wcinh, g_wcin_hi);  cudaGetSymbolAddress((void**)&wcinl, g_wcin_lo);
    cudaGetSymbolAddress((void**)&wcouth, g_wcout_hi);cudaGetSymbolAddress((void**)&wcoutl, g_wcout_lo);
    cudaGetSymbolAddress((void**)&wsih, g_wsi_hi);    cudaGetSymbolAddress((void**)&wsil, g_wsi_lo);
    cudaGetSymbolAddress((void**)&woih, g_woi_hi);    cudaGetSymbolAddress((void**)&woil, g_woi_lo);
    cudaGetSymbolAddress((void**)&wqAh, g_wqA_hi); cudaGetSymbolAddress((void**)&wqAl, g_wqA_lo);
    cudaGetSymbolAddress((void**)&wkAh, g_wkA_hi); cudaGetSymbolAddress((void**)&wkAl, g_wkA_lo);
    cudaGetSymbolAddress((void**)&wvAh, g_wvA_hi); cudaGetSymbolAddress((void**)&wvAl, g_wvA_lo);
    cudaGetSymbolAddress((void**)&wqBh, g_wqB_hi); cudaGetSymbolAddress((void**)&wqBl, g_wqB_lo);
    cudaGetSymbolAddress((void**)&wkBh, g_wkB_hi); cudaGetSymbolAddress((void**)&wkBl, g_wkB_lo);
    cudaGetSymbolAddress((void**)&wvBh, g_wvB_hi); cudaGetSymbolAddress((void**)&wvBl, g_wvB_lo);

    cudaFuncSetAttribute(tc_gemm<0,0,1>, cudaFuncAttributeMaxDynamicSharedMemorySize, TCG_SMEM);
    cudaFuncSetAttribute(tc_gemm<1,1,1>, cudaFuncAttributeMaxDynamicSharedMemorySize, TCG_SMEM);
    cudaFuncSetAttribute(tc_gemm<2,1,0>, cudaFuncAttributeMaxDynamicSharedMemorySize, TCG_SMEM);
    cudaFuncSetAttribute(qkv_mma,  cudaFuncAttributeMaxDynamicSharedMemorySize, QKV_SMEM);
    cudaFuncSetAttribute(attn_mma, cudaFuncAttributeMaxDynamicSharedMemorySize, ATTN_SMEM);

    dim3 gb(4, 4, BATCH);
    dim3 gq(8, NH, BATCH);
    dim3 gattn(4, NH, BATCH);
    dim3 gts(16, 16, BATCH), tts(32, 8);
    const long W4 = MB / 4, H4 = (long)NH * 4096 / 4;

    // Combined weights: fp32 GEMM with direct bf16 hi/lo epilogue (2 jobs)
    gemm64w<<<dim3(8, 8, 2), 256>>>(W_split_inter, W_proj_in, wcinh, wcinl,
                                    W_proj_out, W_out_inter, wcouth, wcoutl);

    // All independent weight splits in ONE launch
    SplitJobs jobs;
    jobs.j[0] = {(const float4*)W_split_intra, wsih, wsil, W4};
    jobs.j[1] = {(const float4*)W_out_intra,   woih, woil, W4};
    jobs.j[2] = {(const float4*)Wq_inter, wqAh, wqAl, H4};
    jobs.j[3] = {(const float4*)Wk_inter, wkAh, wkAl, H4};
    jobs.j[4] = {(const float4*)Wv_inter, wvAh, wvAl, H4};
    jobs.j[5] = {(const float4*)Wq_intra, wqBh, wqBl, H4};
    jobs.j[6] = {(const float4*)Wk_intra, wkBh, wkBl, H4};
    jobs.j[7] = {(const float4*)Wv_intra, wvBh, wvBl, H4};
    split8<<<dim3(256, 8, 1), 256>>>(jobs);

    transpose_split_kernel<<<gts, tts>>>(x, xTh, xTl);

    // GEMM1: xp = xT @ wcin^T  (bf16 out)
    tc_gemm<0,0,1><<<gb, 256, TCG_SMEM>>>(xTh, xTl, MB, wcinh, wcinl, 0,
                                          nullptr, xph, xpl, MB, nullptr, 0, nullptr);
    // inter path
    qkv_mma<<<gq, 128, QKV_SMEM>>>(xph, xpl, wqAh, wqAl, wkAh, wkAl, wvAh, wvAl,
                                   qhh, qll, khh, kll, vhh, vll);
    attn_mma<<<gattn, 256, ATTN_SMEM>>>(qhh, qll, khh, kll, vhh, vll,
                                        nullptr, cch, ccl);
    // GEMM2: oi = wcout @ cc^T + x  (fp32 + bf16 out)
    tc_gemm<1,1,1><<<gb, 256, TCG_SMEM>>>(wcouth, wcoutl, 0, cch, ccl, MB,
                                          oi, oih, oil, MB, x, MB, nullptr);
    // GEMM3: xi = oi @ wsi^T  (bf16 out, reuse xp)
    tc_gemm<0,0,1><<<gb, 256, TCG_SMEM>>>(oih, oil, MB, wsih, wsil, 0,
                                          nullptr, xph, xpl, MB, nullptr, 0, nullptr);
    // intra path
    qkv_mma<<<gq, 128, QKV_SMEM>>>(xph, xpl, wqBh, wqBl, wkBh, wkBl, wvBh, wvBl,
                                   qhh, qll, khh, kll, vhh, vll);
    attn_mma<<<gattn, 256, ATTN_SMEM>>>(qhh, qll, khh, kll, vhh, vll,
                                        mask, cch, ccl);
    // GEMM4: out = (1-a)*(cc @ woi^T) + a*oi
    tc_gemm<2,1,0><<<gb, 256, TCG_SMEM>>>(cch, ccl, MB, woih, woil, 0,
                                          out, nullptr, nullptr, MB, oi, MB, alpha);
}

// round 12
// speedup vs baseline: 1.8787x; 1.6809x over previous
#include <cuda_runtime.h>
#include <cuda_bf16.h>
#include <cstdint>

using bf = __nv_bfloat16;
static constexpr int  BATCH = 32;
static constexpr int  NH    = 8;
static constexpr long MB    = 512L * 512L;
static constexpr long HB    = 512L * 64L;

// ---------------------------------------------------------------------------
// Scratch (static __device__ arrays: allocation-free per harness rules)
// ---------------------------------------------------------------------------
__device__ float g_oi [(long)BATCH * 512 * 512];

__device__ bf g_xT [(long)BATCH * MB];
__device__ bf g_xp [(long)BATCH * MB];
__device__ bf g_cc [(long)BATCH * MB];
__device__ bf g_oib[(long)BATCH * MB];
__device__ bf g_q_hi[(long)BATCH * NH * HB], g_q_lo[(long)BATCH * NH * HB];
__device__ bf g_k_hi[(long)BATCH * NH * HB], g_k_lo[(long)BATCH * NH * HB];
__device__ bf g_v   [(long)BATCH * NH * HB];

__device__ bf g_wcin [MB];
__device__ bf g_wcout[MB];
__device__ bf g_wsi  [MB];
__device__ bf g_woi  [MB];
__device__ bf g_wqA[NH*4096], g_wkA[NH*4096], g_wvA[NH*4096];
__device__ bf g_wqB[NH*4096], g_wkB[NH*4096], g_wvB[NH*4096];

// ---------------------------------------------------------------------------
// Low-level helpers (sm_80+ baseline)
// ---------------------------------------------------------------------------
__device__ __forceinline__ void mma16816(float* c, const uint32_t* a,
                                         uint32_t b0, uint32_t b1) {
    asm volatile(
        "mma.sync.aligned.m16n8k16.row.col.f32.bf16.bf16.f32 "
        "{%0,%1,%2,%3}, {%4,%5,%6,%7}, {%8,%9}, {%0,%1,%2,%3};"
        : "+f"(c[0]), "+f"(c[1]), "+f"(c[2]), "+f"(c[3])
        : "r"(a[0]), "r"(a[1]), "r"(a[2]), "r"(a[3]), "r"(b0), "r"(b1));
}
__device__ __forceinline__ void ldsm4(uint32_t* r, uint32_t a) {
    asm volatile("ldmatrix.sync.aligned.m8n8.x4.shared.b16 {%0,%1,%2,%3}, [%4];"
                 : "=r"(r[0]), "=r"(r[1]), "=r"(r[2]), "=r"(r[3]) : "r"(a));
}
__device__ __forceinline__ void ldsm4t(uint32_t* r, uint32_t a) {
    asm volatile("ldmatrix.sync.aligned.m8n8.x4.trans.shared.b16 {%0,%1,%2,%3}, [%4];"
                 : "=r"(r[0]), "=r"(r[1]), "=r"(r[2]), "=r"(r[3]) : "r"(a));
}
__device__ __forceinline__ void cpa16(uint32_t s, const void* g) {
    asm volatile("cp.async.cg.shared.global [%0], [%1], 16;" :: "r"(s), "l"(g));
}
#define CP_COMMIT() asm volatile("cp.async.commit_group;" ::: "memory")
#define CP_WAIT(N)  asm volatile("cp.async.wait_group %0;" :: "n"(N) : "memory")
__device__ __forceinline__ uint32_t smem_u32(const void* p) {
    uint32_t a;
    asm("{ .reg .u64 t; cvta.to.shared.u64 t, %1; cvt.u32.u64 %0, t; }"
        : "=r"(a) : "l"(p));
    return a;
}
// XOR swizzles (conflict-free for ldsm 8-row phases)
__device__ __forceinline__ uint32_t sw64(int r, int c) {   // 64B rows
    return (uint32_t)(r * 64 + ((c ^ ((r >> 1) & 3)) << 4));
}
__device__ __forceinline__ uint32_t sw128(int r, int c) {  // 128B rows
    return (uint32_t)(r * 128 + ((c ^ (r & 7)) << 4));
}
__device__ __forceinline__ void split_pack(float a, float b,
                                           uint32_t& hi, uint32_t& lo) {
    __nv_bfloat162 h, l;
    h.x = __float2bfloat16_rn(a); h.y = __float2bfloat16_rn(b);
    l.x = __float2bfloat16_rn(a - __bfloat162float(h.x));
    l.y = __float2bfloat16_rn(b - __bfloat162float(h.y));
    hi = *reinterpret_cast<uint32_t*>(&h);
    lo = *reinterpret_cast<uint32_t*>(&l);
}
__device__ __forceinline__ void split_store(bf* H, bf* L, long off,
                                            float a, float b) {
    uint32_t h, l; split_pack(a, b, h, l);
    *reinterpret_cast<uint32_t*>(H + off) = h;
    *reinterpret_cast<uint32_t*>(L + off) = l;
}
__device__ __forceinline__ void pack_store(bf* C, long off, float a, float b) {
    __nv_bfloat162 h;
    h.x = __float2bfloat16_rn(a); h.y = __float2bfloat16_rn(b);
    *reinterpret_cast<uint32_t*>(C + off) = *reinterpret_cast<uint32_t*>(&h);
}
__device__ __forceinline__ uint32_t pack_bf2(float a, float b) {
    __nv_bfloat162 h;
    h.x = __float2bfloat16_rn(a); h.y = __float2bfloat16_rn(b);
    return *reinterpret_cast<uint32_t*>(&h);
}

// ---------------------------------------------------------------------------
// Batched fp32 -> bf16 weight conversions: 8 jobs, one launch
// ---------------------------------------------------------------------------
struct SplitJob  { const float4* src; bf* dst; long n4; };
struct SplitJobs { SplitJob j[8]; };

__global__ __launch_bounds__(256) void split8(SplitJobs jobs)
{
    const SplitJob jb = jobs.j[blockIdx.y];
    long i = (long)blockIdx.x * 256 + threadIdx.x;
    if (i >= jb.n4) return;
    float4 v = jb.src[i];
    uint2 p;
    p.x = pack_bf2(v.x, v.y);
    p.y = pack_bf2(v.z, v.w);
    *(uint2*)(jb.dst + i * 4) = p;
}

__global__ __launch_bounds__(256) void transpose_bf16_kernel(
    const float* __restrict__ in, bf* __restrict__ outb)
{
    __shared__ float t[32][33];
    const int b = blockIdx.z;
    const int s0 = blockIdx.x * 32, d0 = blockIdx.y * 32;
    const long base = (long)b * MB;
    const int tx = threadIdx.x, ty = threadIdx.y;
    #pragma unroll
    for (int i = ty; i < 32; i += 8)
        t[i][tx] = in[base + (long)(s0 + i) * 512 + d0 + tx];
    __syncthreads();
    #pragma unroll
    for (int i = ty; i < 32; i += 8) {
        long o = base + (long)(d0 + i) * 512 + s0 + tx;
        outb[o] = __float2bfloat16_rn(t[tx][i]);
    }
}

// ---------------------------------------------------------------------------
// Weight-combine GEMM (fp32 in, bf16 out): C[m][n] = sum_k A[m,k]*B[k,n]
// ---------------------------------------------------------------------------
__global__ __launch_bounds__(256) void gemm64w(
    const float* __restrict__ A0, const float* __restrict__ B0,
    bf* __restrict__ C0,
    const float* __restrict__ A1, const float* __restrict__ B1,
    bf* __restrict__ C1)
{
    const float* A = blockIdx.z ? A1 : A0;
    const float* B = blockIdx.z ? B1 : B0;
    bf* Cb = blockIdx.z ? C1 : C0;
    __shared__ float As[16][64], Bs[16][64];
    const int bM = blockIdx.y * 64, bN = blockIdx.x * 64;
    const int tid = threadIdx.x, tx = tid & 15, ty = tid >> 4;
    float acc[4][4];
    #pragma unroll
    for (int i = 0; i < 4; i++)
        #pragma unroll
        for (int j = 0; j < 4; j++) acc[i][j] = 0.f;
    for (int kt = 0; kt < 32; kt++) {
        const int k0 = kt * 16;
        __syncthreads();
        #pragma unroll
        for (int it = 0; it < 4; it++) {
            int id = tid + it * 256;
            As[id & 15][id >> 4] = A[(long)(bM + (id >> 4)) * 512 + k0 + (id & 15)];
            Bs[id >> 6][id & 63] = B[(long)(k0 + (id >> 6)) * 512 + bN + (id & 63)];
        }
        __syncthreads();
        #pragma unroll
        for (int k = 0; k < 16; k++) {
            float av[4], bv[4];
            #pragma unroll
            for (int i = 0; i < 4; i++) av[i] = As[k][ty * 4 + i];
            #pragma unroll
            for (int j = 0; j < 4; j++) bv[j] = Bs[k][tx * 4 + j];
            #pragma unroll
            for (int i = 0; i < 4; i++)
                #pragma unroll
                for (int j = 0; j < 4; j++)
                    acc[i][j] = fmaf(av[i], bv[j], acc[i][j]);
        }
    }
    #pragma unroll
    for (int i = 0; i < 4; i++) {
        const long o = (long)(bM + ty * 4 + i) * 512 + bN + tx * 4;
        pack_store(Cb, o,     acc[i][0], acc[i][1]);
        pack_store(Cb, o + 2, acc[i][2], acc[i][3]);
    }
}

// ---------------------------------------------------------------------------
// Pipelined tensor-core batched GEMM (1-term bf16):
// C[b][m][n] = sum_k A[b][m][k]*B[b][n][k]
// BK=32, 3-stage cp.async, swizzled smem, ONE sync/iter.
// ---------------------------------------------------------------------------
static constexpr int ARR = 128 * 64;           // bytes per array (8192)
static constexpr int STG = 2 * ARR;            // bytes per stage  (16384)
static constexpr int TCG_SMEM = 3 * STG;       // 49152

__device__ __forceinline__ void tcg_load(
    uint32_t sb, const bf* A, const bf* B, int bM, int bN, int k0, int tid)
{
    #pragma unroll
    for (int a = 0; a < 2; a++) {
        const bf* src = a ? B : A;
        const int row0 = a ? bN : bM;
        const uint32_t dst = sb + a * ARR;
        #pragma unroll
        for (int it = 0; it < 2; it++) {
            int id = tid + it * 256;           // 0..511
            int r = id >> 2, c4 = id & 3;
            cpa16(dst + sw64(r, c4),
                  src + (long)(row0 + r) * 512 + k0 + c4 * 8);
        }
    }
}

template<int EPI, int OF32, int OBF16>
__global__ __launch_bounds__(256, 2) void tc_gemm(
    const bf* __restrict__ A, long sA,
    const bf* __restrict__ B, long sB,
    float* __restrict__ C, bf* __restrict__ Cb, long sC,
    const float* __restrict__ R, long sR, const float* __restrict__ alpha_ptr)
{
    extern __shared__ __align__(16) char smc[];
    const uint32_t sb0 = smem_u32(smc);
    const int tid = threadIdx.x, lane = tid & 31, wid = tid >> 5;
    const int g = lane >> 2, tg = lane & 3;
    const int wm = (wid >> 1) * 32, wn = (wid & 1) * 64;
    const int bN = blockIdx.x * 128, bM = blockIdx.y * 128, bz = blockIdx.z;
    A += (long)bz * sA;
    B += (long)bz * sB;
    if (EPI != 0) R += (long)bz * sR;

    const int lrow = (lane & 7) + ((lane >> 3) & 1) * 8;
    const int lch  = lane >> 4;                 // chunk half-select 0/1

    float acc[2][8][4];
    #pragma unroll
    for (int i = 0; i < 2; i++)
        #pragma unroll
        for (int j = 0; j < 8; j++)
            #pragma unroll
            for (int q = 0; q < 4; q++) acc[i][j][q] = 0.f;

    tcg_load(sb0,       A, B, bM, bN, 0,  tid); CP_COMMIT();
    tcg_load(sb0 + STG, A, B, bM, bN, 32, tid); CP_COMMIT();

    int st = 0, ld = 2;
    for (int t = 0; t < 16; t++) {
        if (t < 15) { CP_WAIT(1); } else { CP_WAIT(0); }
        __syncthreads();
        if (t < 14) {
            tcg_load(sb0 + ld * STG, A, B, bM, bN, (t + 2) * 32, tid);
            CP_COMMIT();
            if (++ld == 3) ld = 0;
        }
        const uint32_t sb = sb0 + st * STG;
        if (++st == 3) st = 0;
        #pragma unroll
        for (int ks = 0; ks < 2; ks++) {
            const int ch = 2 * ks + lch;
            uint32_t af[2][4];
            #pragma unroll
            for (int mi = 0; mi < 2; mi++)
                ldsm4(af[mi], sb + sw64(wm + mi * 16 + lrow, ch));
            #pragma unroll
            for (int nb = 0; nb < 4; nb++) {
                uint32_t bh[4];
                ldsm4(bh, sb + ARR + sw64(wn + nb * 16 + lrow, ch));
                #pragma unroll
                for (int h2 = 0; h2 < 2; h2++)
                    #pragma unroll
                    for (int mi = 0; mi < 2; mi++)
                        mma16816(acc[mi][nb * 2 + h2], af[mi],
                                 bh[h2], bh[h2 + 2]);
            }
        }
    }

    float ab = 0.f;
    if (EPI == 2) ab = 1.f / (1.f + expf(-alpha_ptr[0]));
    #pragma unroll
    for (int mi = 0; mi < 2; mi++)
        #pragma unroll
        for (int nj = 0; nj < 8; nj++) {
            const int row = bM + wm + mi * 16 + g;
            const int col = bN + wn + nj * 8 + tg * 2;
            float v0 = acc[mi][nj][0], v1 = acc[mi][nj][1];
            float v2 = acc[mi][nj][2], v3 = acc[mi][nj][3];
            const long o0 = (long)bz * sC + (long)row * 512 + col;
            const long o1 = o0 + 8 * 512;
            if (EPI == 1) {
                float2 r0 = *(const float2*)(R + (long)row * 512 + col);
                float2 r1 = *(const float2*)(R + (long)(row + 8) * 512 + col);
                v0 += r0.x; v1 += r0.y; v2 += r1.x; v3 += r1.y;
            } else if (EPI == 2) {
                float2 r0 = *(const float2*)(R + (long)row * 512 + col);
                float2 r1 = *(const float2*)(R + (long)(row + 8) * 512 + col);
                v0 = (1.f - ab) * v0 + ab * r0.x;
                v1 = (1.f - ab) * v1 + ab * r0.y;
                v2 = (1.f - ab) * v2 + ab * r1.x;
                v3 = (1.f - ab) * v3 + ab * r1.y;
            }
            if (OF32) {
                float2 w0 = {v0, v1}, w1 = {v2, v3};
                *(float2*)(C + o0) = w0;
                *(float2*)(C + o1) = w1;
            }
            if (OBF16) {
                pack_store(Cb, o0, v0, v1);
                pack_store(Cb, o1, v2, v3);
            }
        }
}

// ---------------------------------------------------------------------------
// QKV projection (mma, 1-term): per (64-token tile, head, batch).
// Q,K outputs split hi/lo (for 3-term S); V single bf16.
// ---------------------------------------------------------------------------
static constexpr int SK = 72;
static constexpr int QKV_SMEM = 4 * 64 * SK * 2;   // 36864

template<bool SPLIT>
__device__ __forceinline__ void head_gemm(
    uint32_t wbase, const uint32_t xf[4][4],
    float scale, bf* Oh, bf* Ol, long obase, int row0, int lane)
{
    const int g = lane >> 2, tg = lane & 3;
    const uint32_t lrow = (lane & 7) + ((lane >> 3) & 1) * 8;
    const uint32_t lc8 = (lane >> 4) * 8;
    float acc[8][4];
    #pragma unroll
    for (int j = 0; j < 8; j++)
        #pragma unroll
        for (int q = 0; q < 4; q++) acc[j][q] = 0.f;
    #pragma unroll
    for (int ks = 0; ks < 4; ks++) {
        #pragma unroll
        for (int nb = 0; nb < 4; nb++) {
            uint32_t bh[4];
            ldsm4(bh, wbase + ((nb * 16 + lrow) * SK + ks * 16 + lc8) * 2);
            #pragma unroll
            for (int h2 = 0; h2 < 2; h2++)
                mma16816(acc[nb * 2 + h2], xf[ks], bh[h2], bh[h2 + 2]);
        }
    }
    #pragma unroll
    for (int nj = 0; nj < 8; nj++) {
        const long o0 = obase + (long)(row0 + g) * 64 + nj * 8 + tg * 2;
        if (SPLIT) {
            split_store(Oh, Ol, o0, acc[nj][0] * scale, acc[nj][1] * scale);
            split_store(Oh, Ol, o0 + 8 * 64, acc[nj][2] * scale, acc[nj][3] * scale);
        } else {
            pack_store(Oh, o0, acc[nj][0], acc[nj][1]);
            pack_store(Oh, o0 + 8 * 64, acc[nj][2], acc[nj][3]);
        }
    }
}

__global__ __launch_bounds__(128) void qkv_mma(
    const bf* __restrict__ X,
    const bf* __restrict__ Wq, const bf* __restrict__ Wk,
    const bf* __restrict__ Wv,
    bf* __restrict__ Qh, bf* __restrict__ Ql,
    bf* __restrict__ Kh, bf* __restrict__ Kl,
    bf* __restrict__ V)
{
    extern __shared__ __align__(16) bf smq[];
    const int tile0 = blockIdx.x * 64, h = blockIdx.y, b = blockIdx.z;
    const int tid = threadIdx.x, lane = tid & 31, wid = tid >> 5;
    const long xbase = (long)b * MB;
    const long obase = (long)(b * NH + h) * HB;
    bf* Xs = smq;
    bf* Ws = smq + 64 * SK;

    #pragma unroll
    for (int it = 0; it < 4; it++) {
        int id = tid + it * 128;
        int r = id >> 3, c8 = (id & 7) * 8;
        *(uint4*)(Xs + r * SK + c8) =
            *(const uint4*)(X + xbase + (long)(tile0 + r) * 512 + h * 64 + c8);
    }
    const bf* wsrc[3] = {Wq, Wk, Wv};
    #pragma unroll
    for (int a = 0; a < 3; a++)
        #pragma unroll
        for (int it = 0; it < 4; it++) {
            int id = tid + it * 128;
            int r = id >> 3, c8 = (id & 7) * 8;
            *(uint4*)(Ws + a * 64 * SK + r * SK + c8) =
                *(const uint4*)(wsrc[a] + h * 4096 + r * 64 + c8);
        }
    __syncthreads();

    const uint32_t xb = smem_u32(Xs);
    const uint32_t lrow = (lane & 7) + ((lane >> 3) & 1) * 8;
    const uint32_t lc8 = (lane >> 4) * 8;
    uint32_t xf[4][4];
    #pragma unroll
    for (int ks = 0; ks < 4; ks++)
        ldsm4(xf[ks], xb + ((wid * 16 + lrow) * SK + ks * 16 + lc8) * 2);

    const uint32_t wb = smem_u32(Ws);
    const int row0 = tile0 + wid * 16;
    head_gemm<true >(wb,               xf, 0.125f, Qh, Ql, obase, row0, lane);
    head_gemm<true >(wb + 64 * SK * 2, xf, 1.f,    Kh, Kl, obase, row0, lane);
    head_gemm<false>(wb + 128 * SK * 2, xf, 1.f,   V, nullptr, obase, row0, lane);
}

// ---------------------------------------------------------------------------
// Flash attention (mma): 256 threads, 128-row q-strip, 3-stage swizzled
// cp.async KV pipeline. S = QK^T uses 3-term hi/lo (softmax sensitivity);
// P·V uses 1-term bf16. Output single bf16, head-concat: O[b][row][h*64+e].
// ---------------------------------------------------------------------------
static constexpr int AAR = 64 * 128;                 // bytes per KV array (8192)
static constexpr int STA = 3 * AAR;                  // Kh, Kl, V (24576)
static constexpr int ATTN_SMEM = 3 * STA;            // 73728

__device__ __forceinline__ void attn_load_kv(
    uint32_t dst, const bf* Kh, const bf* Kl, const bf* V,
    long base, int kt, int tid)
{
    #pragma unroll
    for (int it = 0; it < 2; it++) {
        int id = tid + it * 256;       // 0..511
        int r = id >> 3, c8 = id & 7;
        const long gsrc = base + (long)(kt * 64 + r) * 64 + c8 * 8;
        const uint32_t so = sw128(r, c8);
        cpa16(dst           + so, Kh + gsrc);
        cpa16(dst +     AAR + so, Kl + gsrc);
        cpa16(dst + 2 * AAR + so, V  + gsrc);
    }
}

__global__ __launch_bounds__(256, 2) void attn_mma(
    const bf* __restrict__ Qh, const bf* __restrict__ Ql,
    const bf* __restrict__ Kh, const bf* __restrict__ Kl,
    const bf* __restrict__ V,
    const float* __restrict__ mask,
    bf* __restrict__ O)
{
    extern __shared__ __align__(16) bf sma[];
    const int q0 = blockIdx.x * 128, h = blockIdx.y, b = blockIdx.z;
    const int tid = threadIdx.x, lane = tid & 31, wid = tid >> 5;
    const int g = lane >> 2, tg = lane & 3;
    const long base = (long)(b * NH + h) * HB;
    const uint32_t sb = smem_u32(sma);
    const int lrow = (lane & 7) + ((lane >> 3) & 1) * 8;
    const int lch  = lane >> 4;

    // Stage the 128-row Q strip (hi, lo) through the start of smem
    #pragma unroll
    for (int it = 0; it < 4; it++) {
        int id = tid + it * 256;       // 0..1023
        int r = id >> 3, c8 = id & 7;
        const long gq = base + (long)(q0 + r) * 64 + c8 * 8;
        cpa16(sb +         sw128(r, c8), Qh + gq);
        cpa16(sb + 16384 + sw128(r, c8), Ql + gq);
    }
    CP_COMMIT(); CP_WAIT(0);
    __syncthreads();
    uint32_t qh[4][4], ql[4][4];
    #pragma unroll
    for (int ks = 0; ks < 4; ks++) {
        uint32_t ad = sb + sw128(wid * 16 + lrow, 2 * ks + lch);
        ldsm4(qh[ks], ad);
        ldsm4(ql[ks], ad + 16384);
    }
    __syncthreads();   // all warps done reading Q before stages are reused

    float m0 = -1e30f, m1 = -1e30f, l0 = 0.f, l1 = 0.f;
    float o[8][4];
    #pragma unroll
    for (int j = 0; j < 8; j++)
        #pragma unroll
        for (int q = 0; q < 4; q++) o[j][q] = 0.f;

    attn_load_kv(sb,       Kh, Kl, V, base, 0, tid); CP_COMMIT();
    attn_load_kv(sb + STA, Kh, Kl, V, base, 1, tid); CP_COMMIT();

    int st = 0, ld = 2;
    for (int kt = 0; kt < 8; kt++) {
        if (kt < 7) { CP_WAIT(1); } else { CP_WAIT(0); }
        __syncthreads();
        if (kt < 6) {
            attn_load_kv(sb + ld * STA, Kh, Kl, V, base, kt + 2, tid);
            CP_COMMIT();
            if (++ld == 3) ld = 0;
        }
        const uint32_t KHs = sb + st * STA;
        if (++st == 3) st = 0;
        const uint32_t VHs = KHs + 2 * AAR;

        // S = Q K^T (3-term hi/lo)
        float s[8][4];
        #pragma unroll
        for (int j = 0; j < 8; j++)
            #pragma unroll
            for (int q = 0; q < 4; q++) s[j][q] = 0.f;
        #pragma unroll
        for (int ks = 0; ks < 4; ks++) {
            #pragma unroll
            for (int nb = 0; nb < 4; nb++) {
                uint32_t bh[4], bl[4];
                uint32_t ad = KHs + sw128(nb * 16 + lrow, 2 * ks + lch);
                ldsm4(bh, ad);
                ldsm4(bl, ad + AAR);
                #pragma unroll
                for (int h2 = 0; h2 < 2; h2++) {
                    float* a = s[nb * 2 + h2];
                    mma16816(a, qh[ks], bh[h2], bh[h2 + 2]);
                    mma16816(a, qh[ks], bl[h2], bl[h2 + 2]);
                    mma16816(a, ql[ks], bh[h2], bh[h2 + 2]);
                }
            }
        }
        if (mask) {
            const int mr = q0 + wid * 16 + g;
            #pragma unroll
            for (int nj = 0; nj < 8; nj++) {
                const int mc = kt * 64 + nj * 8 + tg * 2;
                float2 a0 = *(const float2*)(mask + (long)mr * 512 + mc);
                float2 a1 = *(const float2*)(mask + (long)(mr + 8) * 512 + mc);
                s[nj][0] += a0.x; s[nj][1] += a0.y;
                s[nj][2] += a1.x; s[nj][3] += a1.y;
            }
        }

        // online softmax (rows g and g+8; reduce across tg lanes)
        float tm0 = -1e30f, tm1 = -1e30f;
        #pragma unroll
        for (int nj = 0; nj < 8; nj++) {
            tm0 = fmaxf(tm0, fmaxf(s[nj][0], s[nj][1]));
            tm1 = fmaxf(tm1, fmaxf(s[nj][2], s[nj][3]));
        }
        tm0 = fmaxf(tm0, __shfl_xor_sync(~0u, tm0, 1));
        tm0 = fmaxf(tm0, __shfl_xor_sync(~0u, tm0, 2));
        tm1 = fmaxf(tm1, __shfl_xor_sync(~0u, tm1, 1));
        tm1 = fmaxf(tm1, __shfl_xor_sync(~0u, tm1, 2));
        const float nm0 = fmaxf(m0, tm0), nm1 = fmaxf(m1, tm1);
        float sum0 = 0.f, sum1 = 0.f;
        #pragma unroll
        for (int nj = 0; nj < 8; nj++) {
            s[nj][0] = __expf(s[nj][0] - nm0); sum0 += s[nj][0];
            s[nj][1] = __expf(s[nj][1] - nm0); sum0 += s[nj][1];
            s[nj][2] = __expf(s[nj][2] - nm1); sum1 += s[nj][2];
            s[nj][3] = __expf(s[nj][3] - nm1); sum1 += s[nj][3];
        }
        sum0 += __shfl_xor_sync(~0u, sum0, 1);
        sum0 += __shfl_xor_sync(~0u, sum0, 2);
        sum1 += __shfl_xor_sync(~0u, sum1, 1);
        sum1 += __shfl_xor_sync(~0u, sum1, 2);
        const float c0 = __expf(m0 - nm0), c1 = __expf(m1 - nm1);
        l0 = l0 * c0 + sum0; l1 = l1 * c1 + sum1;
        m0 = nm0; m1 = nm1;
        #pragma unroll
        for (int j = 0; j < 8; j++) {
            o[j][0] *= c0; o[j][1] *= c0; o[j][2] *= c1; o[j][3] *= c1;
        }

        // P fragments (1-term bf16; FA2 accum->A identity)
        uint32_t ph[4][4];
        #pragma unroll
        for (int ks = 0; ks < 4; ks++) {
            ph[ks][0] = pack_bf2(s[2*ks][0],   s[2*ks][1]);
            ph[ks][1] = pack_bf2(s[2*ks][2],   s[2*ks][3]);
            ph[ks][2] = pack_bf2(s[2*ks+1][0], s[2*ks+1][1]);
            ph[ks][3] = pack_bf2(s[2*ks+1][2], s[2*ks+1][3]);
        }

        // O += P V  (V^T fragments via ldmatrix.trans; 1-term)
        #pragma unroll
        for (int ks = 0; ks < 4; ks++) {
            #pragma unroll
            for (int nb = 0; nb < 4; nb++) {
                uint32_t vh[4];
                ldsm4t(vh, VHs + sw128(ks * 16 + (lane & 15), 2 * nb + lch));
                #pragma unroll
                for (int h2 = 0; h2 < 2; h2++)
                    mma16816(o[nb * 2 + h2], ph[ks],
                             vh[h2 * 2], vh[h2 * 2 + 1]);
            }
        }
    }

    const float i0 = 1.f / l0, i1 = 1.f / l1;
    const int row = q0 + wid * 16 + g;
    #pragma unroll
    for (int nj = 0; nj < 8; nj++) {
        const long o0 = (long)b * MB + (long)row * 512 + h * 64 + nj * 8 + tg * 2;
        pack_store(O, o0,           o[nj][0] * i0, o[nj][1] * i0);
        pack_store(O, o0 + 8 * 512, o[nj][2] * i1, o[nj][3] * i1);
    }
}

// ---------------------------------------------------------------------------
// Launch sequence (single stream, graph-capturable, allocation-free)
// ---------------------------------------------------------------------------
extern "C" void kernel_launch(void* const* d_in, const int* in_sizes, int n_in,
                              void* d_out, int out_size)
{
    const float* x             = (const float*)d_in[0];
    const float* mask          = (const float*)d_in[1];
    const float* Wq_inter      = (const float*)d_in[2];
    const float* Wk_inter      = (const float*)d_in[3];
    const float* Wv_inter      = (const float*)d_in[4];
    const float* Wq_intra      = (const float*)d_in[5];
    const float* Wk_intra      = (const float*)d_in[6];
    const float* Wv_intra      = (const float*)d_in[7];
    const float* W_proj_in     = (const float*)d_in[8];
    const float* W_proj_out    = (const float*)d_in[9];
    const float* W_split_inter = (const float*)d_in[10];
    const float* W_out_inter   = (const float*)d_in[11];
    const float* W_split_intra = (const float*)d_in[12];
    const float* W_out_intra   = (const float*)d_in[13];
    const float* alpha         = (const float*)d_in[14];
    float* out = (float*)d_out;

    float* oi;
    cudaGetSymbolAddress((void**)&oi, g_oi);

    bf *xT, *xp, *cc, *oib, *qh, *ql, *kh, *kl, *vv;
    bf *wcin, *wcout, *wsi, *woi;
    bf *wqA, *wkA, *wvA, *wqB, *wkB, *wvB;
    cudaGetSymbolAddress((void**)&xT,  g_xT);
    cudaGetSymbolAddress((void**)&xp,  g_xp);
    cudaGetSymbolAddress((void**)&cc,  g_cc);
    cudaGetSymbolAddress((void**)&oib, g_oib);
    cudaGetSymbolAddress((void**)&qh,  g_q_hi);
    cudaGetSymbolAddress((void**)&ql,  g_q_lo);
    cudaGetSymbolAddress((void**)&kh,  g_k_hi);
    cudaGetSymbolAddress((void**)&kl,  g_k_lo);
    cudaGetSymbolAddress((void**)&vv,  g_v);
    cudaGetSymbolAddress((void**)&wcin,  g_wcin);
    cudaGetSymbolAddress((void**)&wcout, g_wcout);
    cudaGetSymbolAddress((void**)&wsi,   g_wsi);
    cudaGetSymbolAddress((void**)&woi,   g_woi);
    cudaGetSymbolAddress((void**)&wqA, g_wqA);
    cudaGetSymbolAddress((void**)&wkA, g_wkA);
    cudaGetSymbolAddress((void**)&wvA, g_wvA);
    cudaGetSymbolAddress((void**)&wqB, g_wqB);
    cudaGetSymbolAddress((void**)&wkB, g_wkB);
    cudaGetSymbolAddress((void**)&wvB, g_wvB);

    cudaFuncSetAttribute(tc_gemm<0,0,1>, cudaFuncAttributeMaxDynamicSharedMemorySize, TCG_SMEM);
    cudaFuncSetAttribute(tc_gemm<1,1,1>, cudaFuncAttributeMaxDynamicSharedMemorySize, TCG_SMEM);
    cudaFuncSetAttribute(tc_gemm<2,1,0>, cudaFuncAttributeMaxDynamicSharedMemorySize, TCG_SMEM);
    cudaFuncSetAttribute(qkv_mma,  cudaFuncAttributeMaxDynamicSharedMemorySize, QKV_SMEM);
    cudaFuncSetAttribute(attn_mma, cudaFuncAttributeMaxDynamicSharedMemorySize, ATTN_SMEM);

    dim3 gb(4, 4, BATCH);
    dim3 gq(8, NH, BATCH);
    dim3 gattn(4, NH, BATCH);
    dim3 gts(16, 16, BATCH), tts(32, 8);
    const long W4 = MB / 4, H4 = (long)NH * 4096 / 4;

    // Combined weights: fp32 GEMM with direct bf16 epilogue (2 jobs)
    gemm64w<<<dim3(8, 8, 2), 256>>>(W_split_inter, W_proj_in, wcin,
                                    W_proj_out, W_out_inter, wcout);

    // All independent weight conversions in ONE launch
    SplitJobs jobs;
    jobs.j[0] = {(const float4*)W_split_intra, wsi, W4};
    jobs.j[1] = {(const float4*)W_out_intra,   woi, W4};
    jobs.j[2] = {(const float4*)Wq_inter, wqA, H4};
    jobs.j[3] = {(const float4*)Wk_inter, wkA, H4};
    jobs.j[4] = {(const float4*)Wv_inter, wvA, H4};
    jobs.j[5] = {(const float4*)Wq_intra, wqB, H4};
    jobs.j[6] = {(const float4*)Wk_intra, wkB, H4};
    jobs.j[7] = {(const float4*)Wv_intra, wvB, H4};
    split8<<<dim3(256, 8, 1), 256>>>(jobs);

    transpose_bf16_kernel<<<gts, tts>>>(x, xT);

    // GEMM1: xp = xT @ wcin^T  (bf16 out)
    tc_gemm<0,0,1><<<gb, 256, TCG_SMEM>>>(xT, MB, wcin, 0,
                                          nullptr, xp, MB, nullptr, 0, nullptr);
    // inter path
    qkv_mma<<<gq, 128, QKV_SMEM>>>(xp, wqA, wkA, wvA, qh, ql, kh, kl, vv);
    attn_mma<<<gattn, 256, ATTN_SMEM>>>(qh, ql, kh, kl, vv, nullptr, cc);
    // GEMM2: oi = wcout @ cc^T + x  (fp32 + bf16 out)
    tc_gemm<1,1,1><<<gb, 256, TCG_SMEM>>>(wcout, 0, cc, MB,
                                          oi, oib, MB, x, MB, nullptr);
    // GEMM3: xi = oib @ wsi^T  (bf16 out, reuse xp)
    tc_gemm<0,0,1><<<gb, 256, TCG_SMEM>>>(oib, MB, wsi, 0,
                                          nullptr, xp, MB, nullptr, 0, nullptr);
    // intra path
    qkv_mma<<<gq, 128, QKV_SMEM>>>(xp, wqB, wkB, wvB, qh, ql, kh, kl, vv);
    attn_mma<<<gattn, 256, ATTN_SMEM>>>(qh, ql, kh, kl, vv, mask, cc);
    // GEMM4: out = (1-a)*(cc @ woi^T) + a*oi
    tc_gemm<2,1,0><<<gb, 256, TCG_SMEM>>>(cc, MB, woi, 0,
                                          out, nullptr, MB, oi, MB, alpha);
}

// round 14
// speedup vs baseline: 2.3486x; 1.2502x over previous
#include <cuda_runtime.h>
#include <cuda_bf16.h>
#include <cstdint>

using bf = __nv_bfloat16;
static constexpr int  BATCH = 32;
static constexpr int  NH    = 8;
static constexpr long MB    = 512L * 512L;
static constexpr long HB    = 512L * 64L;

// ---------------------------------------------------------------------------
// Scratch (static __device__ arrays: allocation-free per harness rules)
// ---------------------------------------------------------------------------
__device__ float g_oi [(long)BATCH * 512 * 512];

__device__ bf g_xT [(long)BATCH * MB];
__device__ bf g_xp [(long)BATCH * MB];
__device__ bf g_cc [(long)BATCH * MB];
__device__ bf g_oib[(long)BATCH * MB];
__device__ bf g_q  [(long)BATCH * NH * HB];
__device__ bf g_k  [(long)BATCH * NH * HB];
__device__ bf g_v  [(long)BATCH * NH * HB];

__device__ bf g_wcin [MB];
__device__ bf g_wcout[MB];
__device__ bf g_wsi  [MB];
__device__ bf g_woi  [MB];
__device__ bf g_wqA[NH*4096], g_wkA[NH*4096], g_wvA[NH*4096];
__device__ bf g_wqB[NH*4096], g_wkB[NH*4096], g_wvB[NH*4096];

// ---------------------------------------------------------------------------
// Low-level helpers (sm_80+ baseline)
// ---------------------------------------------------------------------------
__device__ __forceinline__ void mma16816(float* c, const uint32_t* a,
                                         uint32_t b0, uint32_t b1) {
    asm volatile(
        "mma.sync.aligned.m16n8k16.row.col.f32.bf16.bf16.f32 "
        "{%0,%1,%2,%3}, {%4,%5,%6,%7}, {%8,%9}, {%0,%1,%2,%3};"
        : "+f"(c[0]), "+f"(c[1]), "+f"(c[2]), "+f"(c[3])
        : "r"(a[0]), "r"(a[1]), "r"(a[2]), "r"(a[3]), "r"(b0), "r"(b1));
}
__device__ __forceinline__ void ldsm4(uint32_t* r, uint32_t a) {
    asm volatile("ldmatrix.sync.aligned.m8n8.x4.shared.b16 {%0,%1,%2,%3}, [%4];"
                 : "=r"(r[0]), "=r"(r[1]), "=r"(r[2]), "=r"(r[3]) : "r"(a));
}
__device__ __forceinline__ void ldsm4t(uint32_t* r, uint32_t a) {
    asm volatile("ldmatrix.sync.aligned.m8n8.x4.trans.shared.b16 {%0,%1,%2,%3}, [%4];"
                 : "=r"(r[0]), "=r"(r[1]), "=r"(r[2]), "=r"(r[3]) : "r"(a));
}
__device__ __forceinline__ void cpa16(uint32_t s, const void* g) {
    asm volatile("cp.async.cg.shared.global [%0], [%1], 16;" :: "r"(s), "l"(g));
}
#define CP_COMMIT() asm volatile("cp.async.commit_group;" ::: "memory")
#define CP_WAIT(N)  asm volatile("cp.async.wait_group %0;" :: "n"(N) : "memory")
__device__ __forceinline__ uint32_t smem_u32(const void* p) {
    uint32_t a;
    asm("{ .reg .u64 t; cvta.to.shared.u64 t, %1; cvt.u32.u64 %0, t; }"
        : "=r"(a) : "l"(p));
    return a;
}
// XOR swizzle for 128B rows (conflict-free for ldsm/ldsm.trans 8-row phases)
__device__ __forceinline__ uint32_t sw128(int r, int c) {
    return (uint32_t)(r * 128 + ((c ^ (r & 7)) << 4));
}
__device__ __forceinline__ void pack_store(bf* C, long off, float a, float b) {
    __nv_bfloat162 h;
    h.x = __float2bfloat16_rn(a); h.y = __float2bfloat16_rn(b);
    *reinterpret_cast<uint32_t*>(C + off) = *reinterpret_cast<uint32_t*>(&h);
}
__device__ __forceinline__ uint32_t pack_bf2(float a, float b) {
    __nv_bfloat162 h;
    h.x = __float2bfloat16_rn(a); h.y = __float2bfloat16_rn(b);
    return *reinterpret_cast<uint32_t*>(&h);
}

// ---------------------------------------------------------------------------
// Batched fp32 -> bf16 weight conversions: 8 jobs, one launch
// ---------------------------------------------------------------------------
struct SplitJob  { const float4* src; bf* dst; long n4; };
struct SplitJobs { SplitJob j[8]; };

__global__ __launch_bounds__(256) void split8(SplitJobs jobs)
{
    const SplitJob jb = jobs.j[blockIdx.y];
    long i = (long)blockIdx.x * 256 + threadIdx.x;
    if (i >= jb.n4) return;
    float4 v = jb.src[i];
    uint2 p;
    p.x = pack_bf2(v.x, v.y);
    p.y = pack_bf2(v.z, v.w);
    *(uint2*)(jb.dst + i * 4) = p;
}

__global__ __launch_bounds__(256) void transpose_bf16_kernel(
    const float* __restrict__ in, bf* __restrict__ outb)
{
    __shared__ float t[32][33];
    const int b = blockIdx.z;
    const int s0 = blockIdx.x * 32, d0 = blockIdx.y * 32;
    const long base = (long)b * MB;
    const int tx = threadIdx.x, ty = threadIdx.y;
    #pragma unroll
    for (int i = ty; i < 32; i += 8)
        t[i][tx] = in[base + (long)(s0 + i) * 512 + d0 + tx];
    __syncthreads();
    #pragma unroll
    for (int i = ty; i < 32; i += 8) {
        long o = base + (long)(d0 + i) * 512 + s0 + tx;
        outb[o] = __float2bfloat16_rn(t[tx][i]);
    }
}

// ---------------------------------------------------------------------------
// Weight-combine GEMM (fp32 in, bf16 out): C[m][n] = sum_k A[m,k]*B[k,n]
// ---------------------------------------------------------------------------
__global__ __launch_bounds__(256) void gemm64w(
    const float* __restrict__ A0, const float* __restrict__ B0,
    bf* __restrict__ C0,
    const float* __restrict__ A1, const float* __restrict__ B1,
    bf* __restrict__ C1)
{
    const float* A = blockIdx.z ? A1 : A0;
    const float* B = blockIdx.z ? B1 : B0;
    bf* Cb = blockIdx.z ? C1 : C0;
    __shared__ float As[16][64], Bs[16][64];
    const int bM = blockIdx.y * 64, bN = blockIdx.x * 64;
    const int tid = threadIdx.x, tx = tid & 15, ty = tid >> 4;
    float acc[4][4];
    #pragma unroll
    for (int i = 0; i < 4; i++)
        #pragma unroll
        for (int j = 0; j < 4; j++) acc[i][j] = 0.f;
    for (int kt = 0; kt < 32; kt++) {
        const int k0 = kt * 16;
        __syncthreads();
        #pragma unroll
        for (int it = 0; it < 4; it++) {
            int id = tid + it * 256;
            As[id & 15][id >> 4] = A[(long)(bM + (id >> 4)) * 512 + k0 + (id & 15)];
            Bs[id >> 6][id & 63] = B[(long)(k0 + (id >> 6)) * 512 + bN + (id & 63)];
        }
        __syncthreads();
        #pragma unroll
        for (int k = 0; k < 16; k++) {
            float av[4], bv[4];
            #pragma unroll
            for (int i = 0; i < 4; i++) av[i] = As[k][ty * 4 + i];
            #pragma unroll
            for (int j = 0; j < 4; j++) bv[j] = Bs[k][tx * 4 + j];
            #pragma unroll
            for (int i = 0; i < 4; i++)
                #pragma unroll
                for (int j = 0; j < 4; j++)
                    acc[i][j] = fmaf(av[i], bv[j], acc[i][j]);
        }
    }
    #pragma unroll
    for (int i = 0; i < 4; i++) {
        const long o = (long)(bM + ty * 4 + i) * 512 + bN + tx * 4;
        pack_store(Cb, o,     acc[i][0], acc[i][1]);
        pack_store(Cb, o + 2, acc[i][2], acc[i][3]);
    }
}

// ---------------------------------------------------------------------------
// Pipelined tensor-core batched GEMM (1-term bf16):
// C[b][m][n] = sum_k A[b][m][k]*B[b][n][k]
// BK=64, 3-stage cp.async, sw128-swizzled smem, ONE sync per 64-K iter.
// ---------------------------------------------------------------------------
static constexpr int ARR = 128 * 128;          // bytes per array (16384)
static constexpr int STG = 2 * ARR;            // bytes per stage  (32768)
static constexpr int TCG_SMEM = 3 * STG;       // 98304

__device__ __forceinline__ void tcg_load(
    uint32_t sb, const bf* A, const bf* B, int bM, int bN, int k0, int tid)
{
    #pragma unroll
    for (int a = 0; a < 2; a++) {
        const bf* src = a ? B : A;
        const int row0 = a ? bN : bM;
        const uint32_t dst = sb + a * ARR;
        #pragma unroll
        for (int it = 0; it < 4; it++) {
            int id = tid + it * 256;           // 0..1023
            int r = id >> 3, c8 = id & 7;
            cpa16(dst + sw128(r, c8),
                  src + (long)(row0 + r) * 512 + k0 + c8 * 8);
        }
    }
}

template<int EPI, int OF32, int OBF16>
__global__ __launch_bounds__(256, 2) void tc_gemm(
    const bf* __restrict__ A, long sA,
    const bf* __restrict__ B, long sB,
    float* __restrict__ C, bf* __restrict__ Cb, long sC,
    const float* __restrict__ R, long sR, const float* __restrict__ alpha_ptr)
{
    extern __shared__ __align__(16) char smc[];
    const uint32_t sb0 = smem_u32(smc);
    const int tid = threadIdx.x, lane = tid & 31, wid = tid >> 5;
    const int g = lane >> 2, tg = lane & 3;
    const int wm = (wid >> 1) * 32, wn = (wid & 1) * 64;
    const int bN = blockIdx.x * 128, bM = blockIdx.y * 128, bz = blockIdx.z;
    A += (long)bz * sA;
    B += (long)bz * sB;
    if (EPI != 0) R += (long)bz * sR;

    const int lrow = (lane & 7) + ((lane >> 3) & 1) * 8;
    const int lch  = lane >> 4;                 // chunk half-select 0/1

    float acc[2][8][4];
    #pragma unroll
    for (int i = 0; i < 2; i++)
        #pragma unroll
        for (int j = 0; j < 8; j++)
            #pragma unroll
            for (int q = 0; q < 4; q++) acc[i][j][q] = 0.f;

    tcg_load(sb0,       A, B, bM, bN, 0,  tid); CP_COMMIT();
    tcg_load(sb0 + STG, A, B, bM, bN, 64, tid); CP_COMMIT();

    int st = 0, ld = 2;
    for (int t = 0; t < 8; t++) {
        if (t < 7) { CP_WAIT(1); } else { CP_WAIT(0); }
        __syncthreads();
        if (t < 6) {
            tcg_load(sb0 + ld * STG, A, B, bM, bN, (t + 2) * 64, tid);
            CP_COMMIT();
            if (++ld == 3) ld = 0;
        }
        const uint32_t sb = sb0 + st * STG;
        if (++st == 3) st = 0;
        #pragma unroll
        for (int ks = 0; ks < 4; ks++) {
            const int ch = 2 * ks + lch;
            uint32_t af[2][4];
            #pragma unroll
            for (int mi = 0; mi < 2; mi++)
                ldsm4(af[mi], sb + sw128(wm + mi * 16 + lrow, ch));
            #pragma unroll
            for (int nb = 0; nb < 4; nb++) {
                uint32_t bh[4];
                ldsm4(bh, sb + ARR + sw128(wn + nb * 16 + lrow, ch));
                #pragma unroll
                for (int h2 = 0; h2 < 2; h2++)
                    #pragma unroll
                    for (int mi = 0; mi < 2; mi++)
                        mma16816(acc[mi][nb * 2 + h2], af[mi],
                                 bh[h2], bh[h2 + 2]);
            }
        }
    }

    float ab = 0.f;
    if (EPI == 2) ab = 1.f / (1.f + expf(-alpha_ptr[0]));
    #pragma unroll
    for (int mi = 0; mi < 2; mi++)
        #pragma unroll
        for (int nj = 0; nj < 8; nj++) {
            const int row = bM + wm + mi * 16 + g;
            const int col = bN + wn + nj * 8 + tg * 2;
            float v0 = acc[mi][nj][0], v1 = acc[mi][nj][1];
            float v2 = acc[mi][nj][2], v3 = acc[mi][nj][3];
            const long o0 = (long)bz * sC + (long)row * 512 + col;
            const long o1 = o0 + 8 * 512;
            if (EPI == 1) {
                float2 r0 = *(const float2*)(R + (long)row * 512 + col);
                float2 r1 = *(const float2*)(R + (long)(row + 8) * 512 + col);
                v0 += r0.x; v1 += r0.y; v2 += r1.x; v3 += r1.y;
            } else if (EPI == 2) {
                float2 r0 = *(const float2*)(R + (long)row * 512 + col);
                float2 r1 = *(const float2*)(R + (long)(row + 8) * 512 + col);
                v0 = (1.f - ab) * v0 + ab * r0.x;
                v1 = (1.f - ab) * v1 + ab * r0.y;
                v2 = (1.f - ab) * v2 + ab * r1.x;
                v3 = (1.f - ab) * v3 + ab * r1.y;
            }
            if (OF32) {
                float2 w0 = {v0, v1}, w1 = {v2, v3};
                *(float2*)(C + o0) = w0;
                *(float2*)(C + o1) = w1;
            }
            if (OBF16) {
                pack_store(Cb, o0, v0, v1);
                pack_store(Cb, o1, v2, v3);
            }
        }
}

// ---------------------------------------------------------------------------
// QKV projection (mma, 1-term): per (64-token tile, head, batch).
// Single-bf16 outputs. Q pre-scaled by 1/8.
// ---------------------------------------------------------------------------
static constexpr int SK = 72;
static constexpr int QKV_SMEM = 4 * 64 * SK * 2;   // 36864

__device__ __forceinline__ void head_gemm(
    uint32_t wbase, const uint32_t xf[4][4],
    float scale, bf* O, long obase, int row0, int lane)
{
    const int g = lane >> 2, tg = lane & 3;
    const uint32_t lrow = (lane & 7) + ((lane >> 3) & 1) * 8;
    const uint32_t lc8 = (lane >> 4) * 8;
    float acc[8][4];
    #pragma unroll
    for (int j = 0; j < 8; j++)
        #pragma unroll
        for (int q = 0; q < 4; q++) acc[j][q] = 0.f;
    #pragma unroll
    for (int ks = 0; ks < 4; ks++) {
        #pragma unroll
        for (int nb = 0; nb < 4; nb++) {
            uint32_t bh[4];
            ldsm4(bh, wbase + ((nb * 16 + lrow) * SK + ks * 16 + lc8) * 2);
            #pragma unroll
            for (int h2 = 0; h2 < 2; h2++)
                mma16816(acc[nb * 2 + h2], xf[ks], bh[h2], bh[h2 + 2]);
        }
    }
    #pragma unroll
    for (int nj = 0; nj < 8; nj++) {
        const long o0 = obase + (long)(row0 + g) * 64 + nj * 8 + tg * 2;
        pack_store(O, o0,          acc[nj][0] * scale, acc[nj][1] * scale);
        pack_store(O, o0 + 8 * 64, acc[nj][2] * scale, acc[nj][3] * scale);
    }
}

__global__ __launch_bounds__(128) void qkv_mma(
    const bf* __restrict__ X,
    const bf* __restrict__ Wq, const bf* __restrict__ Wk,
    const bf* __restrict__ Wv,
    bf* __restrict__ Q, bf* __restrict__ K, bf* __restrict__ V)
{
    extern __shared__ __align__(16) bf smq[];
    const int tile0 = blockIdx.x * 64, h = blockIdx.y, b = blockIdx.z;
    const int tid = threadIdx.x, lane = tid & 31, wid = tid >> 5;
    const long xbase = (long)b * MB;
    const long obase = (long)(b * NH + h) * HB;
    bf* Xs = smq;
    bf* Ws = smq + 64 * SK;

    #pragma unroll
    for (int it = 0; it < 4; it++) {
        int id = tid + it * 128;
        int r = id >> 3, c8 = (id & 7) * 8;
        *(uint4*)(Xs + r * SK + c8) =
            *(const uint4*)(X + xbase + (long)(tile0 + r) * 512 + h * 64 + c8);
    }
    const bf* wsrc[3] = {Wq, Wk, Wv};
    #pragma unroll
    for (int a = 0; a < 3; a++)
        #pragma unroll
        for (int it = 0; it < 4; it++) {
            int id = tid + it * 128;
            int r = id >> 3, c8 = (id & 7) * 8;
            *(uint4*)(Ws + a * 64 * SK + r * SK + c8) =
                *(const uint4*)(wsrc[a] + h * 4096 + r * 64 + c8);
        }
    __syncthreads();

    const uint32_t xb = smem_u32(Xs);
    const uint32_t lrow = (lane & 7) + ((lane >> 3) & 1) * 8;
    const uint32_t lc8 = (lane >> 4) * 8;
    uint32_t xf[4][4];
    #pragma unroll
    for (int ks = 0; ks < 4; ks++)
        ldsm4(xf[ks], xb + ((wid * 16 + lrow) * SK + ks * 16 + lc8) * 2);

    const uint32_t wb = smem_u32(Ws);
    const int row0 = tile0 + wid * 16;
    head_gemm(wb,                xf, 0.125f, Q, obase, row0, lane);
    head_gemm(wb + 64 * SK * 2,  xf, 1.f,    K, obase, row0, lane);
    head_gemm(wb + 128 * SK * 2, xf, 1.f,    V, obase, row0, lane);
}

// ---------------------------------------------------------------------------
// Flash attention (mma, 1-term): 256 threads, 128-row q-strip, 3-stage
// swizzled cp.async K/V pipeline, ONE sync per kv-iter.
// Output single bf16, head-concat: O[b][row][h*64+e].
// ---------------------------------------------------------------------------
static constexpr int AAR = 64 * 128;                 // bytes per KV array (8192)
static constexpr int STA = 2 * AAR;                  // K, V (16384)
static constexpr int ATTN_SMEM = 3 * STA;            // 49152

__device__ __forceinline__ void attn_load_kv(
    uint32_t dst, const bf* K, const bf* V, long base, int kt, int tid)
{
    #pragma unroll
    for (int it = 0; it < 2; it++) {
        int id = tid + it * 256;       // 0..511
        int r = id >> 3, c8 = id & 7;
        const long gsrc = base + (long)(kt * 64 + r) * 64 + c8 * 8;
        const uint32_t so = sw128(r, c8);
        cpa16(dst       + so, K + gsrc);
        cpa16(dst + AAR + so, V + gsrc);
    }
}

__global__ __launch_bounds__(256, 2) void attn_mma(
    const bf* __restrict__ Q, const bf* __restrict__ K,
    const bf* __restrict__ V,
    const float* __restrict__ mask,
    bf* __restrict__ O)
{
    extern __shared__ __align__(16) bf sma[];
    const int q0 = blockIdx.x * 128, h = blockIdx.y, b = blockIdx.z;
    const int tid = threadIdx.x, lane = tid & 31, wid = tid >> 5;
    const int g = lane >> 2, tg = lane & 3;
    const long base = (long)(b * NH + h) * HB;
    const uint32_t sb = smem_u32(sma);
    const int lrow = (lane & 7) + ((lane >> 3) & 1) * 8;
    const int lch  = lane >> 4;

    // Stage the 128-row Q strip through the start of smem
    #pragma unroll
    for (int it = 0; it < 2; it++) {
        int id = tid + it * 256;       // 0..511
        int r = id >> 2, c8 = (id & 3) * 2;  // 128 rows x 4 pairs of chunks
        const long gq = base + (long)(q0 + r) * 64 + c8 * 8;
        cpa16(sb + sw128(r, c8),     Q + gq);
        cpa16(sb + sw128(r, c8 + 1), Q + gq + 8);
    }
    CP_COMMIT(); CP_WAIT(0);
    __syncthreads();
    uint32_t qf[4][4];
    #pragma unroll
    for (int ks = 0; ks < 4; ks++)
        ldsm4(qf[ks], sb + sw128(wid * 16 + lrow, 2 * ks + lch));
    __syncthreads();   // all warps done reading Q before stages are reused

    float m0 = -1e30f, m1 = -1e30f, l0 = 0.f, l1 = 0.f;
    float o[8][4];
    #pragma unroll
    for (int j = 0; j < 8; j++)
        #pragma unroll
        for (int q = 0; q < 4; q++) o[j][q] = 0.f;

    attn_load_kv(sb,       K, V, base, 0, tid); CP_COMMIT();
    attn_load_kv(sb + STA, K, V, base, 1, tid); CP_COMMIT();

    int st = 0, ld = 2;
    for (int kt = 0; kt < 8; kt++) {
        if (kt < 7) { CP_WAIT(1); } else { CP_WAIT(0); }
        __syncthreads();
        if (kt < 6) {
            attn_load_kv(sb + ld * STA, K, V, base, kt + 2, tid);
            CP_COMMIT();
            if (++ld == 3) ld = 0;
        }
        const uint32_t KHs = sb + st * STA;
        if (++st == 3) st = 0;
        const uint32_t VHs = KHs + AAR;

        // S = Q K^T (1-term)
        float s[8][4];
        #pragma unroll
        for (int j = 0; j < 8; j++)
            #pragma unroll
            for (int q = 0; q < 4; q++) s[j][q] = 0.f;
        #pragma unroll
        for (int ks = 0; ks < 4; ks++) {
            #pragma unroll
            for (int nb = 0; nb < 4; nb++) {
                uint32_t bh[4];
                ldsm4(bh, KHs + sw128(nb * 16 + lrow, 2 * ks + lch));
                #pragma unroll
                for (int h2 = 0; h2 < 2; h2++)
                    mma16816(s[nb * 2 + h2], qf[ks], bh[h2], bh[h2 + 2]);
            }
        }
        if (mask) {
            const int mr = q0 + wid * 16 + g;
            #pragma unroll
            for (int nj = 0; nj < 8; nj++) {
                const int mc = kt * 64 + nj * 8 + tg * 2;
                float2 a0 = *(const float2*)(mask + (long)mr * 512 + mc);
                float2 a1 = *(const float2*)(mask + (long)(mr + 8) * 512 + mc);
                s[nj][0] += a0.x; s[nj][1] += a0.y;
                s[nj][2] += a1.x; s[nj][3] += a1.y;
            }
        }

        // online softmax (rows g and g+8; reduce across tg lanes)
        float tm0 = -1e30f, tm1 = -1e30f;
        #pragma unroll
        for (int nj = 0; nj < 8; nj++) {
            tm0 = fmaxf(tm0, fmaxf(s[nj][0], s[nj][1]));
            tm1 = fmaxf(tm1, fmaxf(s[nj][2], s[nj][3]));
        }
        tm0 = fmaxf(tm0, __shfl_xor_sync(~0u, tm0, 1));
        tm0 = fmaxf(tm0, __shfl_xor_sync(~0u, tm0, 2));
        tm1 = fmaxf(tm1, __shfl_xor_sync(~0u, tm1, 1));
        tm1 = fmaxf(tm1, __shfl_xor_sync(~0u, tm1, 2));
        const float nm0 = fmaxf(m0, tm0), nm1 = fmaxf(m1, tm1);
        float sum0 = 0.f, sum1 = 0.f;
        #pragma unroll
        for (int nj = 0; nj < 8; nj++) {
            s[nj][0] = __expf(s[nj][0] - nm0); sum0 += s[nj][0];
            s[nj][1] = __expf(s[nj][1] - nm0); sum0 += s[nj][1];
            s[nj][2] = __expf(s[nj][2] - nm1); sum1 += s[nj][2];
            s[nj][3] = __expf(s[nj][3] - nm1); sum1 += s[nj][3];
        }
        sum0 += __shfl_xor_sync(~0u, sum0, 1);
        sum0 += __shfl_xor_sync(~0u, sum0, 2);
        sum1 += __shfl_xor_sync(~0u, sum1, 1);
        sum1 += __shfl_xor_sync(~0u, sum1, 2);
        const float c0 = __expf(m0 - nm0), c1 = __expf(m1 - nm1);
        l0 = l0 * c0 + sum0; l1 = l1 * c1 + sum1;
        m0 = nm0; m1 = nm1;
        #pragma unroll
        for (int j = 0; j < 8; j++) {
            o[j][0] *= c0; o[j][1] *= c0; o[j][2] *= c1; o[j][3] *= c1;
        }

        // P fragments (1-term bf16; FA2 accum->A identity)
        uint32_t ph[4][4];
        #pragma unroll
        for (int ks = 0; ks < 4; ks++) {
            ph[ks][0] = pack_bf2(s[2*ks][0],   s[2*ks][1]);
            ph[ks][1] = pack_bf2(s[2*ks][2],   s[2*ks][3]);
            ph[ks][2] = pack_bf2(s[2*ks+1][0], s[2*ks+1][1]);
            ph[ks][3] = pack_bf2(s[2*ks+1][2], s[2*ks+1][3]);
        }

        // O += P V  (V^T fragments via ldmatrix.trans; 1-term)
        #pragma unroll
        for (int ks = 0; ks < 4; ks++) {
            #pragma unroll
            for (int nb = 0; nb < 4; nb++) {
                uint32_t vh[4];
                ldsm4t(vh, VHs + sw128(ks * 16 + (lane & 15), 2 * nb + lch));
                #pragma unroll
                for (int h2 = 0; h2 < 2; h2++)
                    mma16816(o[nb * 2 + h2], ph[ks],
                             vh[h2 * 2], vh[h2 * 2 + 1]);
            }
        }
    }

    const float i0 = 1.f / l0, i1 = 1.f / l1;
    const int row = q0 + wid * 16 + g;
    #pragma unroll
    for (int nj = 0; nj < 8; nj++) {
        const long o0 = (long)b * MB + (long)row * 512 + h * 64 + nj * 8 + tg * 2;
        pack_store(O, o0,           o[nj][0] * i0, o[nj][1] * i0);
        pack_store(O, o0 + 8 * 512, o[nj][2] * i1, o[nj][3] * i1);
    }
}

// ---------------------------------------------------------------------------
// Launch sequence (single stream, graph-capturable, allocation-free)
// ---------------------------------------------------------------------------
extern "C" void kernel_launch(void* const* d_in, const int* in_sizes, int n_in,
                              void* d_out, int out_size)
{
    const float* x             = (const float*)d_in[0];
    const float* mask          = (const float*)d_in[1];
    const float* Wq_inter      = (const float*)d_in[2];
    const float* Wk_inter      = (const float*)d_in[3];
    const float* Wv_inter      = (const float*)d_in[4];
    const float* Wq_intra      = (const float*)d_in[5];
    const float* Wk_intra      = (const float*)d_in[6];
    const float* Wv_intra      = (const float*)d_in[7];
    const float* W_proj_in     = (const float*)d_in[8];
    const float* W_proj_out    = (const float*)d_in[9];
    const float* W_split_inter = (const float*)d_in[10];
    const float* W_out_inter   = (const float*)d_in[11];
    const float* W_split_intra = (const float*)d_in[12];
    const float* W_out_intra   = (const float*)d_in[13];
    const float* alpha         = (const float*)d_in[14];
    float* out = (float*)d_out;

    float* oi;
    cudaGetSymbolAddress((void**)&oi, g_oi);

    bf *xT, *xp, *cc, *oib, *qq, *kk, *vv;
    bf *wcin, *wcout, *wsi, *woi;
    bf *wqA, *wkA, *wvA, *wqB, *wkB, *wvB;
    cudaGetSymbolAddress((void**)&xT,  g_xT);
    cudaGetSymbolAddress((void**)&xp,  g_xp);
    cudaGetSymbolAddress((void**)&cc,  g_cc);
    cudaGetSymbolAddress((void**)&oib, g_oib);
    cudaGetSymbolAddress((void**)&qq,  g_q);
    cudaGetSymbolAddress((void**)&kk,  g_k);
    cudaGetSymbolAddress((void**)&vv,  g_v);
    cudaGetSymbolAddress((void**)&wcin,  g_wcin);
    cudaGetSymbolAddress((void**)&wcout, g_wcout);
    cudaGetSymbolAddress((void**)&wsi,   g_wsi);
    cudaGetSymbolAddress((void**)&woi,   g_woi);
    cudaGetSymbolAddress((void**)&wqA, g_wqA);
    cudaGetSymbolAddress((void**)&wkA, g_wkA);
    cudaGetSymbolAddress((void**)&wvA, g_wvA);
    cudaGetSymbolAddress((void**)&wqB, g_wqB);
    cudaGetSymbolAddress((void**)&wkB, g_wkB);
    cudaGetSymbolAddress((void**)&wvB, g_wvB);

    cudaFuncSetAttribute(tc_gemm<0,0,1>, cudaFuncAttributeMaxDynamicSharedMemorySize, TCG_SMEM);
    cudaFuncSetAttribute(tc_gemm<1,1,1>, cudaFuncAttributeMaxDynamicSharedMemorySize, TCG_SMEM);
    cudaFuncSetAttribute(tc_gemm<2,1,0>, cudaFuncAttributeMaxDynamicSharedMemorySize, TCG_SMEM);
    cudaFuncSetAttribute(qkv_mma,  cudaFuncAttributeMaxDynamicSharedMemorySize, QKV_SMEM);
    cudaFuncSetAttribute(attn_mma, cudaFuncAttributeMaxDynamicSharedMemorySize, ATTN_SMEM);

    dim3 gb(4, 4, BATCH);
    dim3 gq(8, NH, BATCH);
    dim3 gattn(4, NH, BATCH);
    dim3 gts(16, 16, BATCH), tts(32, 8);
    const long W4 = MB / 4, H4 = (long)NH * 4096 / 4;

    // Combined weights: fp32 GEMM with direct bf16 epilogue (2 jobs)
    gemm64w<<<dim3(8, 8, 2), 256>>>(W_split_inter, W_proj_in, wcin,
                                    W_proj_out, W_out_inter, wcout);

    // All independent weight conversions in ONE launch
    SplitJobs jobs;
    jobs.j[0] = {(const float4*)W_split_intra, wsi, W4};
    jobs.j[1] = {(const float4*)W_out_intra,   woi, W4};
    jobs.j[2] = {(const float4*)Wq_inter, wqA, H4};
    jobs.j[3] = {(const float4*)Wk_inter, wkA, H4};
    jobs.j[4] = {(const float4*)Wv_inter, wvA, H4};
    jobs.j[5] = {(const float4*)Wq_intra, wqB, H4};
    jobs.j[6] = {(const float4*)Wk_intra, wkB, H4};
    jobs.j[7] = {(const float4*)Wv_intra, wvB, H4};
    split8<<<dim3(256, 8, 1), 256>>>(jobs);

    transpose_bf16_kernel<<<gts, tts>>>(x, xT);

    // GEMM1: xp = xT @ wcin^T  (bf16 out)
    tc_gemm<0,0,1><<<gb, 256, TCG_SMEM>>>(xT, MB, wcin, 0,
                                          nullptr, xp, MB, nullptr, 0, nullptr);
    // inter path
    qkv_mma<<<gq, 128, QKV_SMEM>>>(xp, wqA, wkA, wvA, qq, kk, vv);
    attn_mma<<<gattn, 256, ATTN_SMEM>>>(qq, kk, vv, nullptr, cc);
    // GEMM2: oi = wcout @ cc^T + x  (fp32 + bf16 out)
    tc_gemm<1,1,1><<<gb, 256, TCG_SMEM>>>(wcout, 0, cc, MB,
                                          oi, oib, MB, x, MB, nullptr);
    // GEMM3: xi = oib @ wsi^T  (bf16 out, reuse xp)
    tc_gemm<0,0,1><<<gb, 256, TCG_SMEM>>>(oib, MB, wsi, 0,
                                          nullptr, xp, MB, nullptr, 0, nullptr);
    // intra path
    qkv_mma<<<gq, 128, QKV_SMEM>>>(xp, wqB, wkB, wvB, qq, kk, vv);
    attn_mma<<<gattn, 256, ATTN_SMEM>>>(qq, kk, vv, mask, cc);
    // GEMM4: out = (1-a)*(cc @ woi^T) + a*oi
    tc_gemm<2,1,0><<<gb, 256, TCG_SMEM>>>(cc, MB, woi, 0,
                                          out, nullptr, MB, oi, MB, alpha);
}

// round 16
// speedup vs baseline: 2.3594x; 1.0046x over previous
#include <cuda_runtime.h>
#include <cuda_bf16.h>
#include <cstdint>

using bf = __nv_bfloat16;
static constexpr int  BATCH = 32;
static constexpr int  NH    = 8;
static constexpr long MB    = 512L * 512L;
static constexpr long HB    = 512L * 64L;

// ---------------------------------------------------------------------------
// Scratch (static __device__ arrays: allocation-free per harness rules)
// ---------------------------------------------------------------------------
__device__ float g_oi [(long)BATCH * 512 * 512];

__device__ bf g_xT [(long)BATCH * MB];
__device__ bf g_xp [(long)BATCH * MB];
__device__ bf g_cc [(long)BATCH * MB];
__device__ bf g_oib[(long)BATCH * MB];
__device__ bf g_q  [(long)BATCH * NH * HB];
__device__ bf g_k  [(long)BATCH * NH * HB];
__device__ bf g_v  [(long)BATCH * NH * HB];

__device__ bf g_wcin [MB];
__device__ bf g_wcout[MB];
__device__ bf g_wsi  [MB];
__device__ bf g_woi  [MB];
__device__ bf g_wqA[NH*4096], g_wkA[NH*4096], g_wvA[NH*4096];
__device__ bf g_wqB[NH*4096], g_wkB[NH*4096], g_wvB[NH*4096];

// ---------------------------------------------------------------------------
// Low-level helpers (sm_80+ baseline)
// ---------------------------------------------------------------------------
__device__ __forceinline__ void mma16816(float* c, const uint32_t* a,
                                         uint32_t b0, uint32_t b1) {
    asm volatile(
        "mma.sync.aligned.m16n8k16.row.col.f32.bf16.bf16.f32 "
        "{%0,%1,%2,%3}, {%4,%5,%6,%7}, {%8,%9}, {%0,%1,%2,%3};"
        : "+f"(c[0]), "+f"(c[1]), "+f"(c[2]), "+f"(c[3])
        : "r"(a[0]), "r"(a[1]), "r"(a[2]), "r"(a[3]), "r"(b0), "r"(b1));
}
__device__ __forceinline__ void ldsm4(uint32_t* r, uint32_t a) {
    asm volatile("ldmatrix.sync.aligned.m8n8.x4.shared.b16 {%0,%1,%2,%3}, [%4];"
                 : "=r"(r[0]), "=r"(r[1]), "=r"(r[2]), "=r"(r[3]) : "r"(a));
}
__device__ __forceinline__ void ldsm4t(uint32_t* r, uint32_t a) {
    asm volatile("ldmatrix.sync.aligned.m8n8.x4.trans.shared.b16 {%0,%1,%2,%3}, [%4];"
                 : "=r"(r[0]), "=r"(r[1]), "=r"(r[2]), "=r"(r[3]) : "r"(a));
}
__device__ __forceinline__ void cpa16(uint32_t s, const void* g) {
    asm volatile("cp.async.cg.shared.global [%0], [%1], 16;" :: "r"(s), "l"(g));
}
#define CP_COMMIT() asm volatile("cp.async.commit_group;" ::: "memory")
#define CP_WAIT(N)  asm volatile("cp.async.wait_group %0;" :: "n"(N) : "memory")
__device__ __forceinline__ uint32_t smem_u32(const void* p) {
    uint32_t a;
    asm("{ .reg .u64 t; cvta.to.shared.u64 t, %1; cvt.u32.u64 %0, t; }"
        : "=r"(a) : "l"(p));
    return a;
}
// XOR swizzle for 128B rows (conflict-free for ldsm/ldsm.trans 8-row phases)
__device__ __forceinline__ uint32_t sw128(int r, int c) {
    return (uint32_t)(r * 128 + ((c ^ (r & 7)) << 4));
}
__device__ __forceinline__ void pack_store(bf* C, long off, float a, float b) {
    __nv_bfloat162 h;
    h.x = __float2bfloat16_rn(a); h.y = __float2bfloat16_rn(b);
    *reinterpret_cast<uint32_t*>(C + off) = *reinterpret_cast<uint32_t*>(&h);
}
__device__ __forceinline__ uint32_t pack_bf2(float a, float b) {
    __nv_bfloat162 h;
    h.x = __float2bfloat16_rn(a); h.y = __float2bfloat16_rn(b);
    return *reinterpret_cast<uint32_t*>(&h);
}

// ---------------------------------------------------------------------------
// Batched fp32 -> bf16 weight conversions: 8 jobs, one launch
// ---------------------------------------------------------------------------
struct SplitJob  { const float4* src; bf* dst; long n4; };
struct SplitJobs { SplitJob j[8]; };

__global__ __launch_bounds__(256) void split8(SplitJobs jobs)
{
    const SplitJob jb = jobs.j[blockIdx.y];
    long i = (long)blockIdx.x * 256 + threadIdx.x;
    if (i >= jb.n4) return;
    float4 v = jb.src[i];
    uint2 p;
    p.x = pack_bf2(v.x, v.y);
    p.y = pack_bf2(v.z, v.w);
    *(uint2*)(jb.dst + i * 4) = p;
}

__global__ __launch_bounds__(256) void transpose_bf16_kernel(
    const float* __restrict__ in, bf* __restrict__ outb)
{
    __shared__ float t[32][33];
    const int b = blockIdx.z;
    const int s0 = blockIdx.x * 32, d0 = blockIdx.y * 32;
    const long base = (long)b * MB;
    const int tx = threadIdx.x, ty = threadIdx.y;
    #pragma unroll
    for (int i = ty; i < 32; i += 8)
        t[i][tx] = in[base + (long)(s0 + i) * 512 + d0 + tx];
    __syncthreads();
    #pragma unroll
    for (int i = ty; i < 32; i += 8) {
        long o = base + (long)(d0 + i) * 512 + s0 + tx;
        outb[o] = __float2bfloat16_rn(t[tx][i]);
    }
}

// ---------------------------------------------------------------------------
// Weight-combine GEMM (fp32 in, bf16 out): C[m][n] = sum_k A[m,k]*B[k,n]
// ---------------------------------------------------------------------------
__global__ __launch_bounds__(256) void gemm64w(
    const float* __restrict__ A0, const float* __restrict__ B0,
    bf* __restrict__ C0,
    const float* __restrict__ A1, const float* __restrict__ B1,
    bf* __restrict__ C1)
{
    const float* A = blockIdx.z ? A1 : A0;
    const float* B = blockIdx.z ? B1 : B0;
    bf* Cb = blockIdx.z ? C1 : C0;
    __shared__ float As[16][64], Bs[16][64];
    const int bM = blockIdx.y * 64, bN = blockIdx.x * 64;
    const int tid = threadIdx.x, tx = tid & 15, ty = tid >> 4;
    float acc[4][4];
    #pragma unroll
    for (int i = 0; i < 4; i++)
        #pragma unroll
        for (int j = 0; j < 4; j++) acc[i][j] = 0.f;
    for (int kt = 0; kt < 32; kt++) {
        const int k0 = kt * 16;
        __syncthreads();
        #pragma unroll
        for (int it = 0; it < 4; it++) {
            int id = tid + it * 256;
            As[id & 15][id >> 4] = A[(long)(bM + (id >> 4)) * 512 + k0 + (id & 15)];
            Bs[id >> 6][id & 63] = B[(long)(k0 + (id >> 6)) * 512 + bN + (id & 63)];
        }
        __syncthreads();
        #pragma unroll
        for (int k = 0; k < 16; k++) {
            float av[4], bv[4];
            #pragma unroll
            for (int i = 0; i < 4; i++) av[i] = As[k][ty * 4 + i];
            #pragma unroll
            for (int j = 0; j < 4; j++) bv[j] = Bs[k][tx * 4 + j];
            #pragma unroll
            for (int i = 0; i < 4; i++)
                #pragma unroll
                for (int j = 0; j < 4; j++)
                    acc[i][j] = fmaf(av[i], bv[j], acc[i][j]);
        }
    }
    #pragma unroll
    for (int i = 0; i < 4; i++) {
        const long o = (long)(bM + ty * 4 + i) * 512 + bN + tx * 4;
        pack_store(Cb, o,     acc[i][0], acc[i][1]);
        pack_store(Cb, o + 2, acc[i][2], acc[i][3]);
    }
}

// ---------------------------------------------------------------------------
// Pipelined tensor-core batched GEMM (1-term bf16):
// C[b][m][n] = sum_k A[b][m][k]*B[b][n][k]
// BK=64, 3-stage cp.async, sw128-swizzled smem, ONE sync per 64-K iter,
// B-fragment ping-pong prefetch across nb blocks.
// ---------------------------------------------------------------------------
static constexpr int ARR = 128 * 128;          // bytes per array (16384)
static constexpr int STG = 2 * ARR;            // bytes per stage  (32768)
static constexpr int TCG_SMEM = 3 * STG;       // 98304

__device__ __forceinline__ void tcg_load(
    uint32_t sb, const bf* A, const bf* B, int bM, int bN, int k0, int tid)
{
    #pragma unroll
    for (int a = 0; a < 2; a++) {
        const bf* src = a ? B : A;
        const int row0 = a ? bN : bM;
        const uint32_t dst = sb + a * ARR;
        #pragma unroll
        for (int it = 0; it < 4; it++) {
            int id = tid + it * 256;           // 0..1023
            int r = id >> 3, c8 = id & 7;
            cpa16(dst + sw128(r, c8),
                  src + (long)(row0 + r) * 512 + k0 + c8 * 8);
        }
    }
}

template<int EPI, int OF32, int OBF16>
__global__ __launch_bounds__(256, 2) void tc_gemm(
    const bf* __restrict__ A, long sA,
    const bf* __restrict__ B, long sB,
    float* __restrict__ C, bf* __restrict__ Cb, long sC,
    const float* __restrict__ R, long sR, const float* __restrict__ alpha_ptr)
{
    extern __shared__ __align__(16) char smc[];
    const uint32_t sb0 = smem_u32(smc);
    const int tid = threadIdx.x, lane = tid & 31, wid = tid >> 5;
    const int g = lane >> 2, tg = lane & 3;
    const int wm = (wid >> 1) * 32, wn = (wid & 1) * 64;
    const int bN = blockIdx.x * 128, bM = blockIdx.y * 128, bz = blockIdx.z;
    A += (long)bz * sA;
    B += (long)bz * sB;
    if (EPI != 0) R += (long)bz * sR;

    const int lrow = (lane & 7) + ((lane >> 3) & 1) * 8;
    const int lch  = lane >> 4;                 // chunk half-select 0/1

    float acc[2][8][4];
    #pragma unroll
    for (int i = 0; i < 2; i++)
        #pragma unroll
        for (int j = 0; j < 8; j++)
            #pragma unroll
            for (int q = 0; q < 4; q++) acc[i][j][q] = 0.f;

    tcg_load(sb0,       A, B, bM, bN, 0,  tid); CP_COMMIT();
    tcg_load(sb0 + STG, A, B, bM, bN, 64, tid); CP_COMMIT();

    int st = 0, ld = 2;
    for (int t = 0; t < 8; t++) {
        if (t < 7) { CP_WAIT(1); } else { CP_WAIT(0); }
        __syncthreads();
        if (t < 6) {
            tcg_load(sb0 + ld * STG, A, B, bM, bN, (t + 2) * 64, tid);
            CP_COMMIT();
            if (++ld == 3) ld = 0;
        }
        const uint32_t sb = sb0 + st * STG;
        if (++st == 3) st = 0;
        #pragma unroll
        for (int ks = 0; ks < 4; ks++) {
            const int ch = 2 * ks + lch;
            uint32_t af[2][4];
            #pragma unroll
            for (int mi = 0; mi < 2; mi++)
                ldsm4(af[mi], sb + sw128(wm + mi * 16 + lrow, ch));
            // B-fragment ping-pong: prefetch nb+1 before nb's MMAs
            uint32_t bA[4], bB[4];
            ldsm4(bA, sb + ARR + sw128(wn + lrow, ch));
            #pragma unroll
            for (int nb = 0; nb < 4; nb++) {
                uint32_t* bc = (nb & 1) ? bB : bA;
                uint32_t* bn = (nb & 1) ? bA : bB;
                if (nb < 3)
                    ldsm4(bn, sb + ARR + sw128(wn + (nb + 1) * 16 + lrow, ch));
                #pragma unroll
                for (int h2 = 0; h2 < 2; h2++)
                    #pragma unroll
                    for (int mi = 0; mi < 2; mi++)
                        mma16816(acc[mi][nb * 2 + h2], af[mi],
                                 bc[h2], bc[h2 + 2]);
            }
        }
    }

    float ab = 0.f;
    if (EPI == 2) ab = 1.f / (1.f + expf(-alpha_ptr[0]));
    #pragma unroll
    for (int mi = 0; mi < 2; mi++)
        #pragma unroll
        for (int nj = 0; nj < 8; nj++) {
            const int row = bM + wm + mi * 16 + g;
            const int col = bN + wn + nj * 8 + tg * 2;
            float v0 = acc[mi][nj][0], v1 = acc[mi][nj][1];
            float v2 = acc[mi][nj][2], v3 = acc[mi][nj][3];
            const long o0 = (long)bz * sC + (long)row * 512 + col;
            const long o1 = o0 + 8 * 512;
            if (EPI == 1) {
                float2 r0 = *(const float2*)(R + (long)row * 512 + col);
                float2 r1 = *(const float2*)(R + (long)(row + 8) * 512 + col);
                v0 += r0.x; v1 += r0.y; v2 += r1.x; v3 += r1.y;
            } else if (EPI == 2) {
                float2 r0 = *(const float2*)(R + (long)row * 512 + col);
                float2 r1 = *(const float2*)(R + (long)(row + 8) * 512 + col);
                v0 = (1.f - ab) * v0 + ab * r0.x;
                v1 = (1.f - ab) * v1 + ab * r0.y;
                v2 = (1.f - ab) * v2 + ab * r1.x;
                v3 = (1.f - ab) * v3 + ab * r1.y;
            }
            if (OF32) {
                float2 w0 = {v0, v1}, w1 = {v2, v3};
                *(float2*)(C + o0) = w0;
                *(float2*)(C + o1) = w1;
            }
            if (OBF16) {
                pack_store(Cb, o0, v0, v1);
                pack_store(Cb, o1, v2, v3);
            }
        }
}

// ---------------------------------------------------------------------------
// QKV projection (mma, 1-term): per (64-token tile, head, batch).
// Single-bf16 outputs. Q pre-scaled by 1/8. B-fragment ping-pong.
// ---------------------------------------------------------------------------
static constexpr int SK = 72;
static constexpr int QKV_SMEM = 4 * 64 * SK * 2;   // 36864

__device__ __forceinline__ void head_gemm(
    uint32_t wbase, const uint32_t xf[4][4],
    float scale, bf* O, long obase, int row0, int lane)
{
    const int g = lane >> 2, tg = lane & 3;
    const uint32_t lrow = (lane & 7) + ((lane >> 3) & 1) * 8;
    const uint32_t lc8 = (lane >> 4) * 8;
    float acc[8][4];
    #pragma unroll
    for (int j = 0; j < 8; j++)
        #pragma unroll
        for (int q = 0; q < 4; q++) acc[j][q] = 0.f;
    #pragma unroll
    for (int ks = 0; ks < 4; ks++) {
        uint32_t bA[4], bB[4];
        ldsm4(bA, wbase + (lrow * SK + ks * 16 + lc8) * 2);
        #pragma unroll
        for (int nb = 0; nb < 4; nb++) {
            uint32_t* bc = (nb & 1) ? bB : bA;
            uint32_t* bn = (nb & 1) ? bA : bB;
            if (nb < 3)
                ldsm4(bn, wbase + (((nb + 1) * 16 + lrow) * SK + ks * 16 + lc8) * 2);
            #pragma unroll
            for (int h2 = 0; h2 < 2; h2++)
                mma16816(acc[nb * 2 + h2], xf[ks], bc[h2], bc[h2 + 2]);
        }
    }
    #pragma unroll
    for (int nj = 0; nj < 8; nj++) {
        const long o0 = obase + (long)(row0 + g) * 64 + nj * 8 + tg * 2;
        pack_store(O, o0,          acc[nj][0] * scale, acc[nj][1] * scale);
        pack_store(O, o0 + 8 * 64, acc[nj][2] * scale, acc[nj][3] * scale);
    }
}

__global__ __launch_bounds__(128) void qkv_mma(
    const bf* __restrict__ X,
    const bf* __restrict__ Wq, const bf* __restrict__ Wk,
    const bf* __restrict__ Wv,
    bf* __restrict__ Q, bf* __restrict__ K, bf* __restrict__ V)
{
    extern __shared__ __align__(16) bf smq[];
    const int tile0 = blockIdx.x * 64, h = blockIdx.y, b = blockIdx.z;
    const int tid = threadIdx.x, lane = tid & 31, wid = tid >> 5;
    const long xbase = (long)b * MB;
    const long obase = (long)(b * NH + h) * HB;
    bf* Xs = smq;
    bf* Ws = smq + 64 * SK;

    #pragma unroll
    for (int it = 0; it < 4; it++) {
        int id = tid + it * 128;
        int r = id >> 3, c8 = (id & 7) * 8;
        *(uint4*)(Xs + r * SK + c8) =
            *(const uint4*)(X + xbase + (long)(tile0 + r) * 512 + h * 64 + c8);
    }
    const bf* wsrc[3] = {Wq, Wk, Wv};
    #pragma unroll
    for (int a = 0; a < 3; a++)
        #pragma unroll
        for (int it = 0; it < 4; it++) {
            int id = tid + it * 128;
            int r = id >> 3, c8 = (id & 7) * 8;
            *(uint4*)(Ws + a * 64 * SK + r * SK + c8) =
                *(const uint4*)(wsrc[a] + h * 4096 + r * 64 + c8);
        }
    __syncthreads();

    const uint32_t xb = smem_u32(Xs);
    const uint32_t lrow = (lane & 7) + ((lane >> 3) & 1) * 8;
    const uint32_t lc8 = (lane >> 4) * 8;
    uint32_t xf[4][4];
    #pragma unroll
    for (int ks = 0; ks < 4; ks++)
        ldsm4(xf[ks], xb + ((wid * 16 + lrow) * SK + ks * 16 + lc8) * 2);

    const uint32_t wb = smem_u32(Ws);
    const int row0 = tile0 + wid * 16;
    head_gemm(wb,                xf, 0.125f, Q, obase, row0, lane);
    head_gemm(wb + 64 * SK * 2,  xf, 1.f,    K, obase, row0, lane);
    head_gemm(wb + 128 * SK * 2, xf, 1.f,    V, obase, row0, lane);
}

// ---------------------------------------------------------------------------
// Flash attention (mma, 1-term): 256 threads, 128-row q-strip, 3-stage
// swizzled cp.async K/V pipeline, ONE sync per kv-iter.
// K/V fragment ping-pong prefetch. Output bf16, head-concat.
// ---------------------------------------------------------------------------
static constexpr int AAR = 64 * 128;                 // bytes per KV array (8192)
static constexpr int STA = 2 * AAR;                  // K, V (16384)
static constexpr int ATTN_SMEM = 3 * STA;            // 49152

__device__ __forceinline__ void attn_load_kv(
    uint32_t dst, const bf* K, const bf* V, long base, int kt, int tid)
{
    #pragma unroll
    for (int it = 0; it < 2; it++) {
        int id = tid + it * 256;       // 0..511
        int r = id >> 3, c8 = id & 7;
        const long gsrc = base + (long)(kt * 64 + r) * 64 + c8 * 8;
        const uint32_t so = sw128(r, c8);
        cpa16(dst       + so, K + gsrc);
        cpa16(dst + AAR + so, V + gsrc);
    }
}

__global__ __launch_bounds__(256, 2) void attn_mma(
    const bf* __restrict__ Q, const bf* __restrict__ K,
    const bf* __restrict__ V,
    const float* __restrict__ mask,
    bf* __restrict__ O)
{
    extern __shared__ __align__(16) bf sma[];
    const int q0 = blockIdx.x * 128, h = blockIdx.y, b = blockIdx.z;
    const int tid = threadIdx.x, lane = tid & 31, wid = tid >> 5;
    const int g = lane >> 2, tg = lane & 3;
    const long base = (long)(b * NH + h) * HB;
    const uint32_t sb = smem_u32(sma);
    const int lrow = (lane & 7) + ((lane >> 3) & 1) * 8;
    const int lch  = lane >> 4;

    // Stage the 128-row Q strip through the start of smem
    #pragma unroll
    for (int it = 0; it < 2; it++) {
        int id = tid + it * 256;       // 0..511
        int r = id >> 2, c8 = (id & 3) * 2;
        const long gq = base + (long)(q0 + r) * 64 + c8 * 8;
        cpa16(sb + sw128(r, c8),     Q + gq);
        cpa16(sb + sw128(r, c8 + 1), Q + gq + 8);
    }
    CP_COMMIT(); CP_WAIT(0);
    __syncthreads();
    uint32_t qf[4][4];
    #pragma unroll
    for (int ks = 0; ks < 4; ks++)
        ldsm4(qf[ks], sb + sw128(wid * 16 + lrow, 2 * ks + lch));
    __syncthreads();   // all warps done reading Q before stages are reused

    float m0 = -1e30f, m1 = -1e30f, l0 = 0.f, l1 = 0.f;
    float o[8][4];
    #pragma unroll
    for (int j = 0; j < 8; j++)
        #pragma unroll
        for (int q = 0; q < 4; q++) o[j][q] = 0.f;

    attn_load_kv(sb,       K, V, base, 0, tid); CP_COMMIT();
    attn_load_kv(sb + STA, K, V, base, 1, tid); CP_COMMIT();

    int st = 0, ld = 2;
    for (int kt = 0; kt < 8; kt++) {
        if (kt < 7) { CP_WAIT(1); } else { CP_WAIT(0); }
        __syncthreads();
        if (kt < 6) {
            attn_load_kv(sb + ld * STA, K, V, base, kt + 2, tid);
            CP_COMMIT();
            if (++ld == 3) ld = 0;
        }
        const uint32_t KHs = sb + st * STA;
        if (++st == 3) st = 0;
        const uint32_t VHs = KHs + AAR;

        // S = Q K^T (1-term), K-fragment ping-pong across nb
        float s[8][4];
        #pragma unroll
        for (int j = 0; j < 8; j++)
            #pragma unroll
            for (int q = 0; q < 4; q++) s[j][q] = 0.f;
        #pragma unroll
        for (int ks = 0; ks < 4; ks++) {
            uint32_t bA[4], bB[4];
            ldsm4(bA, KHs + sw128(lrow, 2 * ks + lch));
            #pragma unroll
            for (int nb = 0; nb < 4; nb++) {
                uint32_t* bc = (nb & 1) ? bB : bA;
                uint32_t* bn = (nb & 1) ? bA : bB;
                if (nb < 3)
                    ldsm4(bn, KHs + sw128((nb + 1) * 16 + lrow, 2 * ks + lch));
                #pragma unroll
                for (int h2 = 0; h2 < 2; h2++)
                    mma16816(s[nb * 2 + h2], qf[ks], bc[h2], bc[h2 + 2]);
            }
        }
        if (mask) {
            const int mr = q0 + wid * 16 + g;
            #pragma unroll
            for (int nj = 0; nj < 8; nj++) {
                const int mc = kt * 64 + nj * 8 + tg * 2;
                float2 a0 = *(const float2*)(mask + (long)mr * 512 + mc);
                float2 a1 = *(const float2*)(mask + (long)(mr + 8) * 512 + mc);
                s[nj][0] += a0.x; s[nj][1] += a0.y;
                s[nj][2] += a1.x; s[nj][3] += a1.y;
            }
        }

        // online softmax (rows g and g+8; reduce across tg lanes)
        float tm0 = -1e30f, tm1 = -1e30f;
        #pragma unroll
        for (int nj = 0; nj < 8; nj++) {
            tm0 = fmaxf(tm0, fmaxf(s[nj][0], s[nj][1]));
            tm1 = fmaxf(tm1, fmaxf(s[nj][2], s[nj][3]));
        }
        tm0 = fmaxf(tm0, __shfl_xor_sync(~0u, tm0, 1));
        tm0 = fmaxf(tm0, __shfl_xor_sync(~0u, tm0, 2));
        tm1 = fmaxf(tm1, __shfl_xor_sync(~0u, tm1, 1));
        tm1 = fmaxf(tm1, __shfl_xor_sync(~0u, tm1, 2));
        const float nm0 = fmaxf(m0, tm0), nm1 = fmaxf(m1, tm1);
        float sum0 = 0.f, sum1 = 0.f;
        #pragma unroll
        for (int nj = 0; nj < 8; nj++) {
            s[nj][0] = __expf(s[nj][0] - nm0); sum0 += s[nj][0];
            s[nj][1] = __expf(s[nj][1] - nm0); sum0 += s[nj][1];
            s[nj][2] = __expf(s[nj][2] - nm1); sum1 += s[nj][2];
            s[nj][3] = __expf(s[nj][3] - nm1); sum1 += s[nj][3];
        }
        sum0 += __shfl_xor_sync(~0u, sum0, 1);
        sum0 += __shfl_xor_sync(~0u, sum0, 2);
        sum1 += __shfl_xor_sync(~0u, sum1, 1);
        sum1 += __shfl_xor_sync(~0u, sum1, 2);
        const float c0 = __expf(m0 - nm0), c1 = __expf(m1 - nm1);
        l0 = l0 * c0 + sum0; l1 = l1 * c1 + sum1;
        m0 = nm0; m1 = nm1;
        #pragma unroll
        for (int j = 0; j < 8; j++) {
            o[j][0] *= c0; o[j][1] *= c0; o[j][2] *= c1; o[j][3] *= c1;
        }

        // P fragments (1-term bf16; FA2 accum->A identity)
        uint32_t ph[4][4];
        #pragma unroll
        for (int ks = 0; ks < 4; ks++) {
            ph[ks][0] = pack_bf2(s[2*ks][0],   s[2*ks][1]);
            ph[ks][1] = pack_bf2(s[2*ks][2],   s[2*ks][3]);
            ph[ks][2] = pack_bf2(s[2*ks+1][0], s[2*ks+1][1]);
            ph[ks][3] = pack_bf2(s[2*ks+1][2], s[2*ks+1][3]);
        }

        // O += P V  (V^T fragments via ldmatrix.trans; ping-pong across nb)
        #pragma unroll
        for (int ks = 0; ks < 4; ks++) {
            uint32_t vA[4], vB[4];
            ldsm4t(vA, VHs + sw128(ks * 16 + (lane & 15), lch));
            #pragma unroll
            for (int nb = 0; nb < 4; nb++) {
                uint32_t* vc = (nb & 1) ? vB : vA;
                uint32_t* vn = (nb & 1) ? vA : vB;
                if (nb < 3)
                    ldsm4t(vn, VHs + sw128(ks * 16 + (lane & 15),
                                           2 * (nb + 1) + lch));
                #pragma unroll
                for (int h2 = 0; h2 < 2; h2++)
                    mma16816(o[nb * 2 + h2], ph[ks],
                             vc[h2 * 2], vc[h2 * 2 + 1]);
            }
        }
    }

    const float i0 = 1.f / l0, i1 = 1.f / l1;
    const int row = q0 + wid * 16 + g;
    #pragma unroll
    for (int nj = 0; nj < 8; nj++) {
        const long o0 = (long)b * MB + (long)row * 512 + h * 64 + nj * 8 + tg * 2;
        pack_store(O, o0,           o[nj][0] * i0, o[nj][1] * i0);
        pack_store(O, o0 + 8 * 512, o[nj][2] * i1, o[nj][3] * i1);
    }
}

// ---------------------------------------------------------------------------
// Launch sequence (single stream, graph-capturable, allocation-free)
// ---------------------------------------------------------------------------
extern "C" void kernel_launch(void* const* d_in, const int* in_sizes, int n_in,
                              void* d_out, int out_size)
{
    const float* x             = (const float*)d_in[0];
    const float* mask          = (const float*)d_in[1];
    const float* Wq_inter      = (const float*)d_in[2];
    const float* Wk_inter      = (const float*)d_in[3];
    const float* Wv_inter      = (const float*)d_in[4];
    const float* Wq_intra      = (const float*)d_in[5];
    const float* Wk_intra      = (const float*)d_in[6];
    const float* Wv_intra      = (const float*)d_in[7];
    const float* W_proj_in     = (const float*)d_in[8];
    const float* W_proj_out    = (const float*)d_in[9];
    const float* W_split_inter = (const float*)d_in[10];
    const float* W_out_inter   = (const float*)d_in[11];
    const float* W_split_intra = (const float*)d_in[12];
    const float* W_out_intra   = (const float*)d_in[13];
    const float* alpha         = (const float*)d_in[14];
    float* out = (float*)d_out;

    float* oi;
    cudaGetSymbolAddress((void**)&oi, g_oi);

    bf *xT, *xp, *cc, *oib, *qq, *kk, *vv;
    bf *wcin, *wcout, *wsi, *woi;
    bf *wqA, *wkA, *wvA, *wqB, *wkB, *wvB;
    cudaGetSymbolAddress((void**)&xT,  g_xT);
    cudaGetSymbolAddress((void**)&xp,  g_xp);
    cudaGetSymbolAddress((void**)&cc,  g_cc);
    cudaGetSymbolAddress((void**)&oib, g_oib);
    cudaGetSymbolAddress((void**)&qq,  g_q);
    cudaGetSymbolAddress((void**)&kk,  g_k);
    cudaGetSymbolAddress((void**)&vv,  g_v);
    cudaGetSymbolAddress((void**)&wcin,  g_wcin);
    cudaGetSymbolAddress((void**)&wcout, g_wcout);
    cudaGetSymbolAddress((void**)&wsi,   g_wsi);
    cudaGetSymbolAddress((void**)&woi,   g_woi);
    cudaGetSymbolAddress((void**)&wqA, g_wqA);
    cudaGetSymbolAddress((void**)&wkA, g_wkA);
    cudaGetSymbolAddress((void**)&wvA, g_wvA);
    cudaGetSymbolAddress((void**)&wqB, g_wqB);
    cudaGetSymbolAddress((void**)&wkB, g_wkB);
    cudaGetSymbolAddress((void**)&wvB, g_wvB);

    cudaFuncSetAttribute(tc_gemm<0,0,1>, cudaFuncAttributeMaxDynamicSharedMemorySize, TCG_SMEM);
    cudaFuncSetAttribute(tc_gemm<1,1,1>, cudaFuncAttributeMaxDynamicSharedMemorySize, TCG_SMEM);
    cudaFuncSetAttribute(tc_gemm<2,1,0>, cudaFuncAttributeMaxDynamicSharedMemorySize, TCG_SMEM);
    cudaFuncSetAttribute(qkv_mma,  cudaFuncAttributeMaxDynamicSharedMemorySize, QKV_SMEM);
    cudaFuncSetAttribute(attn_mma, cudaFuncAttributeMaxDynamicSharedMemorySize, ATTN_SMEM);

    dim3 gb(4, 4, BATCH);
    dim3 gq(8, NH, BATCH);
    dim3 gattn(4, NH, BATCH);
    dim3 gts(16, 16, BATCH), tts(32, 8);
    const long W4 = MB / 4, H4 = (long)NH * 4096 / 4;

    // Combined weights: fp32 GEMM with direct bf16 epilogue (2 jobs)
    gemm64w<<<dim3(8, 8, 2), 256>>>(W_split_inter, W_proj_in, wcin,
                                    W_proj_out, W_out_inter, wcout);

    // All independent weight conversions in ONE launch
    SplitJobs jobs;
    jobs.j[0] = {(const float4*)W_split_intra, wsi, W4};
    jobs.j[1] = {(const float4*)W_out_intra,   woi, W4};
    jobs.j[2] = {(const float4*)Wq_inter, wqA, H4};
    jobs.j[3] = {(const float4*)Wk_inter, wkA, H4};
    jobs.j[4] = {(const float4*)Wv_inter, wvA, H4};
    jobs.j[5] = {(const float4*)Wq_intra, wqB, H4};
    jobs.j[6] = {(const float4*)Wk_intra, wkB, H4};
    jobs.j[7] = {(const float4*)Wv_intra, wvB, H4};
    split8<<<dim3(256, 8, 1), 256>>>(jobs);

    transpose_bf16_kernel<<<gts, tts>>>(x, xT);

    // GEMM1: xp = xT @ wcin^T  (bf16 out)
    tc_gemm<0,0,1><<<gb, 256, TCG_SMEM>>>(xT, MB, wcin, 0,
                                          nullptr, xp, MB, nullptr, 0, nullptr);
    // inter path
    qkv_mma<<<gq, 128, QKV_SMEM>>>(xp, wqA, wkA, wvA, qq, kk, vv);
    attn_mma<<<gattn, 256, ATTN_SMEM>>>(qq, kk, vv, nullptr, cc);
    // GEMM2: oi = wcout @ cc^T + x  (fp32 + bf16 out)
    tc_gemm<1,1,1><<<gb, 256, TCG_SMEM>>>(wcout, 0, cc, MB,
                                          oi, oib, MB, x, MB, nullptr);
    // GEMM3: xi = oib @ wsi^T  (bf16 out, reuse xp)
    tc_gemm<0,0,1><<<gb, 256, TCG_SMEM>>>(oib, MB, wsi, 0,
                                          nullptr, xp, MB, nullptr, 0, nullptr);
    // intra path
    qkv_mma<<<gq, 128, QKV_SMEM>>>(xp, wqB, wkB, wvB, qq, kk, vv);
    attn_mma<<<gattn, 256, ATTN_SMEM>>>(qq, kk, vv, mask, cc);
    // GEMM4: out = (1-a)*(cc @ woi^T) + a*oi
    tc_gemm<2,1,0><<<gb, 256, TCG_SMEM>>>(cc, MB, woi, 0,
                                          out, nullptr, MB, oi, MB, alpha);
}

// round 17
// speedup vs baseline: 2.5069x; 1.0625x over previous
#include <cuda_runtime.h>
#include <cuda_bf16.h>
#include <cstdint>

using bf = __nv_bfloat16;
static constexpr int  BATCH = 32;
static constexpr int  NH    = 8;
static constexpr long MB    = 512L * 512L;
static constexpr long HB    = 512L * 64L;

// ---------------------------------------------------------------------------
// Scratch (static __device__ arrays: allocation-free per harness rules)
// ---------------------------------------------------------------------------
__device__ float g_oi [(long)BATCH * 512 * 512];

__device__ bf g_xT [(long)BATCH * MB];
__device__ bf g_xp [(long)BATCH * MB];
__device__ bf g_cc [(long)BATCH * MB];
__device__ bf g_oib[(long)BATCH * MB];
__device__ bf g_q  [(long)BATCH * NH * HB];
__device__ bf g_k  [(long)BATCH * NH * HB];
__device__ bf g_v  [(long)BATCH * NH * HB];

__device__ bf g_wcin [MB];
__device__ bf g_wcout[MB];
__device__ bf g_wsi  [MB];
__device__ bf g_woi  [MB];
__device__ bf g_maskb[MB];
__device__ bf g_wqA[NH*4096], g_wkA[NH*4096], g_wvA[NH*4096];
__device__ bf g_wqB[NH*4096], g_wkB[NH*4096], g_wvB[NH*4096];

// ---------------------------------------------------------------------------
// Low-level helpers (sm_80+ baseline)
// ---------------------------------------------------------------------------
__device__ __forceinline__ void mma16816(float* c, const uint32_t* a,
                                         uint32_t b0, uint32_t b1) {
    asm volatile(
        "mma.sync.aligned.m16n8k16.row.col.f32.bf16.bf16.f32 "
        "{%0,%1,%2,%3}, {%4,%5,%6,%7}, {%8,%9}, {%0,%1,%2,%3};"
        : "+f"(c[0]), "+f"(c[1]), "+f"(c[2]), "+f"(c[3])
        : "r"(a[0]), "r"(a[1]), "r"(a[2]), "r"(a[3]), "r"(b0), "r"(b1));
}
__device__ __forceinline__ void ldsm4(uint32_t* r, uint32_t a) {
    asm volatile("ldmatrix.sync.aligned.m8n8.x4.shared.b16 {%0,%1,%2,%3}, [%4];"
                 : "=r"(r[0]), "=r"(r[1]), "=r"(r[2]), "=r"(r[3]) : "r"(a));
}
__device__ __forceinline__ void ldsm4t(uint32_t* r, uint32_t a) {
    asm volatile("ldmatrix.sync.aligned.m8n8.x4.trans.shared.b16 {%0,%1,%2,%3}, [%4];"
                 : "=r"(r[0]), "=r"(r[1]), "=r"(r[2]), "=r"(r[3]) : "r"(a));
}
__device__ __forceinline__ void cpa16(uint32_t s, const void* g) {
    asm volatile("cp.async.cg.shared.global [%0], [%1], 16;" :: "r"(s), "l"(g));
}
#define CP_COMMIT() asm volatile("cp.async.commit_group;" ::: "memory")
#define CP_WAIT(N)  asm volatile("cp.async.wait_group %0;" :: "n"(N) : "memory")
__device__ __forceinline__ uint32_t smem_u32(const void* p) {
    uint32_t a;
    asm("{ .reg .u64 t; cvta.to.shared.u64 t, %1; cvt.u32.u64 %0, t; }"
        : "=r"(a) : "l"(p));
    return a;
}
// XOR swizzle for 128B rows (conflict-free for ldsm/ldsm.trans 8-row phases)
__device__ __forceinline__ uint32_t sw128(int r, int c) {
    return (uint32_t)(r * 128 + ((c ^ (r & 7)) << 4));
}
__device__ __forceinline__ void pack_store(bf* C, long off, float a, float b) {
    __nv_bfloat162 h;
    h.x = __float2bfloat16_rn(a); h.y = __float2bfloat16_rn(b);
    *reinterpret_cast<uint32_t*>(C + off) = *reinterpret_cast<uint32_t*>(&h);
}
__device__ __forceinline__ uint32_t pack_bf2(float a, float b) {
    __nv_bfloat162 h;
    h.x = __float2bfloat16_rn(a); h.y = __float2bfloat16_rn(b);
    return *reinterpret_cast<uint32_t*>(&h);
}

// ---------------------------------------------------------------------------
// Batched fp32 -> bf16 conversions: 9 jobs (8 weights + mask), one launch
// ---------------------------------------------------------------------------
struct SplitJob  { const float4* src; bf* dst; long n4; };
struct SplitJobs { SplitJob j[9]; };

__global__ __launch_bounds__(256) void split9(SplitJobs jobs)
{
    const SplitJob jb = jobs.j[blockIdx.y];
    long i = (long)blockIdx.x * 256 + threadIdx.x;
    if (i >= jb.n4) return;
    float4 v = jb.src[i];
    uint2 p;
    p.x = pack_bf2(v.x, v.y);
    p.y = pack_bf2(v.z, v.w);
    *(uint2*)(jb.dst + i * 4) = p;
}

__global__ __launch_bounds__(256) void transpose_bf16_kernel(
    const float* __restrict__ in, bf* __restrict__ outb)
{
    __shared__ float t[32][33];
    const int b = blockIdx.z;
    const int s0 = blockIdx.x * 32, d0 = blockIdx.y * 32;
    const long base = (long)b * MB;
    const int tx = threadIdx.x, ty = threadIdx.y;
    #pragma unroll
    for (int i = ty; i < 32; i += 8)
        t[i][tx] = in[base + (long)(s0 + i) * 512 + d0 + tx];
    __syncthreads();
    #pragma unroll
    for (int i = ty; i < 32; i += 8) {
        long o = base + (long)(d0 + i) * 512 + s0 + tx;
        outb[o] = __float2bfloat16_rn(t[tx][i]);
    }
}

// ---------------------------------------------------------------------------
// Weight-combine GEMM (fp32 in, bf16 out): C[m][n] = sum_k A[m,k]*B[k,n]
// ---------------------------------------------------------------------------
__global__ __launch_bounds__(256) void gemm64w(
    const float* __restrict__ A0, const float* __restrict__ B0,
    bf* __restrict__ C0,
    const float* __restrict__ A1, const float* __restrict__ B1,
    bf* __restrict__ C1)
{
    const float* A = blockIdx.z ? A1 : A0;
    const float* B = blockIdx.z ? B1 : B0;
    bf* Cb = blockIdx.z ? C1 : C0;
    __shared__ float As[16][64], Bs[16][64];
    const int bM = blockIdx.y * 64, bN = blockIdx.x * 64;
    const int tid = threadIdx.x, tx = tid & 15, ty = tid >> 4;
    float acc[4][4];
    #pragma unroll
    for (int i = 0; i < 4; i++)
        #pragma unroll
        for (int j = 0; j < 4; j++) acc[i][j] = 0.f;
    for (int kt = 0; kt < 32; kt++) {
        const int k0 = kt * 16;
        __syncthreads();
        #pragma unroll
        for (int it = 0; it < 4; it++) {
            int id = tid + it * 256;
            As[id & 15][id >> 4] = A[(long)(bM + (id >> 4)) * 512 + k0 + (id & 15)];
            Bs[id >> 6][id & 63] = B[(long)(k0 + (id >> 6)) * 512 + bN + (id & 63)];
        }
        __syncthreads();
        #pragma unroll
        for (int k = 0; k < 16; k++) {
            float av[4], bv[4];
            #pragma unroll
            for (int i = 0; i < 4; i++) av[i] = As[k][ty * 4 + i];
            #pragma unroll
            for (int j = 0; j < 4; j++) bv[j] = Bs[k][tx * 4 + j];
            #pragma unroll
            for (int i = 0; i < 4; i++)
                #pragma unroll
                for (int j = 0; j < 4; j++)
                    acc[i][j] = fmaf(av[i], bv[j], acc[i][j]);
        }
    }
    #pragma unroll
    for (int i = 0; i < 4; i++) {
        const long o = (long)(bM + ty * 4 + i) * 512 + bN + tx * 4;
        pack_store(Cb, o,     acc[i][0], acc[i][1]);
        pack_store(Cb, o + 2, acc[i][2], acc[i][3]);
    }
}

// ---------------------------------------------------------------------------
// Pipelined tensor-core batched GEMM (1-term bf16):
// C[b][m][n] = sum_k A[b][m][k]*B[b][n][k]
// BK=64, 3-stage cp.async, sw128-swizzled smem, ONE sync per 64-K iter.
// ---------------------------------------------------------------------------
static constexpr int ARR = 128 * 128;          // bytes per array (16384)
static constexpr int STG = 2 * ARR;            // bytes per stage  (32768)
static constexpr int TCG_SMEM = 3 * STG;       // 98304

__device__ __forceinline__ void tcg_load(
    uint32_t sb, const bf* A, const bf* B, int bM, int bN, int k0, int tid)
{
    #pragma unroll
    for (int a = 0; a < 2; a++) {
        const bf* src = a ? B : A;
        const int row0 = a ? bN : bM;
        const uint32_t dst = sb + a * ARR;
        #pragma unroll
        for (int it = 0; it < 4; it++) {
            int id = tid + it * 256;           // 0..1023
            int r = id >> 3, c8 = id & 7;
            cpa16(dst + sw128(r, c8),
                  src + (long)(row0 + r) * 512 + k0 + c8 * 8);
        }
    }
}

template<int EPI, int OF32, int OBF16>
__global__ __launch_bounds__(256, 2) void tc_gemm(
    const bf* __restrict__ A, long sA,
    const bf* __restrict__ B, long sB,
    float* __restrict__ C, bf* __restrict__ Cb, long sC,
    const float* __restrict__ R, long sR, const float* __restrict__ alpha_ptr)
{
    extern __shared__ __align__(16) char smc[];
    const uint32_t sb0 = smem_u32(smc);
    const int tid = threadIdx.x, lane = tid & 31, wid = tid >> 5;
    const int g = lane >> 2, tg = lane & 3;
    const int wm = (wid >> 1) * 32, wn = (wid & 1) * 64;
    const int bN = blockIdx.x * 128, bM = blockIdx.y * 128, bz = blockIdx.z;
    A += (long)bz * sA;
    B += (long)bz * sB;
    if (EPI != 0) R += (long)bz * sR;

    const int lrow = (lane & 7) + ((lane >> 3) & 1) * 8;
    const int lch  = lane >> 4;                 // chunk half-select 0/1

    float acc[2][8][4];
    #pragma unroll
    for (int i = 0; i < 2; i++)
        #pragma unroll
        for (int j = 0; j < 8; j++)
            #pragma unroll
            for (int q = 0; q < 4; q++) acc[i][j][q] = 0.f;

    tcg_load(sb0,       A, B, bM, bN, 0,  tid); CP_COMMIT();
    tcg_load(sb0 + STG, A, B, bM, bN, 64, tid); CP_COMMIT();

    int st = 0, ld = 2;
    for (int t = 0; t < 8; t++) {
        if (t < 7) { CP_WAIT(1); } else { CP_WAIT(0); }
        __syncthreads();
        if (t < 6) {
            tcg_load(sb0 + ld * STG, A, B, bM, bN, (t + 2) * 64, tid);
            CP_COMMIT();
            if (++ld == 3) ld = 0;
        }
        const uint32_t sb = sb0 + st * STG;
        if (++st == 3) st = 0;
        #pragma unroll
        for (int ks = 0; ks < 4; ks++) {
            const int ch = 2 * ks + lch;
            uint32_t af[2][4];
            #pragma unroll
            for (int mi = 0; mi < 2; mi++)
                ldsm4(af[mi], sb + sw128(wm + mi * 16 + lrow, ch));
            #pragma unroll
            for (int nb = 0; nb < 4; nb++) {
                uint32_t bh[4];
                ldsm4(bh, sb + ARR + sw128(wn + nb * 16 + lrow, ch));
                #pragma unroll
                for (int h2 = 0; h2 < 2; h2++)
                    #pragma unroll
                    for (int mi = 0; mi < 2; mi++)
                        mma16816(acc[mi][nb * 2 + h2], af[mi],
                                 bh[h2], bh[h2 + 2]);
            }
        }
    }

    float ab = 0.f;
    if (EPI == 2) ab = 1.f / (1.f + expf(-alpha_ptr[0]));
    #pragma unroll
    for (int mi = 0; mi < 2; mi++)
        #pragma unroll
        for (int nj = 0; nj < 8; nj++) {
            const int row = bM + wm + mi * 16 + g;
            const int col = bN + wn + nj * 8 + tg * 2;
            float v0 = acc[mi][nj][0], v1 = acc[mi][nj][1];
            float v2 = acc[mi][nj][2], v3 = acc[mi][nj][3];
            const long o0 = (long)bz * sC + (long)row * 512 + col;
            const long o1 = o0 + 8 * 512;
            if (EPI == 1) {
                float2 r0 = *(const float2*)(R + (long)row * 512 + col);
                float2 r1 = *(const float2*)(R + (long)(row + 8) * 512 + col);
                v0 += r0.x; v1 += r0.y; v2 += r1.x; v3 += r1.y;
            } else if (EPI == 2) {
                float2 r0 = *(const float2*)(R + (long)row * 512 + col);
                float2 r1 = *(const float2*)(R + (long)(row + 8) * 512 + col);
                v0 = (1.f - ab) * v0 + ab * r0.x;
                v1 = (1.f - ab) * v1 + ab * r0.y;
                v2 = (1.f - ab) * v2 + ab * r1.x;
                v3 = (1.f - ab) * v3 + ab * r1.y;
            }
            if (OF32) {
                float2 w0 = {v0, v1}, w1 = {v2, v3};
                *(float2*)(C + o0) = w0;
                *(float2*)(C + o1) = w1;
            }
            if (OBF16) {
                pack_store(Cb, o0, v0, v1);
                pack_store(Cb, o1, v2, v3);
            }
        }
}

// ---------------------------------------------------------------------------
// QKV projection (mma, 1-term): 256 threads per (128-token tile, head, batch).
// Single-bf16 outputs. Q pre-scaled by 1/8.
// ---------------------------------------------------------------------------
static constexpr int SK = 72;
static constexpr int QKV_SMEM = (128 + 3 * 64) * SK * 2;   // 46080

__device__ __forceinline__ void head_gemm(
    uint32_t wbase, const uint32_t xf[4][4],
    float scale, bf* O, long obase, int row0, int lane)
{
    const int g = lane >> 2, tg = lane & 3;
    const uint32_t lrow = (lane & 7) + ((lane >> 3) & 1) * 8;
    const uint32_t lc8 = (lane >> 4) * 8;
    float acc[8][4];
    #pragma unroll
    for (int j = 0; j < 8; j++)
        #pragma unroll
        for (int q = 0; q < 4; q++) acc[j][q] = 0.f;
    #pragma unroll
    for (int ks = 0; ks < 4; ks++) {
        #pragma unroll
        for (int nb = 0; nb < 4; nb++) {
            uint32_t bh[4];
            ldsm4(bh, wbase + ((nb * 16 + lrow) * SK + ks * 16 + lc8) * 2);
            #pragma unroll
            for (int h2 = 0; h2 < 2; h2++)
                mma16816(acc[nb * 2 + h2], xf[ks], bh[h2], bh[h2 + 2]);
        }
    }
    #pragma unroll
    for (int nj = 0; nj < 8; nj++) {
        const long o0 = obase + (long)(row0 + g) * 64 + nj * 8 + tg * 2;
        pack_store(O, o0,          acc[nj][0] * scale, acc[nj][1] * scale);
        pack_store(O, o0 + 8 * 64, acc[nj][2] * scale, acc[nj][3] * scale);
    }
}

__global__ __launch_bounds__(256) void qkv_mma(
    const bf* __restrict__ X,
    const bf* __restrict__ Wq, const bf* __restrict__ Wk,
    const bf* __restrict__ Wv,
    bf* __restrict__ Q, bf* __restrict__ K, bf* __restrict__ V)
{
    extern __shared__ __align__(16) bf smq[];
    const int tile0 = blockIdx.x * 128, h = blockIdx.y, b = blockIdx.z;
    const int tid = threadIdx.x, lane = tid & 31, wid = tid >> 5;
    const long xbase = (long)b * MB;
    const long obase = (long)(b * NH + h) * HB;
    bf* Xs = smq;                   // 128 rows
    bf* Ws = smq + 128 * SK;        // 3 x 64 rows

    #pragma unroll
    for (int it = 0; it < 4; it++) {
        int id = tid + it * 256;    // 0..1023
        int r = id >> 3, c8 = (id & 7) * 8;
        *(uint4*)(Xs + r * SK + c8) =
            *(const uint4*)(X + xbase + (long)(tile0 + r) * 512 + h * 64 + c8);
    }
    const bf* wsrc[3] = {Wq, Wk, Wv};
    #pragma unroll
    for (int a = 0; a < 3; a++)
        #pragma unroll
        for (int it = 0; it < 2; it++) {
            int id = tid + it * 256;   // 0..511
            int r = id >> 3, c8 = (id & 7) * 8;
            *(uint4*)(Ws + a * 64 * SK + r * SK + c8) =
                *(const uint4*)(wsrc[a] + h * 4096 + r * 64 + c8);
        }
    __syncthreads();

    const uint32_t xb = smem_u32(Xs);
    const uint32_t lrow = (lane & 7) + ((lane >> 3) & 1) * 8;
    const uint32_t lc8 = (lane >> 4) * 8;
    uint32_t xf[4][4];
    #pragma unroll
    for (int ks = 0; ks < 4; ks++)
        ldsm4(xf[ks], xb + ((wid * 16 + lrow) * SK + ks * 16 + lc8) * 2);

    const uint32_t wb = smem_u32(Ws);
    const int row0 = tile0 + wid * 16;
    head_gemm(wb,                xf, 0.125f, Q, obase, row0, lane);
    head_gemm(wb + 64 * SK * 2,  xf, 1.f,    K, obase, row0, lane);
    head_gemm(wb + 128 * SK * 2, xf, 1.f,    V, obase, row0, lane);
}

// ---------------------------------------------------------------------------
// Flash attention (mma, 1-term): 256 threads, 128-row q-strip, 3-stage
// swizzled cp.async K/V(/mask) pipeline, ONE sync per kv-iter.
// HM=1 streams the bf16 mask tile through the pipeline (stride-72 rows).
// Output bf16, head-concat: O[b][row][h*64+e].
// ---------------------------------------------------------------------------
static constexpr int AAR  = 64 * 128;                // bytes per KV array (8192)
static constexpr int MROW = 72;                      // mask row stride (elems)
static constexpr int MARR = 128 * MROW * 2;          // mask tile bytes (18432)

template<int HM>
__device__ __forceinline__ void attn_load_kv(
    uint32_t dst, const bf* K, const bf* V, const bf* Mb,
    long base, int q0, int kt, int tid)
{
    #pragma unroll
    for (int it = 0; it < 2; it++) {
        int id = tid + it * 256;       // 0..511
        int r = id >> 3, c8 = id & 7;
        const long gsrc = base + (long)(kt * 64 + r) * 64 + c8 * 8;
        const uint32_t so = sw128(r, c8);
        cpa16(dst       + so, K + gsrc);
        cpa16(dst + AAR + so, V + gsrc);
    }
    if (HM) {
        #pragma unroll
        for (int it = 0; it < 4; it++) {
            int id = tid + it * 256;   // 0..1023
            int r = id >> 3, c8 = id & 7;
            cpa16(dst + 2 * AAR + (uint32_t)(r * MROW * 2 + c8 * 16),
                  Mb + (long)(q0 + r) * 512 + kt * 64 + c8 * 8);
        }
    }
}

template<int HM>
__global__ __launch_bounds__(256, 2) void attn_mma(
    const bf* __restrict__ Q, const bf* __restrict__ K,
    const bf* __restrict__ V, const bf* __restrict__ Mb,
    bf* __restrict__ O)
{
    constexpr int STA = 2 * AAR + (HM ? MARR : 0);
    extern __shared__ __align__(16) bf sma[];
    const int q0 = blockIdx.x * 128, h = blockIdx.y, b = blockIdx.z;
    const int tid = threadIdx.x, lane = tid & 31, wid = tid >> 5;
    const int g = lane >> 2, tg = lane & 3;
    const long base = (long)(b * NH + h) * HB;
    const uint32_t sb = smem_u32(sma);
    const int lrow = (lane & 7) + ((lane >> 3) & 1) * 8;
    const int lch  = lane >> 4;

    // Stage the 128-row Q strip through the start of smem
    #pragma unroll
    for (int it = 0; it < 2; it++) {
        int id = tid + it * 256;       // 0..511
        int r = id >> 2, c8 = (id & 3) * 2;
        const long gq = base + (long)(q0 + r) * 64 + c8 * 8;
        cpa16(sb + sw128(r, c8),     Q + gq);
        cpa16(sb + sw128(r, c8 + 1), Q + gq + 8);
    }
    CP_COMMIT(); CP_WAIT(0);
    __syncthreads();
    uint32_t qf[4][4];
    #pragma unroll
    for (int ks = 0; ks < 4; ks++)
        ldsm4(qf[ks], sb + sw128(wid * 16 + lrow, 2 * ks + lch));
    __syncthreads();   // all warps done reading Q before stages are reused

    float m0 = -1e30f, m1 = -1e30f, l0 = 0.f, l1 = 0.f;
    float o[8][4];
    #pragma unroll
    for (int j = 0; j < 8; j++)
        #pragma unroll
        for (int q = 0; q < 4; q++) o[j][q] = 0.f;

    attn_load_kv<HM>(sb,       K, V, Mb, base, q0, 0, tid); CP_COMMIT();
    attn_load_kv<HM>(sb + STA, K, V, Mb, base, q0, 1, tid); CP_COMMIT();

    int st = 0, ld = 2;
    for (int kt = 0; kt < 8; kt++) {
        if (kt < 7) { CP_WAIT(1); } else { CP_WAIT(0); }
        __syncthreads();
        if (kt < 6) {
            attn_load_kv<HM>(sb + ld * STA, K, V, Mb, base, q0, kt + 2, tid);
            CP_COMMIT();
            if (++ld == 3) ld = 0;
        }
        const uint32_t KHs = sb + st * STA;
        if (++st == 3) st = 0;
        const uint32_t VHs = KHs + AAR;
        const uint32_t MHs = KHs + 2 * AAR;

        // S = Q K^T (1-term)
        float s[8][4];
        #pragma unroll
        for (int j = 0; j < 8; j++)
            #pragma unroll
            for (int q = 0; q < 4; q++) s[j][q] = 0.f;
        #pragma unroll
        for (int ks = 0; ks < 4; ks++) {
            #pragma unroll
            for (int nb = 0; nb < 4; nb++) {
                uint32_t bh[4];
                ldsm4(bh, KHs + sw128(nb * 16 + lrow, 2 * ks + lch));
                #pragma unroll
                for (int h2 = 0; h2 < 2; h2++)
                    mma16816(s[nb * 2 + h2], qf[ks], bh[h2], bh[h2 + 2]);
            }
        }
        if (HM) {
            // mask from smem (bf16, stride-72 rows; bank map 4g+tg -> CF)
            const char* smb = (const char*)sma;
            const uint32_t mo = (MHs - sb);
            const int mr = wid * 16 + g;
            #pragma unroll
            for (int nj = 0; nj < 8; nj++) {
                const uint32_t co = (uint32_t)(nj * 8 + tg * 2) * 2;
                uint32_t p0 = *(const uint32_t*)(smb + mo + mr * MROW * 2 + co);
                uint32_t p1 = *(const uint32_t*)(smb + mo + (mr + 8) * MROW * 2 + co);
                float2 f0 = __bfloat1622float2(*reinterpret_cast<__nv_bfloat162*>(&p0));
                float2 f1 = __bfloat1622float2(*reinterpret_cast<__nv_bfloat162*>(&p1));
                s[nj][0] += f0.x; s[nj][1] += f0.y;
                s[nj][2] += f1.x; s[nj][3] += f1.y;
            }
        }

        // online softmax (rows g and g+8; reduce across tg lanes)
        float tm0 = -1e30f, tm1 = -1e30f;
        #pragma unroll
        for (int nj = 0; nj < 8; nj++) {
            tm0 = fmaxf(tm0, fmaxf(s[nj][0], s[nj][1]));
            tm1 = fmaxf(tm1, fmaxf(s[nj][2], s[nj][3]));
        }
        tm0 = fmaxf(tm0, __shfl_xor_sync(~0u, tm0, 1));
        tm0 = fmaxf(tm0, __shfl_xor_sync(~0u, tm0, 2));
        tm1 = fmaxf(tm1, __shfl_xor_sync(~0u, tm1, 1));
        tm1 = fmaxf(tm1, __shfl_xor_sync(~0u, tm1, 2));
        const float nm0 = fmaxf(m0, tm0), nm1 = fmaxf(m1, tm1);
        float sum0 = 0.f, sum1 = 0.f;
        #pragma unroll
        for (int nj = 0; nj < 8; nj++) {
            s[nj][0] = __expf(s[nj][0] - nm0); sum0 += s[nj][0];
            s[nj][1] = __expf(s[nj][1] - nm0); sum0 += s[nj][1];
            s[nj][2] = __expf(s[nj][2] - nm1); sum1 += s[nj][2];
            s[nj][3] = __expf(s[nj][3] - nm1); sum1 += s[nj][3];
        }
        sum0 += __shfl_xor_sync(~0u, sum0, 1);
        sum0 += __shfl_xor_sync(~0u, sum0, 2);
        sum1 += __shfl_xor_sync(~0u, sum1, 1);
        sum1 += __shfl_xor_sync(~0u, sum1, 2);
        const float c0 = __expf(m0 - nm0), c1 = __expf(m1 - nm1);
        l0 = l0 * c0 + sum0; l1 = l1 * c1 + sum1;
        m0 = nm0; m1 = nm1;
        #pragma unroll
        for (int j = 0; j < 8; j++) {
            o[j][0] *= c0; o[j][1] *= c0; o[j][2] *= c1; o[j][3] *= c1;
        }

        // P fragments (1-term bf16; FA2 accum->A identity)
        uint32_t ph[4][4];
        #pragma unroll
        for (int ks = 0; ks < 4; ks++) {
            ph[ks][0] = pack_bf2(s[2*ks][0],   s[2*ks][1]);
            ph[ks][1] = pack_bf2(s[2*ks][2],   s[2*ks][3]);
            ph[ks][2] = pack_bf2(s[2*ks+1][0], s[2*ks+1][1]);
            ph[ks][3] = pack_bf2(s[2*ks+1][2], s[2*ks+1][3]);
        }

        // O += P V  (V^T fragments via ldmatrix.trans; 1-term)
        #pragma unroll
        for (int ks = 0; ks < 4; ks++) {
            #pragma unroll
            for (int nb = 0; nb < 4; nb++) {
                uint32_t vh[4];
                ldsm4t(vh, VHs + sw128(ks * 16 + (lane & 15), 2 * nb + lch));
                #pragma unroll
                for (int h2 = 0; h2 < 2; h2++)
                    mma16816(o[nb * 2 + h2], ph[ks],
                             vh[h2 * 2], vh[h2 * 2 + 1]);
            }
        }
    }

    const float i0 = 1.f / l0, i1 = 1.f / l1;
    const int row = q0 + wid * 16 + g;
    #pragma unroll
    for (int nj = 0; nj < 8; nj++) {
        const long o0 = (long)b * MB + (long)row * 512 + h * 64 + nj * 8 + tg * 2;
        pack_store(O, o0,           o[nj][0] * i0, o[nj][1] * i0);
        pack_store(O, o0 + 8 * 512, o[nj][2] * i1, o[nj][3] * i1);
    }
}

static constexpr int ATTN_SMEM0 = 3 * (2 * AAR);          // 49152
static constexpr int ATTN_SMEM1 = 3 * (2 * AAR + MARR);   // 104448

// ---------------------------------------------------------------------------
// Launch sequence (single stream, graph-capturable, allocation-free)
// ---------------------------------------------------------------------------
extern "C" void kernel_launch(void* const* d_in, const int* in_sizes, int n_in,
                              void* d_out, int out_size)
{
    const float* x             = (const float*)d_in[0];
    const float* mask          = (const float*)d_in[1];
    const float* Wq_inter      = (const float*)d_in[2];
    const float* Wk_inter      = (const float*)d_in[3];
    const float* Wv_inter      = (const float*)d_in[4];
    const float* Wq_intra      = (const float*)d_in[5];
    const float* Wk_intra      = (const float*)d_in[6];
    const float* Wv_intra      = (const float*)d_in[7];
    const float* W_proj_in     = (const float*)d_in[8];
    const float* W_proj_out    = (const float*)d_in[9];
    const float* W_split_inter = (const float*)d_in[10];
    const float* W_out_inter   = (const float*)d_in[11];
    const float* W_split_intra = (const float*)d_in[12];
    const float* W_out_intra   = (const float*)d_in[13];
    const float* alpha         = (const float*)d_in[14];
    float* out = (float*)d_out;

    float* oi;
    cudaGetSymbolAddress((void**)&oi, g_oi);

    bf *xT, *xp, *cc, *oib, *qq, *kk, *vv, *mb;
    bf *wcin, *wcout, *wsi, *woi;
    bf *wqA, *wkA, *wvA, *wqB, *wkB, *wvB;
    cudaGetSymbolAddress((void**)&xT,  g_xT);
    cudaGetSymbolAddress((void**)&xp,  g_xp);
    cudaGetSymbolAddress((void**)&cc,  g_cc);
    cudaGetSymbolAddress((void**)&oib, g_oib);
    cudaGetSymbolAddress((void**)&qq,  g_q);
    cudaGetSymbolAddress((void**)&kk,  g_k);
    cudaGetSymbolAddress((void**)&vv,  g_v);
    cudaGetSymbolAddress((void**)&mb,  g_maskb);
    cudaGetSymbolAddress((void**)&wcin,  g_wcin);
    cudaGetSymbolAddress((void**)&wcout, g_wcout);
    cudaGetSymbolAddress((void**)&wsi,   g_wsi);
    cudaGetSymbolAddress((void**)&woi,   g_woi);
    cudaGetSymbolAddress((void**)&wqA, g_wqA);
    cudaGetSymbolAddress((void**)&wkA, g_wkA);
    cudaGetSymbolAddress((void**)&wvA, g_wvA);
    cudaGetSymbolAddress((void**)&wqB, g_wqB);
    cudaGetSymbolAddress((void**)&wkB, g_wkB);
    cudaGetSymbolAddress((void**)&wvB, g_wvB);

    cudaFuncSetAttribute(tc_gemm<0,0,1>, cudaFuncAttributeMaxDynamicSharedMemorySize, TCG_SMEM);
    cudaFuncSetAttribute(tc_gemm<1,1,1>, cudaFuncAttributeMaxDynamicSharedMemorySize, TCG_SMEM);
    cudaFuncSetAttribute(tc_gemm<2,1,0>, cudaFuncAttributeMaxDynamicSharedMemorySize, TCG_SMEM);
    cudaFuncSetAttribute(qkv_mma,     cudaFuncAttributeMaxDynamicSharedMemorySize, QKV_SMEM);
    cudaFuncSetAttribute(attn_mma<0>, cudaFuncAttributeMaxDynamicSharedMemorySize, ATTN_SMEM0);
    cudaFuncSetAttribute(attn_mma<1>, cudaFuncAttributeMaxDynamicSharedMemorySize, ATTN_SMEM1);

    dim3 gb(4, 4, BATCH);
    dim3 gq(4, NH, BATCH);
    dim3 gattn(4, NH, BATCH);
    dim3 gts(16, 16, BATCH), tts(32, 8);
    const long W4 = MB / 4, H4 = (long)NH * 4096 / 4;

    // Combined weights: fp32 GEMM with direct bf16 epilogue (2 jobs)
    gemm64w<<<dim3(8, 8, 2), 256>>>(W_split_inter, W_proj_in, wcin,
                                    W_proj_out, W_out_inter, wcout);

    // All independent conversions (8 weights + mask) in ONE launch
    SplitJobs jobs;
    jobs.j[0] = {(const float4*)W_split_intra, wsi, W4};
    jobs.j[1] = {(const float4*)W_out_intra,   woi, W4};
    jobs.j[2] = {(const float4*)Wq_inter, wqA, H4};
    jobs.j[3] = {(const float4*)Wk_inter, wkA, H4};
    jobs.j[4] = {(const float4*)Wv_inter, wvA, H4};
    jobs.j[5] = {(const float4*)Wq_intra, wqB, H4};
    jobs.j[6] = {(const float4*)Wk_intra, wkB, H4};
    jobs.j[7] = {(const float4*)Wv_intra, wvB, H4};
    jobs.j[8] = {(const float4*)mask,     mb,  W4};
    split9<<<dim3(256, 9, 1), 256>>>(jobs);

    transpose_bf16_kernel<<<gts, tts>>>(x, xT);

    // GEMM1: xp = xT @ wcin^T  (bf16 out)
    tc_gemm<0,0,1><<<gb, 256, TCG_SMEM>>>(xT, MB, wcin, 0,
                                          nullptr, xp, MB, nullptr, 0, nullptr);
    // inter path (no mask)
    qkv_mma<<<gq, 256, QKV_SMEM>>>(xp, wqA, wkA, wvA, qq, kk, vv);
    attn_mma<0><<<gattn, 256, ATTN_SMEM0>>>(qq, kk, vv, nullptr, cc);
    // GEMM2: oi = wcout @ cc^T + x  (fp32 + bf16 out)
    tc_gemm<1,1,1><<<gb, 256, TCG_SMEM>>>(wcout, 0, cc, MB,
                                          oi, oib, MB, x, MB, nullptr);
    // GEMM3: xi = oib @ wsi^T  (bf16 out, reuse xp)
    tc_gemm<0,0,1><<<gb, 256, TCG_SMEM>>>(oib, MB, wsi, 0,
                                          nullptr, xp, MB, nullptr, 0, nullptr);
    // intra path (mask streamed through smem pipeline)
    qkv_mma<<<gq, 256, QKV_SMEM>>>(xp, wqB, wkB, wvB, qq, kk, vv);
    attn_mma<1><<<gattn, 256, ATTN_SMEM1>>>(qq, kk, vv, mb, cc);
    // GEMM4: out = (1-a)*(cc @ woi^T) + a*oi
    tc_gemm<2,1,0><<<gb, 256, TCG_SMEM>>>(cc, MB, woi, 0,
                                          out, nullptr, MB, oi, MB, alpha);
}